// round 1
// baseline (speedup 1.0000x reference)
#include <cuda_runtime.h>
#include <math.h>

#define B_    4
#define E_    50
#define C_    64
#define HW_   2048
#define BE_   200
#define SLAB_ 131072      // C_*HW_
#define NTOT_ 26214400    // BE_*SLAB_

// ---- scratch (static device globals; no allocation) ----
__device__ float g_v[NTOT_];
__device__ float g_k[NTOT_];
__device__ float g_q[NTOT_];
__device__ float g_t[NTOT_];
__device__ float g_after[NTOT_];
__device__ float g_h1[NTOT_];
__device__ float g_gram[B_ * C_ * E_ * E_];
__device__ float g_wts[B_ * C_ * E_ * E_];
__device__ float g_mu[BE_];
__device__ float g_rs[BE_];

// ============================================================
// Kernel 1: LayerNorm statistics per (b,e) slab of C*H*W elems
// ============================================================
__global__ void ln_stats_kernel(const float* __restrict__ x) {
    const int be = blockIdx.x;
    const float4* p = (const float4*)(x + (size_t)be * SLAB_);
    float s = 0.f, s2 = 0.f;
    for (int i = threadIdx.x; i < SLAB_ / 4; i += blockDim.x) {
        float4 v = p[i];
        s  += v.x + v.y + v.z + v.w;
        s2 += v.x * v.x + v.y * v.y + v.z * v.z + v.w * v.w;
    }
    for (int o = 16; o; o >>= 1) {
        s  += __shfl_down_sync(0xffffffffu, s,  o);
        s2 += __shfl_down_sync(0xffffffffu, s2, o);
    }
    __shared__ float shs[8], shq[8];
    const int w = threadIdx.x >> 5, l = threadIdx.x & 31;
    if (l == 0) { shs[w] = s; shq[w] = s2; }
    __syncthreads();
    if (threadIdx.x == 0) {
        float S = 0.f, Q = 0.f;
        const int nw = blockDim.x >> 5;
        for (int i = 0; i < nw; i++) { S += shs[i]; Q += shq[i]; }
        const float mu  = S * (1.f / (float)SLAB_);
        const float var = Q * (1.f / (float)SLAB_) - mu * mu;
        g_mu[be] = mu;
        g_rs[be] = rsqrtf(var + 1e-5f);
    }
}

// ============================================================
// Kernel 2 (templated): 64x64 conv1x1 GEMM over HW columns.
// out[be][o][hw] = sum_c W[o][c] * in'[be][c][hw]  (+bias)(+gelu)(+res)
// in' optionally layernormed on tile load (LN flag).
// Tile: 64 out x 128 hw, 128 threads, 8x8 per-thread micro-tile.
// ============================================================
template <bool LN, bool BIAS, bool RES, bool GELU>
__global__ void __launch_bounds__(128) conv64_kernel(
    const float* __restrict__ in, const float* __restrict__ Wm,
    const float* __restrict__ bias, const float* __restrict__ res,
    const float* __restrict__ lng, const float* __restrict__ lnb,
    float* __restrict__ out)
{
    __shared__ float Ws[64 * 64];    // [c][o] (transposed)
    __shared__ float Xs[64 * 128];   // [c][hw]
    const int be  = blockIdx.y;
    const int hw0 = blockIdx.x * 128;
    const int tid = threadIdx.x;

    // Load weight transposed: Ws[c][o] = W[o][c].
    // (consecutive tid -> consecutive o -> conflict-free smem stores)
    for (int idx = tid; idx < 4096; idx += 128) {
        const int c = idx >> 6, o = idx & 63;
        Ws[c * 64 + o] = Wm[o * 64 + c];
    }

    float mu = 0.f, rs = 1.f;
    if (LN) { mu = g_mu[be]; rs = g_rs[be]; }

    const float* src = in + (size_t)be * SLAB_ + hw0;
    for (int idx = tid; idx < 2048; idx += 128) {
        const int c  = idx >> 5;
        const int q4 = (idx & 31) << 2;
        float4 v = *(const float4*)(src + c * HW_ + q4);
        if (LN) {
            const float4 gg = *(const float4*)(lng + c * HW_ + hw0 + q4);
            const float4 bb = *(const float4*)(lnb + c * HW_ + hw0 + q4);
            v.x = (v.x - mu) * rs * gg.x + bb.x;
            v.y = (v.y - mu) * rs * gg.y + bb.y;
            v.z = (v.z - mu) * rs * gg.z + bb.z;
            v.w = (v.w - mu) * rs * gg.w + bb.w;
        }
        *(float4*)(Xs + c * 128 + q4) = v;
    }
    __syncthreads();

    const int tx = tid & 15, ty = tid >> 4;   // tx: hw, ty: out
    float acc[8][8];
#pragma unroll
    for (int i = 0; i < 8; i++)
#pragma unroll
        for (int j = 0; j < 8; j++) acc[i][j] = 0.f;

#pragma unroll 8
    for (int c = 0; c < 64; c++) {
        float a[8], b[8];
        *(float4*)(a)     = *(const float4*)(Ws + c * 64  + 4 * ty);
        *(float4*)(a + 4) = *(const float4*)(Ws + c * 64  + 32 + 4 * ty);
        *(float4*)(b)     = *(const float4*)(Xs + c * 128 + 4 * tx);
        *(float4*)(b + 4) = *(const float4*)(Xs + c * 128 + 64 + 4 * tx);
#pragma unroll
        for (int i = 0; i < 8; i++)
#pragma unroll
            for (int j = 0; j < 8; j++)
                acc[i][j] = fmaf(a[i], b[j], acc[i][j]);
    }

    float* dst = out + (size_t)be * SLAB_ + hw0;
    const float* rsrc = RES ? (res + (size_t)be * SLAB_ + hw0) : nullptr;
#pragma unroll
    for (int oi = 0; oi < 8; oi++) {
        const int o = (oi < 4) ? (4 * ty + oi) : (32 + 4 * ty + oi - 4);
        const float bv = BIAS ? bias[o] : 0.f;
#pragma unroll
        for (int jh = 0; jh < 2; jh++) {
            const int hw = jh * 64 + 4 * tx;
            float tmp[4];
#pragma unroll
            for (int ji = 0; ji < 4; ji++) {
                float vv = acc[oi][jh * 4 + ji] + bv;
                if (GELU) vv = 0.5f * vv * (1.f + erff(vv * 0.7071067811865475f));
                tmp[ji] = vv;
            }
            float4 r = make_float4(tmp[0], tmp[1], tmp[2], tmp[3]);
            if (RES) {
                const float4 rr = *(const float4*)(rsrc + o * HW_ + hw);
                r.x += rr.x; r.y += rr.y; r.z += rr.z; r.w += rr.w;
            }
            *(float4*)(dst + o * HW_ + hw) = r;
        }
    }
}

// ============================================================
// Kernel 3: gram[b][nh][i][j] = scale * sum_hw K[b,i,nh,hw]*Q[b,j,nh,hw]
// One block per (b,nh). Transposed smem tiles [hw][i_pad68].
// ============================================================
__global__ void __launch_bounds__(256) gram_kernel(
    const float* __restrict__ k, const float* __restrict__ q,
    float* __restrict__ gout)
{
    const int nh = blockIdx.x, b = blockIdx.y;
    __shared__ float Kt[64 * 68];
    __shared__ float Qt[64 * 68];
    const int tid = threadIdx.x;
    const int tx = tid & 15, ty = tid >> 4;

    for (int idx = tid; idx < 64 * 68; idx += 256) { Kt[idx] = 0.f; Qt[idx] = 0.f; }

    float acc[4][4];
#pragma unroll
    for (int i = 0; i < 4; i++)
#pragma unroll
        for (int j = 0; j < 4; j++) acc[i][j] = 0.f;

    for (int t = 0; t < 32; t++) {
        const int hw0 = t * 64;
        __syncthreads();
        for (int idx = tid; idx < E_ * 64; idx += 256) {
            const int i = idx >> 6, hw = idx & 63;
            const size_t goff = ((size_t)(b * E_ + i) * C_ + nh) * HW_ + hw0 + hw;
            Kt[hw * 68 + i] = k[goff];
            Qt[hw * 68 + i] = q[goff];
        }
        __syncthreads();
#pragma unroll 4
        for (int hw = 0; hw < 64; hw++) {
            float a[4], c4[4];
            *(float4*)a  = *(const float4*)(Kt + hw * 68 + 4 * ty);
            *(float4*)c4 = *(const float4*)(Qt + hw * 68 + 4 * tx);
#pragma unroll
            for (int ii = 0; ii < 4; ii++)
#pragma unroll
                for (int jj = 0; jj < 4; jj++)
                    acc[ii][jj] = fmaf(a[ii], c4[jj], acc[ii][jj]);
        }
    }

    const float scale = 0.02209708691207961f;  // 1/sqrt(2048)
    float* gdst = gout + ((size_t)b * C_ + nh) * (E_ * E_);
#pragma unroll
    for (int ii = 0; ii < 4; ii++) {
        const int i = 4 * ty + ii;
        if (i < E_) {
#pragma unroll
            for (int jj = 0; jj < 4; jj++) {
                const int j = 4 * tx + jj;
                if (j < E_) gdst[i * E_ + j] = acc[ii][jj] * scale;
            }
        }
    }
}

// ============================================================
// Kernel 4: softmax over i axis for each (b,nh,j) column of the gram.
// ============================================================
__global__ void softmax_kernel(const float* __restrict__ gin,
                               float* __restrict__ wout) {
    const int bc = blockIdx.x;  // b*C_ + nh
    const float* G = gin + (size_t)bc * (E_ * E_);
    float* Wd = wout + (size_t)bc * (E_ * E_);
    const int j = threadIdx.x;
    if (j >= E_) return;
    float col[E_];
    float m = -1e30f;
#pragma unroll
    for (int i = 0; i < E_; i++) { col[i] = G[i * E_ + j]; m = fmaxf(m, col[i]); }
    float s = 0.f;
#pragma unroll
    for (int i = 0; i < E_; i++) { col[i] = expf(col[i] - m); s += col[i]; }
    const float inv = 1.f / s;
#pragma unroll
    for (int i = 0; i < E_; i++) Wd[i * E_ + j] = col[i] * inv;
}

// ============================================================
// Kernel 5: mean-centered ensemble mixing per (b,nh):
//   T[j,hw] = V[j,hw] - mean_i V[i,hw] + sum_i w[i,j]*V[i,hw]
// (uses sum_i softmax w = 1 to fold the centering)
// ============================================================
__global__ void __launch_bounds__(256) mixing_kernel(
    const float* __restrict__ v, const float* __restrict__ w,
    float* __restrict__ tout)
{
    const int nh = blockIdx.x, b = blockIdx.y;
    __shared__ float ws[E_ * 64];   // [i][j] padded j->64, zero pad
    __shared__ float Vs[E_ * 68];   // [i][hw] pad 68
    __shared__ float vms[64];
    const int tid = threadIdx.x;
    const int tx = tid & 15, ty = tid >> 4;

    const float* wsrc = w + ((size_t)b * C_ + nh) * (E_ * E_);
    for (int idx = tid; idx < E_ * 64; idx += 256) {
        const int i = idx >> 6, j = idx & 63;
        ws[idx] = (j < E_) ? wsrc[i * E_ + j] : 0.f;
    }

    for (int t = 0; t < 32; t++) {
        const int hw0 = t * 64;
        __syncthreads();
        for (int idx = tid; idx < E_ * 64; idx += 256) {
            const int i = idx >> 6, hw = idx & 63;
            Vs[i * 68 + hw] = v[((size_t)(b * E_ + i) * C_ + nh) * HW_ + hw0 + hw];
        }
        __syncthreads();
        if (tid < 64) {
            float s = 0.f;
#pragma unroll
            for (int i = 0; i < E_; i++) s += Vs[i * 68 + tid];
            vms[tid] = s * (1.f / (float)E_);
        }
        __syncthreads();

        float acc[4][4];
#pragma unroll
        for (int ii = 0; ii < 4; ii++)
#pragma unroll
            for (int jj = 0; jj < 4; jj++) acc[ii][jj] = 0.f;

#pragma unroll 5
        for (int i = 0; i < E_; i++) {
            float a[4], c4[4];
            *(float4*)a  = *(const float4*)(ws + i * 64 + 4 * ty);  // w[i][j..]
            *(float4*)c4 = *(const float4*)(Vs + i * 68 + 4 * tx);  // V[i][hw..]
#pragma unroll
            for (int jj = 0; jj < 4; jj++)
#pragma unroll
                for (int hh = 0; hh < 4; hh++)
                    acc[jj][hh] = fmaf(a[jj], c4[hh], acc[jj][hh]);
        }

        const float4 vm4 = *(const float4*)(vms + 4 * tx);
#pragma unroll
        for (int jj = 0; jj < 4; jj++) {
            const int j = 4 * ty + jj;
            if (j < E_) {
                const float4 vj = *(const float4*)(Vs + j * 68 + 4 * tx);
                float4 r;
                r.x = vj.x + acc[jj][0] - vm4.x;
                r.y = vj.y + acc[jj][1] - vm4.y;
                r.z = vj.z + acc[jj][2] - vm4.z;
                r.w = vj.w + acc[jj][3] - vm4.w;
                *(float4*)(tout + ((size_t)(b * E_ + j) * C_ + nh) * HW_ + hw0 + 4 * tx) = r;
            }
        }
    }
}

// ============================================================
// Launch
// ============================================================
extern "C" void kernel_launch(void* const* d_in, const int* in_sizes, int n_in,
                              void* d_out, int out_size)
{
    const float* x    = (const float*)d_in[0];
    const float* lng  = (const float*)d_in[1];
    const float* lnb  = (const float*)d_in[2];
    const float* W_v  = (const float*)d_in[3];
    const float* W_k  = (const float*)d_in[4];
    const float* W_q  = (const float*)d_in[5];
    const float* W_o  = (const float*)d_in[6];
    const float* W_m1 = (const float*)d_in[7];
    const float* b_m1 = (const float*)d_in[8];
    const float* W_m2 = (const float*)d_in[9];
    const float* b_m2 = (const float*)d_in[10];
    float* out = (float*)d_out;

    float *pv, *pk, *pq, *pt, *pa, *ph, *pg, *pw;
    cudaGetSymbolAddress((void**)&pv, g_v);
    cudaGetSymbolAddress((void**)&pk, g_k);
    cudaGetSymbolAddress((void**)&pq, g_q);
    cudaGetSymbolAddress((void**)&pt, g_t);
    cudaGetSymbolAddress((void**)&pa, g_after);
    cudaGetSymbolAddress((void**)&ph, g_h1);
    cudaGetSymbolAddress((void**)&pg, g_gram);
    cudaGetSymbolAddress((void**)&pw, g_wts);

    // 1) LayerNorm stats per (b,e)
    ln_stats_kernel<<<BE_, 256>>>(x);

    const dim3 cg(HW_ / 128, BE_);
    // 2) v, k, q = conv1x1(LN(x), W_*)   (LN fused into tile load)
    conv64_kernel<true,  false, false, false><<<cg, 128>>>(x, W_v, nullptr, nullptr, lng, lnb, pv);
    conv64_kernel<true,  false, false, false><<<cg, 128>>>(x, W_k, nullptr, nullptr, lng, lnb, pk);
    conv64_kernel<true,  false, false, false><<<cg, 128>>>(x, W_q, nullptr, nullptr, lng, lnb, pq);

    // 3) gram + softmax over ensemble axis
    gram_kernel<<<dim3(C_, B_), 256>>>(pk, pq, pg);
    softmax_kernel<<<B_ * C_, 64>>>(pg, pw);

    // 4) mean-centered value mixing
    mixing_kernel<<<dim3(C_, B_), 256>>>(pv, pw, pt);

    // 5) after = x + conv1x1(transformed, W_out)
    conv64_kernel<false, false, true,  false><<<cg, 128>>>(pt, W_o, nullptr, x, nullptr, nullptr, pa);

    // 6) h1 = gelu(conv1x1(after, W_m1) + b_m1)
    conv64_kernel<false, true,  false, true ><<<cg, 128>>>(pa, W_m1, b_m1, nullptr, nullptr, nullptr, ph);

    // 7) out = after + conv1x1(h1, W_m2) + b_m2
    conv64_kernel<false, true,  true,  false><<<cg, 128>>>(ph, W_m2, b_m2, pa, nullptr, nullptr, out);
}

// round 2
// speedup vs baseline: 1.2392x; 1.2392x over previous
#include <cuda_runtime.h>
#include <math.h>

#define B_    4
#define E_    50
#define C_    64
#define HW_   2048
#define BE_   200
#define SLAB_ 131072      // C_*HW_
#define NTOT_ 26214400    // BE_*SLAB_

// ---- scratch (static device globals; no allocation) ----
__device__ float g_v[NTOT_];   // [b][c][e][hw]
__device__ float g_k[NTOT_];   // [b][c][e][hw]
__device__ float g_q[NTOT_];   // [b][c][e][hw]
__device__ float g_t[NTOT_];   // [b][e][c][hw]
__device__ float g_wts[B_ * C_ * E_ * E_];  // w' = softmax - 1/E
__device__ float g_mu[BE_];
__device__ float g_rs[BE_];

typedef unsigned long long ull;

// ---- packed f32x2 helpers (Blackwell FFMA2 path) ----
__device__ __forceinline__ ull pack2(float lo, float hi) {
    ull r; asm("mov.b64 %0, {%1, %2};" : "=l"(r) : "f"(lo), "f"(hi)); return r;
}
__device__ __forceinline__ ull dup2(float v) { return pack2(v, v); }
__device__ __forceinline__ void fma2(ull& d, ull a, ull b) {
    asm("fma.rn.f32x2 %0, %1, %2, %0;" : "+l"(d) : "l"(a), "l"(b));
}
__device__ __forceinline__ float2 unpk(ull v) {
    float2 f; asm("mov.b64 {%0, %1}, %2;" : "=f"(f.x), "=f"(f.y) : "l"(v)); return f;
}

// ============================================================
// Kernel 1: LayerNorm statistics per (b,e) slab
// ============================================================
__global__ void ln_stats_kernel(const float* __restrict__ x) {
    const int be = blockIdx.x;
    const float4* p = (const float4*)(x + (size_t)be * SLAB_);
    float s = 0.f, s2 = 0.f;
    for (int i = threadIdx.x; i < SLAB_ / 4; i += blockDim.x) {
        float4 v = p[i];
        s  += v.x + v.y + v.z + v.w;
        s2 += v.x * v.x + v.y * v.y + v.z * v.z + v.w * v.w;
    }
    for (int o = 16; o; o >>= 1) {
        s  += __shfl_down_sync(0xffffffffu, s,  o);
        s2 += __shfl_down_sync(0xffffffffu, s2, o);
    }
    __shared__ float shs[16], shq[16];
    const int w = threadIdx.x >> 5, l = threadIdx.x & 31;
    if (l == 0) { shs[w] = s; shq[w] = s2; }
    __syncthreads();
    if (threadIdx.x == 0) {
        float S = 0.f, Q = 0.f;
        const int nw = blockDim.x >> 5;
        for (int i = 0; i < nw; i++) { S += shs[i]; Q += shq[i]; }
        const float mu  = S * (1.f / (float)SLAB_);
        const float var = Q * (1.f / (float)SLAB_) - mu * mu;
        g_mu[be] = mu;
        g_rs[be] = rsqrtf(var + 1e-5f);
    }
}

// ============================================================
// Shared GEMM micro-kernel: 8 out x 8 hw per thread, f32x2 packed.
// acc[8][4]: out-index i, hw-pair index j (hw = 4tx..+3, 64+4tx..+3)
// ============================================================
__device__ __forceinline__ void gemm_tile(ull acc[8][4], const float* __restrict__ Wg,
                                          const float* __restrict__ Xs,
                                          int tx, int ty) {
#pragma unroll 8
    for (int c = 0; c < 64; c++) {
        const float4 a0 = *(const float4*)(Wg + c * 64 + 4 * ty);
        const float4 a1 = *(const float4*)(Wg + c * 64 + 32 + 4 * ty);
        ull ap[8];
        ap[0] = dup2(a0.x); ap[1] = dup2(a0.y); ap[2] = dup2(a0.z); ap[3] = dup2(a0.w);
        ap[4] = dup2(a1.x); ap[5] = dup2(a1.y); ap[6] = dup2(a1.z); ap[7] = dup2(a1.w);
        const ulonglong2 b0 = *(const ulonglong2*)(Xs + c * 128 + 4 * tx);
        const ulonglong2 b1 = *(const ulonglong2*)(Xs + c * 128 + 64 + 4 * tx);
        ull bp[4] = {b0.x, b0.y, b1.x, b1.y};
#pragma unroll
        for (int i = 0; i < 8; i++)
#pragma unroll
            for (int j = 0; j < 4; j++) fma2(acc[i][j], ap[i], bp[j]);
    }
}

// ============================================================
// Kernel 2: fused LN + v/k/q conv (3 GEMMs per x-tile)
// out layout: [b][c][e][hw]
// ============================================================
__global__ void __launch_bounds__(128) vkq_kernel(
    const float* __restrict__ x,
    const float* __restrict__ Wv, const float* __restrict__ Wk, const float* __restrict__ Wq,
    const float* __restrict__ lng, const float* __restrict__ lnb,
    float* __restrict__ ov, float* __restrict__ ok, float* __restrict__ oq)
{
    extern __shared__ float sm[];
    float* Ws = sm;            // 3 * 64*64  ([c][o] transposed)
    float* Xs = sm + 12288;    // 64 * 128
    const int be = blockIdx.y, hw0 = blockIdx.x * 128, tid = threadIdx.x;

    const float* Wp[3] = {Wv, Wk, Wq};
    for (int idx = tid; idx < 12288; idx += 128) {
        const int g = idx >> 12, r = idx & 4095, c = r >> 6, o = r & 63;
        Ws[idx] = Wp[g][o * 64 + c];   // Ws[g][c][o] (idx == g*4096 + c*64 + o)
    }

    const float mu = g_mu[be], rs = g_rs[be];
    const float* src = x + (size_t)be * SLAB_ + hw0;
    for (int idx = tid; idx < 2048; idx += 128) {
        const int c  = idx >> 5;
        const int q4 = (idx & 31) << 2;
        float4 v = *(const float4*)(src + c * HW_ + q4);
        const float4 gg = *(const float4*)(lng + c * HW_ + hw0 + q4);
        const float4 bb = *(const float4*)(lnb + c * HW_ + hw0 + q4);
        v.x = (v.x - mu) * rs * gg.x + bb.x;
        v.y = (v.y - mu) * rs * gg.y + bb.y;
        v.z = (v.z - mu) * rs * gg.z + bb.z;
        v.w = (v.w - mu) * rs * gg.w + bb.w;
        *(float4*)(Xs + c * 128 + q4) = v;
    }
    __syncthreads();

    const int tx = tid & 15, ty = tid >> 4;
    const int bb_ = be / E_, ee = be % E_;
    float* outs[3] = {ov, ok, oq};

#pragma unroll 1
    for (int g = 0; g < 3; g++) {
        ull acc[8][4];
#pragma unroll
        for (int i = 0; i < 8; i++)
#pragma unroll
            for (int j = 0; j < 4; j++) acc[i][j] = 0ull;

        gemm_tile(acc, Ws + g * 4096, Xs, tx, ty);

        float* dst = outs[g] + ((size_t)(bb_ * C_) * E_ + ee) * HW_ + hw0;
#pragma unroll
        for (int oi = 0; oi < 8; oi++) {
            const int o = (oi < 4) ? (4 * ty + oi) : (32 + 4 * ty + oi - 4);
#pragma unroll
            for (int jh = 0; jh < 2; jh++) {
                const float2 p0 = unpk(acc[oi][2 * jh]);
                const float2 p1 = unpk(acc[oi][2 * jh + 1]);
                float4 r = make_float4(p0.x, p0.y, p1.x, p1.y);
                *(float4*)(dst + (size_t)o * E_ * HW_ + jh * 64 + 4 * tx) = r;
            }
        }
    }
}

// ============================================================
// Kernel 3: gram + softmax fused per (b,nh).
// gram[i][j] = scale * sum_hw K[i,hw]*Q[j,hw]; softmax over i;
// stores w' = softmax - 1/E  (folds the mean-centering).
// ============================================================
__global__ void __launch_bounds__(256) gram_kernel(
    const float* __restrict__ k, const float* __restrict__ q,
    float* __restrict__ wts)
{
    __shared__ float Kt[64 * 68];   // [hw][i], pad 68
    __shared__ float Qt[64 * 68];
    const int nh = blockIdx.x, b = blockIdx.y, tid = threadIdx.x;
    const int tx = tid & 15, ty = tid >> 4;
    const float* kb = k + (size_t)(b * C_ + nh) * E_ * HW_;
    const float* qb = q + (size_t)(b * C_ + nh) * E_ * HW_;

    ull acc[4][2];
#pragma unroll
    for (int i = 0; i < 4; i++) { acc[i][0] = 0ull; acc[i][1] = 0ull; }

    for (int t = 0; t < 32; t++) {
        __syncthreads();
        for (int idx = tid; idx < 4096; idx += 256) {
            const int i = idx >> 6, hw = idx & 63;
            float kv = 0.f, qv = 0.f;
            if (i < E_) {
                kv = kb[i * HW_ + t * 64 + hw];
                qv = qb[i * HW_ + t * 64 + hw];
            }
            Kt[hw * 68 + i] = kv;
            Qt[hw * 68 + i] = qv;
        }
        __syncthreads();
#pragma unroll 8
        for (int hw = 0; hw < 64; hw++) {
            const float4 a = *(const float4*)(Kt + hw * 68 + 4 * ty);
            ull ap[4] = {dup2(a.x), dup2(a.y), dup2(a.z), dup2(a.w)};
            const ulonglong2 bq = *(const ulonglong2*)(Qt + hw * 68 + 4 * tx);
#pragma unroll
            for (int ii = 0; ii < 4; ii++) {
                fma2(acc[ii][0], ap[ii], bq.x);
                fma2(acc[ii][1], ap[ii], bq.y);
            }
        }
    }

    // dump gram (scaled) into smem, reusing Kt
    __syncthreads();
    float* gsm = Kt;  // 64x64
    const float scale = 0.02209708691207961f;  // 1/sqrt(2048)
#pragma unroll
    for (int ii = 0; ii < 4; ii++) {
        const int i = 4 * ty + ii;
        const float2 p0 = unpk(acc[ii][0]);
        const float2 p1 = unpk(acc[ii][1]);
        gsm[i * 64 + 4 * tx + 0] = p0.x * scale;
        gsm[i * 64 + 4 * tx + 1] = p0.y * scale;
        gsm[i * 64 + 4 * tx + 2] = p1.x * scale;
        gsm[i * 64 + 4 * tx + 3] = p1.y * scale;
    }
    __syncthreads();

    // softmax over i per column j, subtract 1/E, write to global
    if (tid < E_) {
        const int j = tid;
        float col[E_];
        float m = -1e30f;
#pragma unroll
        for (int i = 0; i < E_; i++) { col[i] = gsm[i * 64 + j]; m = fmaxf(m, col[i]); }
        float s = 0.f;
#pragma unroll
        for (int i = 0; i < E_; i++) { col[i] = expf(col[i] - m); s += col[i]; }
        const float inv = 1.f / s;
        float* wdst = wts + (size_t)(b * C_ + nh) * E_ * E_;
#pragma unroll
        for (int i = 0; i < E_; i++) wdst[i * E_ + j] = col[i] * inv - 0.02f;
    }
}

// ============================================================
// Kernel 4: ensemble mixing per (b,nh,chunk):
//   T[j,hw] = V[j,hw] + sum_i w'[i,j] * V[i,hw]
// T layout: [b][e][c][hw]
// ============================================================
__global__ void __launch_bounds__(256) mixing_kernel(
    const float* __restrict__ v, const float* __restrict__ w,
    float* __restrict__ tout)
{
    __shared__ float wsm[E_ * 64];   // [i][j], j padded to 64 (zeros)
    __shared__ float Vs[E_ * 64];    // [i][hw]
    const int nh = blockIdx.x, b = blockIdx.y, ch = blockIdx.z;
    const int tid = threadIdx.x;
    const int tx = tid & 15, ty = tid >> 4;

    const float* wsrc = w + (size_t)(b * C_ + nh) * E_ * E_;
    for (int idx = tid; idx < E_ * 64; idx += 256) {
        const int i = idx >> 6, j = idx & 63;
        wsm[idx] = (j < E_) ? wsrc[i * E_ + j] : 0.f;
    }
    const float* vb = v + (size_t)(b * C_ + nh) * E_ * HW_;

    for (int t = 0; t < 8; t++) {
        const int hw0 = ch * 512 + t * 64;
        __syncthreads();
        for (int idx = tid; idx < E_ * 64; idx += 256) {
            const int i = idx >> 6, hw = idx & 63;
            Vs[idx] = vb[i * HW_ + hw0 + hw];
        }
        __syncthreads();

        ull acc[4][2];
#pragma unroll
        for (int jj = 0; jj < 4; jj++) { acc[jj][0] = 0ull; acc[jj][1] = 0ull; }

#pragma unroll 5
        for (int i = 0; i < E_; i++) {
            const float4 aw = *(const float4*)(wsm + i * 64 + 4 * ty);
            ull ap[4] = {dup2(aw.x), dup2(aw.y), dup2(aw.z), dup2(aw.w)};
            const ulonglong2 bv = *(const ulonglong2*)(Vs + i * 64 + 4 * tx);
#pragma unroll
            for (int jj = 0; jj < 4; jj++) {
                fma2(acc[jj][0], ap[jj], bv.x);
                fma2(acc[jj][1], ap[jj], bv.y);
            }
        }

#pragma unroll
        for (int jj = 0; jj < 4; jj++) {
            const int j = 4 * ty + jj;
            if (j < E_) {
                const float4 vj = *(const float4*)(Vs + j * 64 + 4 * tx);
                const float2 p0 = unpk(acc[jj][0]);
                const float2 p1 = unpk(acc[jj][1]);
                float4 r = make_float4(vj.x + p0.x, vj.y + p0.y, vj.z + p1.x, vj.w + p1.y);
                *(float4*)(tout + ((size_t)(b * E_ + j) * C_ + nh) * HW_ + hw0 + 4 * tx) = r;
            }
        }
    }
}

// ============================================================
// Kernel 5: fused tail per (be, hw-tile):
//   after = x + W_out @ T          (after stays in regs + smem)
//   h1    = gelu(W_m1 @ after + b1)
//   out   = after + W_m2 @ h1 + b2
// ============================================================
__global__ void __launch_bounds__(128) tail_kernel(
    const float* __restrict__ T, const float* __restrict__ x,
    const float* __restrict__ Wo, const float* __restrict__ Wm1,
    const float* __restrict__ bm1, const float* __restrict__ Wm2,
    const float* __restrict__ bm2, float* __restrict__ out)
{
    extern __shared__ float sm[];
    float* Ws  = sm;           // 3 * 64*64
    float* buf = sm + 12288;   // 64 * 128
    const int be = blockIdx.y, hw0 = blockIdx.x * 128, tid = threadIdx.x;

    const float* Wp[3] = {Wo, Wm1, Wm2};
    for (int idx = tid; idx < 12288; idx += 128) {
        const int g = idx >> 12, r = idx & 4095, c = r >> 6, o = r & 63;
        Ws[idx] = Wp[g][o * 64 + c];
    }

    const float* src = T + (size_t)be * SLAB_ + hw0;
    for (int idx = tid; idx < 2048; idx += 128) {
        const int c  = idx >> 5;
        const int q4 = (idx & 31) << 2;
        *(float4*)(buf + c * 128 + q4) = *(const float4*)(src + c * HW_ + q4);
    }

    const int tx = tid & 15, ty = tid >> 4;

    // accA = x tile (residual + GEMM1 accumulator)
    ull accA[8][4];
    const float* xb = x + (size_t)be * SLAB_ + hw0;
#pragma unroll
    for (int oi = 0; oi < 8; oi++) {
        const int o = (oi < 4) ? (4 * ty + oi) : (32 + 4 * ty + oi - 4);
#pragma unroll
        for (int jh = 0; jh < 2; jh++) {
            const float4 xr = *(const float4*)(xb + (size_t)o * HW_ + jh * 64 + 4 * tx);
            accA[oi][2 * jh]     = pack2(xr.x, xr.y);
            accA[oi][2 * jh + 1] = pack2(xr.z, xr.w);
        }
    }
    __syncthreads();

    // GEMM1: accA += Wo @ T
    gemm_tile(accA, Ws, buf, tx, ty);
    __syncthreads();

    // after -> buf
#pragma unroll
    for (int oi = 0; oi < 8; oi++) {
        const int o = (oi < 4) ? (4 * ty + oi) : (32 + 4 * ty + oi - 4);
#pragma unroll
        for (int jh = 0; jh < 2; jh++) {
            const float2 p0 = unpk(accA[oi][2 * jh]);
            const float2 p1 = unpk(accA[oi][2 * jh + 1]);
            *(float4*)(buf + o * 128 + jh * 64 + 4 * tx) = make_float4(p0.x, p0.y, p1.x, p1.y);
        }
    }
    __syncthreads();

    // GEMM2: accB = W_m1 @ after + b1, then exact GELU
    ull accB[8][4];
#pragma unroll
    for (int oi = 0; oi < 8; oi++) {
        const int o = (oi < 4) ? (4 * ty + oi) : (32 + 4 * ty + oi - 4);
        const ull bv = dup2(bm1[o]);
#pragma unroll
        for (int j = 0; j < 4; j++) accB[oi][j] = bv;
    }
    gemm_tile(accB, Ws + 4096, buf, tx, ty);
#pragma unroll
    for (int oi = 0; oi < 8; oi++)
#pragma unroll
        for (int j = 0; j < 4; j++) {
            float2 f = unpk(accB[oi][j]);
            f.x = 0.5f * f.x * (1.f + erff(f.x * 0.7071067811865475f));
            f.y = 0.5f * f.y * (1.f + erff(f.y * 0.7071067811865475f));
            accB[oi][j] = pack2(f.x, f.y);
        }
    __syncthreads();

    // h1 -> buf
#pragma unroll
    for (int oi = 0; oi < 8; oi++) {
        const int o = (oi < 4) ? (4 * ty + oi) : (32 + 4 * ty + oi - 4);
#pragma unroll
        for (int jh = 0; jh < 2; jh++) {
            const float2 p0 = unpk(accB[oi][2 * jh]);
            const float2 p1 = unpk(accB[oi][2 * jh + 1]);
            *(float4*)(buf + o * 128 + jh * 64 + 4 * tx) = make_float4(p0.x, p0.y, p1.x, p1.y);
        }
    }
    __syncthreads();

    // GEMM3: accB = W_m2 @ h1 + b2;  out = accA(after) + accB
#pragma unroll
    for (int oi = 0; oi < 8; oi++) {
        const int o = (oi < 4) ? (4 * ty + oi) : (32 + 4 * ty + oi - 4);
        const ull bv = dup2(bm2[o]);
#pragma unroll
        for (int j = 0; j < 4; j++) accB[oi][j] = bv;
    }
    gemm_tile(accB, Ws + 8192, buf, tx, ty);

    float* dst = out + (size_t)be * SLAB_ + hw0;
#pragma unroll
    for (int oi = 0; oi < 8; oi++) {
        const int o = (oi < 4) ? (4 * ty + oi) : (32 + 4 * ty + oi - 4);
#pragma unroll
        for (int jh = 0; jh < 2; jh++) {
            const float2 a0 = unpk(accA[oi][2 * jh]);
            const float2 a1 = unpk(accA[oi][2 * jh + 1]);
            const float2 b0 = unpk(accB[oi][2 * jh]);
            const float2 b1 = unpk(accB[oi][2 * jh + 1]);
            float4 r = make_float4(a0.x + b0.x, a0.y + b0.y, a1.x + b1.x, a1.y + b1.y);
            *(float4*)(dst + (size_t)o * HW_ + jh * 64 + 4 * tx) = r;
        }
    }
}

// ============================================================
// Launch
// ============================================================
extern "C" void kernel_launch(void* const* d_in, const int* in_sizes, int n_in,
                              void* d_out, int out_size)
{
    const float* x    = (const float*)d_in[0];
    const float* lng  = (const float*)d_in[1];
    const float* lnb  = (const float*)d_in[2];
    const float* W_v  = (const float*)d_in[3];
    const float* W_k  = (const float*)d_in[4];
    const float* W_q  = (const float*)d_in[5];
    const float* W_o  = (const float*)d_in[6];
    const float* W_m1 = (const float*)d_in[7];
    const float* b_m1 = (const float*)d_in[8];
    const float* W_m2 = (const float*)d_in[9];
    const float* b_m2 = (const float*)d_in[10];
    float* out = (float*)d_out;

    float *pv, *pk, *pq, *pt, *pw;
    cudaGetSymbolAddress((void**)&pv, g_v);
    cudaGetSymbolAddress((void**)&pk, g_k);
    cudaGetSymbolAddress((void**)&pq, g_q);
    cudaGetSymbolAddress((void**)&pt, g_t);
    cudaGetSymbolAddress((void**)&pw, g_wts);

    const int smem_big = 81920;  // 48KB weights + 32KB tile
    cudaFuncSetAttribute(vkq_kernel,  cudaFuncAttributeMaxDynamicSharedMemorySize, smem_big);
    cudaFuncSetAttribute(tail_kernel, cudaFuncAttributeMaxDynamicSharedMemorySize, smem_big);

    ln_stats_kernel<<<BE_, 256>>>(x);

    vkq_kernel<<<dim3(HW_ / 128, BE_), 128, smem_big>>>(x, W_v, W_k, W_q, lng, lnb, pv, pk, pq);

    gram_kernel<<<dim3(C_, B_), 256>>>(pk, pq, pw);

    mixing_kernel<<<dim3(C_, B_, 4), 256>>>(pv, pw, pt);

    tail_kernel<<<dim3(HW_ / 128, BE_), 128, smem_big>>>(pt, x, W_o, W_m1, b_m1, W_m2, b_m2, out);
}

// round 3
// speedup vs baseline: 1.9642x; 1.5851x over previous
#include <cuda_runtime.h>
#include <math.h>

#define B_    4
#define E_    50
#define C_    64
#define HW_   2048
#define BE_   200
#define SLAB_ 131072      // C_*HW_
#define NTOT_ 26214400    // BE_*SLAB_
#define S_    68          // smem row stride (conflict-free for frags)

// ---- scratch (static device globals; no allocation) ----
__device__ float g_v[NTOT_];   // [b][c][e][hw]
__device__ float g_k[NTOT_];   // [b][c][e][hw]
__device__ float g_q[NTOT_];   // [b][c][e][hw]
__device__ float g_t[NTOT_];   // [b][e][c][hw]
__device__ float g_wts[B_ * C_ * E_ * E_];      // w' = softmax - 1/E
__device__ float g_part[B_ * C_ * 4 * 64 * 56]; // gram partials
__device__ float g_mu[BE_];
__device__ float g_rs[BE_];

typedef unsigned int uint32;
typedef unsigned long long ull;

// ---- fp32 -> tf32 ----
__device__ __forceinline__ uint32 to_tf32(float f) {
    uint32 r; asm("cvt.rna.tf32.f32 %0, %1;" : "=r"(r) : "f"(f)); return r;
}

// ---- m16n8k8 tf32 mma ----
__device__ __forceinline__ void mma8(float d[4], uint32 a0, uint32 a1, uint32 a2, uint32 a3,
                                     uint32 b0, uint32 b1) {
    asm volatile(
        "mma.sync.aligned.m16n8k8.row.col.f32.tf32.tf32.f32 "
        "{%0,%1,%2,%3}, {%4,%5,%6,%7}, {%8,%9}, {%0,%1,%2,%3};"
        : "+f"(d[0]), "+f"(d[1]), "+f"(d[2]), "+f"(d[3])
        : "r"(a0), "r"(a1), "r"(a2), "r"(a3), "r"(b0), "r"(b1));
}

// ---- packed f32x2 helpers (mixing kernel) ----
__device__ __forceinline__ ull pack2(float lo, float hi) {
    ull r; asm("mov.b64 %0, {%1, %2};" : "=l"(r) : "f"(lo), "f"(hi)); return r;
}
__device__ __forceinline__ ull dup2(float v) { return pack2(v, v); }
__device__ __forceinline__ void fma2(ull& d, ull a, ull b) {
    asm("fma.rn.f32x2 %0, %1, %2, %0;" : "+l"(d) : "l"(a), "l"(b));
}
__device__ __forceinline__ float2 unpk(ull v) {
    float2 f; asm("mov.b64 {%0, %1}, %2;" : "=f"(f.x), "=f"(f.y) : "l"(v)); return f;
}

// ============================================================
// Kernel 1: LayerNorm statistics per (b,e) slab
// ============================================================
__global__ void ln_stats_kernel(const float* __restrict__ x) {
    const int be = blockIdx.x;
    const float4* p = (const float4*)(x + (size_t)be * SLAB_);
    float s = 0.f, s2 = 0.f;
    for (int i = threadIdx.x; i < SLAB_ / 4; i += blockDim.x) {
        float4 v = p[i];
        s  += v.x + v.y + v.z + v.w;
        s2 += v.x * v.x + v.y * v.y + v.z * v.z + v.w * v.w;
    }
    for (int o = 16; o; o >>= 1) {
        s  += __shfl_down_sync(0xffffffffu, s,  o);
        s2 += __shfl_down_sync(0xffffffffu, s2, o);
    }
    __shared__ float shs[8], shq[8];
    const int w = threadIdx.x >> 5, l = threadIdx.x & 31;
    if (l == 0) { shs[w] = s; shq[w] = s2; }
    __syncthreads();
    if (threadIdx.x == 0) {
        float S = 0.f, Q = 0.f;
        const int nw = blockDim.x >> 5;
        for (int i = 0; i < nw; i++) { S += shs[i]; Q += shq[i]; }
        const float mu  = S * (1.f / (float)SLAB_);
        const float var = Q * (1.f / (float)SLAB_) - mu * mu;
        g_mu[be] = mu;
        g_rs[be] = rsqrtf(var + 1e-5f);
    }
}

// ============================================================
// Kernel 2: fused LN + v/k/q conv via tf32 mma.
// Block: (hw-tile 64, be). 128 threads = 4 warps (wm over out rows).
// Xs[hw][c] stride 68 (transposed, tf32). B-frags shared by 3 GEMMs.
// ============================================================
__global__ void __launch_bounds__(128) vkq_kernel(
    const float* __restrict__ x,
    const float* __restrict__ Wv, const float* __restrict__ Wk, const float* __restrict__ Wq,
    const float* __restrict__ lng, const float* __restrict__ lnb,
    float* __restrict__ ov, float* __restrict__ ok, float* __restrict__ oq)
{
    extern __shared__ uint32 sm[];
    uint32* Ws = sm;             // 3 * 64*S_   [m][o][c]
    uint32* Xs = sm + 3 * 64 * S_; // 64*S_     [hw][c]
    const int be = blockIdx.y, hw0 = blockIdx.x * 64, tid = threadIdx.x;
    const int wid = tid >> 5, lane = tid & 31;
    const int g = lane >> 2, tg = lane & 3;

    // weights -> smem (tf32), [o][c] row-major stride 68
    for (int it = tid; it < 3072; it += 128) {
        const int m = it >> 10, rem = it & 1023, o = rem >> 4, c4 = (rem & 15) << 2;
        const float* Wp = (m == 0) ? Wv : ((m == 1) ? Wk : Wq);
        const float4 w = *(const float4*)(Wp + o * 64 + c4);
        uint4 u = make_uint4(to_tf32(w.x), to_tf32(w.y), to_tf32(w.z), to_tf32(w.w));
        *(uint4*)&Ws[m * 64 * S_ + o * S_ + c4] = u;
    }

    // x tile: LN + transpose -> Xs[hw][c] (tf32)
    const float mu = g_mu[be], rs = g_rs[be];
    const float* xb = x + (size_t)be * SLAB_ + hw0;
    for (int rep = 0; rep < 16; rep++) {
        const int c = wid * 16 + rep;
        const float* xr = xb + c * HW_;
        const float* gr = lng + c * HW_ + hw0;
        const float* br = lnb + c * HW_ + hw0;
#pragma unroll
        for (int h = 0; h < 2; h++) {
            const int hw = lane + 32 * h;
            float v = (xr[hw] - mu) * rs * gr[hw] + br[hw];
            Xs[hw * S_ + c] = to_tf32(v);
        }
    }
    __syncthreads();

    const int ob = wid * 16;
    float acc[3][8][4];
#pragma unroll
    for (int m = 0; m < 3; m++)
#pragma unroll
        for (int nt = 0; nt < 8; nt++)
#pragma unroll
            for (int r = 0; r < 4; r++) acc[m][nt][r] = 0.f;

#pragma unroll
    for (int ks = 0; ks < 8; ks++) {
        uint32 b0[8], b1[8];
#pragma unroll
        for (int nt = 0; nt < 8; nt++) {
            b0[nt] = Xs[(8 * nt + g) * S_ + tg + 8 * ks];
            b1[nt] = Xs[(8 * nt + g) * S_ + tg + 4 + 8 * ks];
        }
#pragma unroll
        for (int m = 0; m < 3; m++) {
            const uint32* W = Ws + m * 64 * S_;
            const uint32 a0 = W[(ob + g) * S_ + tg + 8 * ks];
            const uint32 a1 = W[(ob + g + 8) * S_ + tg + 8 * ks];
            const uint32 a2 = W[(ob + g) * S_ + tg + 4 + 8 * ks];
            const uint32 a3 = W[(ob + g + 8) * S_ + tg + 4 + 8 * ks];
#pragma unroll
            for (int nt = 0; nt < 8; nt++) mma8(acc[m][nt], a0, a1, a2, a3, b0[nt], b1[nt]);
        }
    }

    // epilogue: out layout [b][c_out][e][hw]
    const int bb = be / E_, ee = be % E_;
    float* outs[3] = {ov, ok, oq};
#pragma unroll
    for (int m = 0; m < 3; m++) {
        float* dst = outs[m];
#pragma unroll
        for (int nt = 0; nt < 8; nt++) {
            const int hw = hw0 + 8 * nt + 2 * tg;
            const int o0 = ob + g, o1 = ob + g + 8;
            *(float2*)(dst + ((size_t)(bb * C_ + o0) * E_ + ee) * HW_ + hw) =
                make_float2(acc[m][nt][0], acc[m][nt][1]);
            *(float2*)(dst + ((size_t)(bb * C_ + o1) * E_ + ee) * HW_ + hw) =
                make_float2(acc[m][nt][2], acc[m][nt][3]);
        }
    }
}

// ============================================================
// Kernel 3: gram partials via tf32 mma. grid (64=c, 4=b, 4=z).
// part[i][j] = sum over hw in z-slice of K[i,hw]*Q[j,hw].
// Both operands already k-contiguous -> no transpose.
// ============================================================
__global__ void __launch_bounds__(128) gram_kernel(
    const float* __restrict__ k, const float* __restrict__ q,
    float* __restrict__ part)
{
    extern __shared__ uint32 sm2[];
    uint32* Ks = sm2;             // [i][hw64] stride 68
    uint32* Qs = sm2 + 64 * S_;
    const int nh = blockIdx.x, b = blockIdx.y, z = blockIdx.z;
    const int tid = threadIdx.x, wid = tid >> 5, lane = tid & 31;
    const int g = lane >> 2, tg = lane & 3;
    const float* kb = k + (size_t)(b * C_ + nh) * E_ * HW_;
    const float* qb = q + (size_t)(b * C_ + nh) * E_ * HW_;

    float acc[7][4];
#pragma unroll
    for (int nt = 0; nt < 7; nt++)
#pragma unroll
        for (int r = 0; r < 4; r++) acc[nt][r] = 0.f;

    for (int ch = 0; ch < 8; ch++) {
        const int hwb = z * 512 + ch * 64;
        __syncthreads();
        for (int it = tid; it < 2048; it += 128) {
            const int arr = it >> 10, rem = it & 1023, e = rem >> 4, h4 = (rem & 15) << 2;
            uint4 u = make_uint4(0u, 0u, 0u, 0u);
            if (e < E_) {
                const float* src = arr ? qb : kb;
                const float4 v = *(const float4*)(src + e * HW_ + hwb + h4);
                u = make_uint4(to_tf32(v.x), to_tf32(v.y), to_tf32(v.z), to_tf32(v.w));
            }
            *(uint4*)&((arr ? Qs : Ks)[e * S_ + h4]) = u;
        }
        __syncthreads();

        const int ib = wid * 16;
#pragma unroll
        for (int ks = 0; ks < 8; ks++) {
            const uint32 a0 = Ks[(ib + g) * S_ + tg + 8 * ks];
            const uint32 a1 = Ks[(ib + g + 8) * S_ + tg + 8 * ks];
            const uint32 a2 = Ks[(ib + g) * S_ + tg + 4 + 8 * ks];
            const uint32 a3 = Ks[(ib + g + 8) * S_ + tg + 4 + 8 * ks];
#pragma unroll
            for (int nt = 0; nt < 7; nt++) {
                const uint32 b0 = Qs[(8 * nt + g) * S_ + tg + 8 * ks];
                const uint32 b1 = Qs[(8 * nt + g) * S_ + tg + 4 + 8 * ks];
                mma8(acc[nt], a0, a1, a2, a3, b0, b1);
            }
        }
    }

    float* pd = part + (((size_t)(b * C_ + nh) * 4 + z) * (64 * 56));
    const int ib = wid * 16;
#pragma unroll
    for (int nt = 0; nt < 7; nt++) {
        const int j = 8 * nt + 2 * tg;
        *(float2*)(pd + (ib + g) * 56 + j)     = make_float2(acc[nt][0], acc[nt][1]);
        *(float2*)(pd + (ib + g + 8) * 56 + j) = make_float2(acc[nt][2], acc[nt][3]);
    }
}

// ============================================================
// Kernel 4: reduce partials + softmax over i; write w' = p - 1/E
// ============================================================
__global__ void softmax_kernel(const float* __restrict__ part,
                               float* __restrict__ wts) {
    const int bc = blockIdx.x;
    const int j = threadIdx.x;
    if (j >= E_) return;
    const float* pp = part + (size_t)bc * 4 * (64 * 56);
    const float scale = 0.02209708691207961f;  // 1/sqrt(2048)
    float col[E_];
    float m = -1e30f;
#pragma unroll 10
    for (int i = 0; i < E_; i++) {
        float s = pp[i * 56 + j] + pp[3584 + i * 56 + j]
                + pp[7168 + i * 56 + j] + pp[10752 + i * 56 + j];
        col[i] = s * scale;
        m = fmaxf(m, col[i]);
    }
    float s = 0.f;
#pragma unroll 10
    for (int i = 0; i < E_; i++) { col[i] = expf(col[i] - m); s += col[i]; }
    const float inv = 1.f / s;
    float* wd = wts + (size_t)bc * E_ * E_;
#pragma unroll 10
    for (int i = 0; i < E_; i++) wd[i * E_ + j] = col[i] * inv - 0.02f;
}

// ============================================================
// Kernel 5: ensemble mixing per (b,nh,chunk) (FFMA2):
//   T[j,hw] = V[j,hw] + sum_i w'[i,j] * V[i,hw];  T: [b][e][c][hw]
// ============================================================
__global__ void __launch_bounds__(256) mixing_kernel(
    const float* __restrict__ v, const float* __restrict__ w,
    float* __restrict__ tout)
{
    __shared__ float wsm[E_ * 64];
    __shared__ float Vs[E_ * 64];
    const int nh = blockIdx.x, b = blockIdx.y, ch = blockIdx.z;
    const int tid = threadIdx.x;
    const int tx = tid & 15, ty = tid >> 4;

    const float* wsrc = w + (size_t)(b * C_ + nh) * E_ * E_;
    for (int idx = tid; idx < E_ * 64; idx += 256) {
        const int i = idx >> 6, j = idx & 63;
        wsm[idx] = (j < E_) ? wsrc[i * E_ + j] : 0.f;
    }
    const float* vb = v + (size_t)(b * C_ + nh) * E_ * HW_;

    for (int t = 0; t < 8; t++) {
        const int hw0 = ch * 512 + t * 64;
        __syncthreads();
        for (int idx = tid; idx < E_ * 64; idx += 256) {
            const int i = idx >> 6, hw = idx & 63;
            Vs[idx] = vb[i * HW_ + hw0 + hw];
        }
        __syncthreads();

        ull acc[4][2];
#pragma unroll
        for (int jj = 0; jj < 4; jj++) { acc[jj][0] = 0ull; acc[jj][1] = 0ull; }

#pragma unroll 5
        for (int i = 0; i < E_; i++) {
            const float4 aw = *(const float4*)(wsm + i * 64 + 4 * ty);
            ull ap[4] = {dup2(aw.x), dup2(aw.y), dup2(aw.z), dup2(aw.w)};
            const ulonglong2 bv = *(const ulonglong2*)(Vs + i * 64 + 4 * tx);
#pragma unroll
            for (int jj = 0; jj < 4; jj++) {
                fma2(acc[jj][0], ap[jj], bv.x);
                fma2(acc[jj][1], ap[jj], bv.y);
            }
        }

#pragma unroll
        for (int jj = 0; jj < 4; jj++) {
            const int j = 4 * ty + jj;
            if (j < E_) {
                const float4 vj = *(const float4*)(Vs + j * 64 + 4 * tx);
                const float2 p0 = unpk(acc[jj][0]);
                const float2 p1 = unpk(acc[jj][1]);
                float4 r = make_float4(vj.x + p0.x, vj.y + p0.y, vj.z + p1.x, vj.w + p1.y);
                *(float4*)(tout + ((size_t)(b * E_ + j) * C_ + nh) * HW_ + hw0 + 4 * tx) = r;
            }
        }
    }
}

// ============================================================
// Kernel 6: fused tail via 3 chained tf32 GEMMs (per be, 64-hw tile):
//   after = x + Wo @ T; h1 = gelu(Wm1 @ after + b1); out = after + Wm2 @ h1 + b2
// ============================================================
__global__ void __launch_bounds__(128) tail_kernel(
    const float* __restrict__ T, const float* __restrict__ x,
    const float* __restrict__ Wo, const float* __restrict__ Wm1,
    const float* __restrict__ bm1, const float* __restrict__ Wm2,
    const float* __restrict__ bm2, float* __restrict__ out)
{
    extern __shared__ uint32 sm[];
    uint32* Ws = sm;                 // 3 * 64*S_
    uint32* Ts = sm + 3 * 64 * S_;   // [hw][c]
    uint32* As = Ts + 64 * S_;       // [hw][o]
    const int be = blockIdx.y, hw0 = blockIdx.x * 64, tid = threadIdx.x;
    const int wid = tid >> 5, lane = tid & 31;
    const int g = lane >> 2, tg = lane & 3;
    const int ob = wid * 16;

    for (int it = tid; it < 3072; it += 128) {
        const int m = it >> 10, rem = it & 1023, o = rem >> 4, c4 = (rem & 15) << 2;
        const float* Wp = (m == 0) ? Wo : ((m == 1) ? Wm1 : Wm2);
        const float4 w = *(const float4*)(Wp + o * 64 + c4);
        uint4 u = make_uint4(to_tf32(w.x), to_tf32(w.y), to_tf32(w.z), to_tf32(w.w));
        *(uint4*)&Ws[m * 64 * S_ + o * S_ + c4] = u;
    }

    const float* tb = T + (size_t)be * SLAB_ + hw0;
    for (int rep = 0; rep < 16; rep++) {
        const int c = wid * 16 + rep;
        const float* tr = tb + c * HW_;
#pragma unroll
        for (int h = 0; h < 2; h++) {
            const int hw = lane + 32 * h;
            Ts[hw * S_ + c] = to_tf32(tr[hw]);
        }
    }
    __syncthreads();

    // GEMM1: acc1 = x + Wo @ T
    float acc1[8][4];
    const float* xb = x + (size_t)be * SLAB_ + hw0;
#pragma unroll
    for (int nt = 0; nt < 8; nt++) {
        const int hw = 8 * nt + 2 * tg;
        const float2 r0 = *(const float2*)(xb + (size_t)(ob + g) * HW_ + hw);
        const float2 r1 = *(const float2*)(xb + (size_t)(ob + g + 8) * HW_ + hw);
        acc1[nt][0] = r0.x; acc1[nt][1] = r0.y; acc1[nt][2] = r1.x; acc1[nt][3] = r1.y;
    }
#pragma unroll
    for (int ks = 0; ks < 8; ks++) {
        const uint32* W = Ws;
        const uint32 a0 = W[(ob + g) * S_ + tg + 8 * ks];
        const uint32 a1 = W[(ob + g + 8) * S_ + tg + 8 * ks];
        const uint32 a2 = W[(ob + g) * S_ + tg + 4 + 8 * ks];
        const uint32 a3 = W[(ob + g + 8) * S_ + tg + 4 + 8 * ks];
#pragma unroll
        for (int nt = 0; nt < 8; nt++) {
            const uint32 b0 = Ts[(8 * nt + g) * S_ + tg + 8 * ks];
            const uint32 b1 = Ts[(8 * nt + g) * S_ + tg + 4 + 8 * ks];
            mma8(acc1[nt], a0, a1, a2, a3, b0, b1);
        }
    }
    // after -> As[hw][o] (tf32); conflict-free scatter (bank = 8tg+g+c)
#pragma unroll
    for (int nt = 0; nt < 8; nt++) {
        const int hw = 8 * nt + 2 * tg;
        As[hw * S_ + ob + g]           = to_tf32(acc1[nt][0]);
        As[(hw + 1) * S_ + ob + g]     = to_tf32(acc1[nt][1]);
        As[hw * S_ + ob + g + 8]       = to_tf32(acc1[nt][2]);
        As[(hw + 1) * S_ + ob + g + 8] = to_tf32(acc1[nt][3]);
    }
    __syncthreads();

    // GEMM2: h1 = gelu(Wm1 @ after + b1)
    float acc2[8][4];
    {
        const float bv0 = bm1[ob + g], bv1 = bm1[ob + g + 8];
#pragma unroll
        for (int nt = 0; nt < 8; nt++) {
            acc2[nt][0] = bv0; acc2[nt][1] = bv0; acc2[nt][2] = bv1; acc2[nt][3] = bv1;
        }
    }
#pragma unroll
    for (int ks = 0; ks < 8; ks++) {
        const uint32* W = Ws + 64 * S_;
        const uint32 a0 = W[(ob + g) * S_ + tg + 8 * ks];
        const uint32 a1 = W[(ob + g + 8) * S_ + tg + 8 * ks];
        const uint32 a2 = W[(ob + g) * S_ + tg + 4 + 8 * ks];
        const uint32 a3 = W[(ob + g + 8) * S_ + tg + 4 + 8 * ks];
#pragma unroll
        for (int nt = 0; nt < 8; nt++) {
            const uint32 b0 = As[(8 * nt + g) * S_ + tg + 8 * ks];
            const uint32 b1 = As[(8 * nt + g) * S_ + tg + 4 + 8 * ks];
            mma8(acc2[nt], a0, a1, a2, a3, b0, b1);
        }
    }
#pragma unroll
    for (int nt = 0; nt < 8; nt++)
#pragma unroll
        for (int r = 0; r < 4; r++) {
            const float v = acc2[nt][r];
            acc2[nt][r] = 0.5f * v * (1.f + erff(v * 0.7071067811865475f));
        }
    // h1 -> Ts (reuse; Ts dead after GEMM1 which completed before last sync)
#pragma unroll
    for (int nt = 0; nt < 8; nt++) {
        const int hw = 8 * nt + 2 * tg;
        Ts[hw * S_ + ob + g]           = to_tf32(acc2[nt][0]);
        Ts[(hw + 1) * S_ + ob + g]     = to_tf32(acc2[nt][1]);
        Ts[hw * S_ + ob + g + 8]       = to_tf32(acc2[nt][2]);
        Ts[(hw + 1) * S_ + ob + g + 8] = to_tf32(acc2[nt][3]);
    }
    __syncthreads();

    // GEMM3: out = after + Wm2 @ h1 + b2
    float acc3[8][4];
    {
        const float bv0 = bm2[ob + g], bv1 = bm2[ob + g + 8];
#pragma unroll
        for (int nt = 0; nt < 8; nt++) {
            acc3[nt][0] = bv0; acc3[nt][1] = bv0; acc3[nt][2] = bv1; acc3[nt][3] = bv1;
        }
    }
#pragma unroll
    for (int ks = 0; ks < 8; ks++) {
        const uint32* W = Ws + 2 * 64 * S_;
        const uint32 a0 = W[(ob + g) * S_ + tg + 8 * ks];
        const uint32 a1 = W[(ob + g + 8) * S_ + tg + 8 * ks];
        const uint32 a2 = W[(ob + g) * S_ + tg + 4 + 8 * ks];
        const uint32 a3 = W[(ob + g + 8) * S_ + tg + 4 + 8 * ks];
#pragma unroll
        for (int nt = 0; nt < 8; nt++) {
            const uint32 b0 = Ts[(8 * nt + g) * S_ + tg + 8 * ks];
            const uint32 b1 = Ts[(8 * nt + g) * S_ + tg + 4 + 8 * ks];
            mma8(acc3[nt], a0, a1, a2, a3, b0, b1);
        }
    }

    float* dst = out + (size_t)be * SLAB_ + hw0;
#pragma unroll
    for (int nt = 0; nt < 8; nt++) {
        const int hw = 8 * nt + 2 * tg;
        *(float2*)(dst + (size_t)(ob + g) * HW_ + hw) =
            make_float2(acc1[nt][0] + acc3[nt][0], acc1[nt][1] + acc3[nt][1]);
        *(float2*)(dst + (size_t)(ob + g + 8) * HW_ + hw) =
            make_float2(acc1[nt][2] + acc3[nt][2], acc1[nt][3] + acc3[nt][3]);
    }
}

// ============================================================
// Launch
// ============================================================
extern "C" void kernel_launch(void* const* d_in, const int* in_sizes, int n_in,
                              void* d_out, int out_size)
{
    const float* x    = (const float*)d_in[0];
    const float* lng  = (const float*)d_in[1];
    const float* lnb  = (const float*)d_in[2];
    const float* W_v  = (const float*)d_in[3];
    const float* W_k  = (const float*)d_in[4];
    const float* W_q  = (const float*)d_in[5];
    const float* W_o  = (const float*)d_in[6];
    const float* W_m1 = (const float*)d_in[7];
    const float* b_m1 = (const float*)d_in[8];
    const float* W_m2 = (const float*)d_in[9];
    const float* b_m2 = (const float*)d_in[10];
    float* out = (float*)d_out;

    float *pv, *pk, *pq, *pt, *pw, *pp;
    cudaGetSymbolAddress((void**)&pv, g_v);
    cudaGetSymbolAddress((void**)&pk, g_k);
    cudaGetSymbolAddress((void**)&pq, g_q);
    cudaGetSymbolAddress((void**)&pt, g_t);
    cudaGetSymbolAddress((void**)&pw, g_wts);
    cudaGetSymbolAddress((void**)&pp, g_part);

    const int smem_vkq  = (3 * 64 * S_ + 64 * S_) * 4;           // 69632
    const int smem_gram = (2 * 64 * S_) * 4;                     // 34816
    const int smem_tail = (3 * 64 * S_ + 2 * 64 * S_) * 4;       // 87040
    cudaFuncSetAttribute(vkq_kernel,  cudaFuncAttributeMaxDynamicSharedMemorySize, smem_vkq);
    cudaFuncSetAttribute(gram_kernel, cudaFuncAttributeMaxDynamicSharedMemorySize, smem_gram);
    cudaFuncSetAttribute(tail_kernel, cudaFuncAttributeMaxDynamicSharedMemorySize, smem_tail);

    ln_stats_kernel<<<BE_, 256>>>(x);

    vkq_kernel<<<dim3(HW_ / 64, BE_), 128, smem_vkq>>>(x, W_v, W_k, W_q, lng, lnb, pv, pk, pq);

    gram_kernel<<<dim3(C_, B_, 4), 128, smem_gram>>>(pk, pq, pp);
    softmax_kernel<<<B_ * C_, 64>>>(pp, pw);

    mixing_kernel<<<dim3(C_, B_, 4), 256>>>(pv, pw, pt);

    tail_kernel<<<dim3(HW_ / 64, BE_), 128, smem_tail>>>(pt, x, W_o, W_m1, b_m1, W_m2, b_m2, out);
}

// round 4
// speedup vs baseline: 2.2203x; 1.1304x over previous
#include <cuda_runtime.h>
#include <math.h>

#define B_    4
#define E_    50
#define C_    64
#define HW_   2048
#define BE_   200
#define SLAB_ 131072      // C_*HW_
#define NTOT_ 26214400    // BE_*SLAB_
#define S_    68          // smem row stride (conflict-free frag loads)
#define SM_   60          // mixing smem stride (also conflict-free)

// ---- scratch (static device globals; no allocation) ----
__device__ float g_v[NTOT_];   // [b][c][e][hw]
__device__ float g_k[NTOT_];   // [b][c][e][hw]
__device__ float g_q[NTOT_];   // [b][c][e][hw]
__device__ float g_t[NTOT_];   // [b][e][c][hw]
__device__ float g_wts[B_ * C_ * E_ * E_];      // w' = softmax - 1/E
__device__ float g_part[B_ * C_ * 4 * 64 * 56]; // gram partials
__device__ float g_mu[BE_];
__device__ float g_rs[BE_];

typedef unsigned int uint32;

// ---- fp32 -> tf32 ----
__device__ __forceinline__ uint32 to_tf32(float f) {
    uint32 r; asm("cvt.rna.tf32.f32 %0, %1;" : "=r"(r) : "f"(f)); return r;
}

// ---- m16n8k8 tf32 mma ----
__device__ __forceinline__ void mma8(float d[4], uint32 a0, uint32 a1, uint32 a2, uint32 a3,
                                     uint32 b0, uint32 b1) {
    asm volatile(
        "mma.sync.aligned.m16n8k8.row.col.f32.tf32.tf32.f32 "
        "{%0,%1,%2,%3}, {%4,%5,%6,%7}, {%8,%9}, {%0,%1,%2,%3};"
        : "+f"(d[0]), "+f"(d[1]), "+f"(d[2]), "+f"(d[3])
        : "r"(a0), "r"(a1), "r"(a2), "r"(a3), "r"(b0), "r"(b1));
}

// ============================================================
// Kernel 1: LayerNorm statistics per (b,e) slab
// ============================================================
__global__ void ln_stats_kernel(const float* __restrict__ x) {
    const int be = blockIdx.x;
    const float4* p = (const float4*)(x + (size_t)be * SLAB_);
    float s = 0.f, s2 = 0.f;
    for (int i = threadIdx.x; i < SLAB_ / 4; i += blockDim.x) {
        float4 v = p[i];
        s  += v.x + v.y + v.z + v.w;
        s2 += v.x * v.x + v.y * v.y + v.z * v.z + v.w * v.w;
    }
    for (int o = 16; o; o >>= 1) {
        s  += __shfl_down_sync(0xffffffffu, s,  o);
        s2 += __shfl_down_sync(0xffffffffu, s2, o);
    }
    __shared__ float shs[8], shq[8];
    const int w = threadIdx.x >> 5, l = threadIdx.x & 31;
    if (l == 0) { shs[w] = s; shq[w] = s2; }
    __syncthreads();
    if (threadIdx.x == 0) {
        float S = 0.f, Q = 0.f;
        const int nw = blockDim.x >> 5;
        for (int i = 0; i < nw; i++) { S += shs[i]; Q += shq[i]; }
        const float mu  = S * (1.f / (float)SLAB_);
        const float var = Q * (1.f / (float)SLAB_) - mu * mu;
        g_mu[be] = mu;
        g_rs[be] = rsqrtf(var + 1e-5f);
    }
}

// ============================================================
// Kernel 2: fused LN + v/k/q conv via tf32 mma (unchanged, proven).
// ============================================================
__global__ void __launch_bounds__(128) vkq_kernel(
    const float* __restrict__ x,
    const float* __restrict__ Wv, const float* __restrict__ Wk, const float* __restrict__ Wq,
    const float* __restrict__ lng, const float* __restrict__ lnb,
    float* __restrict__ ov, float* __restrict__ ok, float* __restrict__ oq)
{
    extern __shared__ uint32 sm[];
    uint32* Ws = sm;               // 3 * 64*S_   [m][o][c]
    uint32* Xs = sm + 3 * 64 * S_; // 64*S_      [hw][c]
    const int be = blockIdx.y, hw0 = blockIdx.x * 64, tid = threadIdx.x;
    const int wid = tid >> 5, lane = tid & 31;
    const int g = lane >> 2, tg = lane & 3;

    for (int it = tid; it < 3072; it += 128) {
        const int m = it >> 10, rem = it & 1023, o = rem >> 4, c4 = (rem & 15) << 2;
        const float* Wp = (m == 0) ? Wv : ((m == 1) ? Wk : Wq);
        const float4 w = *(const float4*)(Wp + o * 64 + c4);
        uint4 u = make_uint4(to_tf32(w.x), to_tf32(w.y), to_tf32(w.z), to_tf32(w.w));
        *(uint4*)&Ws[m * 64 * S_ + o * S_ + c4] = u;
    }

    const float mu = g_mu[be], rs = g_rs[be];
    const float* xb = x + (size_t)be * SLAB_ + hw0;
    for (int rep = 0; rep < 16; rep++) {
        const int c = wid * 16 + rep;
        const float* xr = xb + c * HW_;
        const float* gr = lng + c * HW_ + hw0;
        const float* br = lnb + c * HW_ + hw0;
#pragma unroll
        for (int h = 0; h < 2; h++) {
            const int hw = lane + 32 * h;
            float v = (xr[hw] - mu) * rs * gr[hw] + br[hw];
            Xs[hw * S_ + c] = to_tf32(v);
        }
    }
    __syncthreads();

    const int ob = wid * 16;
    float acc[3][8][4];
#pragma unroll
    for (int m = 0; m < 3; m++)
#pragma unroll
        for (int nt = 0; nt < 8; nt++)
#pragma unroll
            for (int r = 0; r < 4; r++) acc[m][nt][r] = 0.f;

#pragma unroll
    for (int ks = 0; ks < 8; ks++) {
        uint32 b0[8], b1[8];
#pragma unroll
        for (int nt = 0; nt < 8; nt++) {
            b0[nt] = Xs[(8 * nt + g) * S_ + tg + 8 * ks];
            b1[nt] = Xs[(8 * nt + g) * S_ + tg + 4 + 8 * ks];
        }
#pragma unroll
        for (int m = 0; m < 3; m++) {
            const uint32* W = Ws + m * 64 * S_;
            const uint32 a0 = W[(ob + g) * S_ + tg + 8 * ks];
            const uint32 a1 = W[(ob + g + 8) * S_ + tg + 8 * ks];
            const uint32 a2 = W[(ob + g) * S_ + tg + 4 + 8 * ks];
            const uint32 a3 = W[(ob + g + 8) * S_ + tg + 4 + 8 * ks];
#pragma unroll
            for (int nt = 0; nt < 8; nt++) mma8(acc[m][nt], a0, a1, a2, a3, b0[nt], b1[nt]);
        }
    }

    const int bb = be / E_, ee = be % E_;
    float* outs[3] = {ov, ok, oq};
#pragma unroll
    for (int m = 0; m < 3; m++) {
        float* dst = outs[m];
#pragma unroll
        for (int nt = 0; nt < 8; nt++) {
            const int hw = hw0 + 8 * nt + 2 * tg;
            const int o0 = ob + g, o1 = ob + g + 8;
            *(float2*)(dst + ((size_t)(bb * C_ + o0) * E_ + ee) * HW_ + hw) =
                make_float2(acc[m][nt][0], acc[m][nt][1]);
            *(float2*)(dst + ((size_t)(bb * C_ + o1) * E_ + ee) * HW_ + hw) =
                make_float2(acc[m][nt][2], acc[m][nt][3]);
        }
    }
}

// ============================================================
// Kernel 3: gram partials via tf32 mma (unchanged, proven).
// ============================================================
__global__ void __launch_bounds__(128) gram_kernel(
    const float* __restrict__ k, const float* __restrict__ q,
    float* __restrict__ part)
{
    extern __shared__ uint32 sm2[];
    uint32* Ks = sm2;
    uint32* Qs = sm2 + 64 * S_;
    const int nh = blockIdx.x, b = blockIdx.y, z = blockIdx.z;
    const int tid = threadIdx.x, wid = tid >> 5, lane = tid & 31;
    const int g = lane >> 2, tg = lane & 3;
    const float* kb = k + (size_t)(b * C_ + nh) * E_ * HW_;
    const float* qb = q + (size_t)(b * C_ + nh) * E_ * HW_;

    float acc[7][4];
#pragma unroll
    for (int nt = 0; nt < 7; nt++)
#pragma unroll
        for (int r = 0; r < 4; r++) acc[nt][r] = 0.f;

    for (int ch = 0; ch < 8; ch++) {
        const int hwb = z * 512 + ch * 64;
        __syncthreads();
        for (int it = tid; it < 2048; it += 128) {
            const int arr = it >> 10, rem = it & 1023, e = rem >> 4, h4 = (rem & 15) << 2;
            uint4 u = make_uint4(0u, 0u, 0u, 0u);
            if (e < E_) {
                const float* src = arr ? qb : kb;
                const float4 v = *(const float4*)(src + e * HW_ + hwb + h4);
                u = make_uint4(to_tf32(v.x), to_tf32(v.y), to_tf32(v.z), to_tf32(v.w));
            }
            *(uint4*)&((arr ? Qs : Ks)[e * S_ + h4]) = u;
        }
        __syncthreads();

        const int ib = wid * 16;
#pragma unroll
        for (int ks = 0; ks < 8; ks++) {
            const uint32 a0 = Ks[(ib + g) * S_ + tg + 8 * ks];
            const uint32 a1 = Ks[(ib + g + 8) * S_ + tg + 8 * ks];
            const uint32 a2 = Ks[(ib + g) * S_ + tg + 4 + 8 * ks];
            const uint32 a3 = Ks[(ib + g + 8) * S_ + tg + 4 + 8 * ks];
#pragma unroll
            for (int nt = 0; nt < 7; nt++) {
                const uint32 b0 = Qs[(8 * nt + g) * S_ + tg + 8 * ks];
                const uint32 b1 = Qs[(8 * nt + g) * S_ + tg + 4 + 8 * ks];
                mma8(acc[nt], a0, a1, a2, a3, b0, b1);
            }
        }
    }

    float* pd = part + (((size_t)(b * C_ + nh) * 4 + z) * (64 * 56));
    const int ib = wid * 16;
#pragma unroll
    for (int nt = 0; nt < 7; nt++) {
        const int j = 8 * nt + 2 * tg;
        *(float2*)(pd + (ib + g) * 56 + j)     = make_float2(acc[nt][0], acc[nt][1]);
        *(float2*)(pd + (ib + g + 8) * 56 + j) = make_float2(acc[nt][2], acc[nt][3]);
    }
}

// ============================================================
// Kernel 4: reduce partials + softmax; 4 (b,c) pairs per block.
// ============================================================
__global__ void __launch_bounds__(256) softmax_kernel(const float* __restrict__ part,
                                                      float* __restrict__ wts) {
    const int bc = blockIdx.x * 4 + (threadIdx.x >> 6);
    const int j = threadIdx.x & 63;
    if (j >= E_) return;
    const float* pp = part + (size_t)bc * 4 * (64 * 56);
    const float scale = 0.02209708691207961f;  // 1/sqrt(2048)
    float col[E_];
    float m = -1e30f;
#pragma unroll 10
    for (int i = 0; i < E_; i++) {
        float s = pp[i * 56 + j] + pp[3584 + i * 56 + j]
                + pp[7168 + i * 56 + j] + pp[10752 + i * 56 + j];
        col[i] = s * scale;
        m = fmaxf(m, col[i]);
    }
    float s = 0.f;
#pragma unroll 10
    for (int i = 0; i < E_; i++) { col[i] = expf(col[i] - m); s += col[i]; }
    const float inv = 1.f / s;
    float* wd = wts + (size_t)bc * E_ * E_;
#pragma unroll 10
    for (int i = 0; i < E_; i++) wd[i * E_ + j] = col[i] * inv - 0.02f;
}

// ============================================================
// Kernel 5: ensemble mixing via tf32 mma per (b,nh,z):
//   T[j,hw] = V[j,hw] + sum_i w'[i,j] * V[i,hw]
// A = w'^T [j][i] (M=64 pad, K=56 pad); B = V^T [hw][i] tf32;
// Vf keeps fp32 V for the exact residual add.
// ============================================================
__global__ void __launch_bounds__(128) mixing_kernel(
    const float* __restrict__ v, const float* __restrict__ w,
    float* __restrict__ tout)
{
    extern __shared__ uint32 sm3[];
    uint32* As = sm3;                 // [j][i]  64 x SM_
    uint32* Vs = sm3 + 64 * SM_;      // [hw][i] 64 x SM_ (tf32, transposed)
    float*  Vf = (float*)(sm3 + 2 * 64 * SM_);  // [i][hw] 64 x S_ fp32
    const int nh = blockIdx.x, b = blockIdx.y, z = blockIdx.z;
    const int tid = threadIdx.x, wid = tid >> 5, lane = tid & 31;
    const int g = lane >> 2, tg = lane & 3;
    const int ob = wid * 16;
    const int bc = b * C_ + nh;

    // zero A (covers j>=50 rows and i>=50 pad)
    for (int idx = tid; idx < 64 * SM_; idx += 128) As[idx] = 0u;
    // zero Vs pad columns i=50..55 (never rewritten)
    for (int idx = tid; idx < 64 * 6; idx += 128) {
        const int hw = idx / 6, i = 50 + idx % 6;
        Vs[hw * SM_ + i] = 0u;
    }
    __syncthreads();
    // A[j][i] = w'[i][j]
    const float* wsrc = w + (size_t)bc * E_ * E_;
    for (int idx = tid; idx < E_ * E_; idx += 128) {
        const int i = idx / E_, j = idx - i * E_;
        As[j * SM_ + i] = to_tf32(wsrc[idx]);
    }

    const float* vb = v + (size_t)bc * E_ * HW_;

    for (int t = 0; t < 8; t++) {
        const int hw0 = z * 512 + t * 64;
        __syncthreads();
        // load V tile: Vs[hw][i] (tf32) + Vf[i][hw] (fp32)
        for (int p = tid; p < E_ * 64; p += 128) {
            const int i = p >> 6, hw = p & 63;
            const float val = vb[i * HW_ + hw0 + hw];
            Vs[hw * SM_ + i] = to_tf32(val);
            Vf[i * S_ + hw] = val;
        }
        __syncthreads();

        float acc[8][4];
#pragma unroll
        for (int nt = 0; nt < 8; nt++)
#pragma unroll
            for (int r = 0; r < 4; r++) acc[nt][r] = 0.f;

#pragma unroll
        for (int ks = 0; ks < 7; ks++) {
            const uint32 a0 = As[(ob + g) * SM_ + tg + 8 * ks];
            const uint32 a1 = As[(ob + g + 8) * SM_ + tg + 8 * ks];
            const uint32 a2 = As[(ob + g) * SM_ + tg + 4 + 8 * ks];
            const uint32 a3 = As[(ob + g + 8) * SM_ + tg + 4 + 8 * ks];
#pragma unroll
            for (int nt = 0; nt < 8; nt++) {
                const uint32 b0 = Vs[(8 * nt + g) * SM_ + tg + 8 * ks];
                const uint32 b1 = Vs[(8 * nt + g) * SM_ + tg + 4 + 8 * ks];
                mma8(acc[nt], a0, a1, a2, a3, b0, b1);
            }
        }

        const int j0 = ob + g, j1 = ob + g + 8;
#pragma unroll
        for (int nt = 0; nt < 8; nt++) {
            const int hw = 8 * nt + 2 * tg;
            if (j0 < E_) {
                const float2 vv = *(const float2*)(Vf + j0 * S_ + hw);
                *(float2*)(tout + ((size_t)(b * E_ + j0) * C_ + nh) * HW_ + hw0 + hw) =
                    make_float2(vv.x + acc[nt][0], vv.y + acc[nt][1]);
            }
            if (j1 < E_) {
                const float2 vv = *(const float2*)(Vf + j1 * S_ + hw);
                *(float2*)(tout + ((size_t)(b * E_ + j1) * C_ + nh) * HW_ + hw0 + hw) =
                    make_float2(vv.x + acc[nt][2], vv.y + acc[nt][3]);
            }
        }
    }
}

// ============================================================
// Kernel 6: fused tail, 256 threads, 128-hw tile, single data buffer:
//   after = x + Wo @ T; h1 = gelu(Wm1 @ after + b1); out = after + Wm2 @ h1 + b2
// ============================================================
__global__ void __launch_bounds__(256) tail_kernel(
    const float* __restrict__ T, const float* __restrict__ x,
    const float* __restrict__ Wo, const float* __restrict__ Wm1,
    const float* __restrict__ bm1, const float* __restrict__ Wm2,
    const float* __restrict__ bm2, float* __restrict__ out)
{
    extern __shared__ uint32 sm[];
    uint32* Ws = sm;                 // 3 * 64*S_
    uint32* Ds = sm + 3 * 64 * S_;   // [hw 128][c 64] stride S_
    const int be = blockIdx.y, hw0 = blockIdx.x * 128, tid = threadIdx.x;
    const int wid = tid >> 5, lane = tid & 31;
    const int g = lane >> 2, tg = lane & 3;
    const int ob = (wid & 3) * 16;        // m-tile
    const int nh0 = (wid >> 2) * 64;      // hw half

    for (int it = tid; it < 3072; it += 256) {
        const int m = it >> 10, rem = it & 1023, o = rem >> 4, c4 = (rem & 15) << 2;
        const float* Wp = (m == 0) ? Wo : ((m == 1) ? Wm1 : Wm2);
        const float4 w = *(const float4*)(Wp + o * 64 + c4);
        uint4 u = make_uint4(to_tf32(w.x), to_tf32(w.y), to_tf32(w.z), to_tf32(w.w));
        *(uint4*)&Ws[m * 64 * S_ + o * S_ + c4] = u;
    }

    // T tile -> Ds[hw][c]
    const float* tb = T + (size_t)be * SLAB_ + hw0;
    for (int rep = 0; rep < 8; rep++) {
        const int c = (tid >> 5) * 8 + rep;
        const float* tr = tb + c * HW_;
#pragma unroll
        for (int h = 0; h < 4; h++) {
            const int hw = lane + 32 * h;
            Ds[hw * S_ + c] = to_tf32(tr[hw]);
        }
    }
    __syncthreads();

    // GEMM1: acc1 = x + Wo @ T
    float acc1[8][4];
    const float* xb = x + (size_t)be * SLAB_ + hw0;
#pragma unroll
    for (int nt = 0; nt < 8; nt++) {
        const int hw = nh0 + 8 * nt + 2 * tg;
        const float2 r0 = *(const float2*)(xb + (size_t)(ob + g) * HW_ + hw);
        const float2 r1 = *(const float2*)(xb + (size_t)(ob + g + 8) * HW_ + hw);
        acc1[nt][0] = r0.x; acc1[nt][1] = r0.y; acc1[nt][2] = r1.x; acc1[nt][3] = r1.y;
    }
#pragma unroll
    for (int ks = 0; ks < 8; ks++) {
        const uint32* W = Ws;
        const uint32 a0 = W[(ob + g) * S_ + tg + 8 * ks];
        const uint32 a1 = W[(ob + g + 8) * S_ + tg + 8 * ks];
        const uint32 a2 = W[(ob + g) * S_ + tg + 4 + 8 * ks];
        const uint32 a3 = W[(ob + g + 8) * S_ + tg + 4 + 8 * ks];
#pragma unroll
        for (int nt = 0; nt < 8; nt++) {
            const uint32 b0 = Ds[(nh0 + 8 * nt + g) * S_ + tg + 8 * ks];
            const uint32 b1 = Ds[(nh0 + 8 * nt + g) * S_ + tg + 4 + 8 * ks];
            mma8(acc1[nt], a0, a1, a2, a3, b0, b1);
        }
    }
    __syncthreads();   // everyone done reading T from Ds

    // after -> Ds
#pragma unroll
    for (int nt = 0; nt < 8; nt++) {
        const int hw = nh0 + 8 * nt + 2 * tg;
        Ds[hw * S_ + ob + g]           = to_tf32(acc1[nt][0]);
        Ds[(hw + 1) * S_ + ob + g]     = to_tf32(acc1[nt][1]);
        Ds[hw * S_ + ob + g + 8]       = to_tf32(acc1[nt][2]);
        Ds[(hw + 1) * S_ + ob + g + 8] = to_tf32(acc1[nt][3]);
    }
    __syncthreads();

    // GEMM2: h1 = gelu(Wm1 @ after + b1)
    float acc2[8][4];
    {
        const float bv0 = bm1[ob + g], bv1 = bm1[ob + g + 8];
#pragma unroll
        for (int nt = 0; nt < 8; nt++) {
            acc2[nt][0] = bv0; acc2[nt][1] = bv0; acc2[nt][2] = bv1; acc2[nt][3] = bv1;
        }
    }
#pragma unroll
    for (int ks = 0; ks < 8; ks++) {
        const uint32* W = Ws + 64 * S_;
        const uint32 a0 = W[(ob + g) * S_ + tg + 8 * ks];
        const uint32 a1 = W[(ob + g + 8) * S_ + tg + 8 * ks];
        const uint32 a2 = W[(ob + g) * S_ + tg + 4 + 8 * ks];
        const uint32 a3 = W[(ob + g + 8) * S_ + tg + 4 + 8 * ks];
#pragma unroll
        for (int nt = 0; nt < 8; nt++) {
            const uint32 b0 = Ds[(nh0 + 8 * nt + g) * S_ + tg + 8 * ks];
            const uint32 b1 = Ds[(nh0 + 8 * nt + g) * S_ + tg + 4 + 8 * ks];
            mma8(acc2[nt], a0, a1, a2, a3, b0, b1);
        }
    }
#pragma unroll
    for (int nt = 0; nt < 8; nt++)
#pragma unroll
        for (int r = 0; r < 4; r++) {
            const float v = acc2[nt][r];
            acc2[nt][r] = 0.5f * v * (1.f + erff(v * 0.7071067811865475f));
        }
    __syncthreads();   // everyone done reading 'after' from Ds

    // h1 -> Ds
#pragma unroll
    for (int nt = 0; nt < 8; nt++) {
        const int hw = nh0 + 8 * nt + 2 * tg;
        Ds[hw * S_ + ob + g]           = to_tf32(acc2[nt][0]);
        Ds[(hw + 1) * S_ + ob + g]     = to_tf32(acc2[nt][1]);
        Ds[hw * S_ + ob + g + 8]       = to_tf32(acc2[nt][2]);
        Ds[(hw + 1) * S_ + ob + g + 8] = to_tf32(acc2[nt][3]);
    }
    __syncthreads();

    // GEMM3: out = after + Wm2 @ h1 + b2
    float acc3[8][4];
    {
        const float bv0 = bm2[ob + g], bv1 = bm2[ob + g + 8];
#pragma unroll
        for (int nt = 0; nt < 8; nt++) {
            acc3[nt][0] = bv0; acc3[nt][1] = bv0; acc3[nt][2] = bv1; acc3[nt][3] = bv1;
        }
    }
#pragma unroll
    for (int ks = 0; ks < 8; ks++) {
        const uint32* W = Ws + 2 * 64 * S_;
        const uint32 a0 = W[(ob + g) * S_ + tg + 8 * ks];
        const uint32 a1 = W[(ob + g + 8) * S_ + tg + 8 * ks];
        const uint32 a2 = W[(ob + g) * S_ + tg + 4 + 8 * ks];
        const uint32 a3 = W[(ob + g + 8) * S_ + tg + 4 + 8 * ks];
#pragma unroll
        for (int nt = 0; nt < 8; nt++) {
            const uint32 b0 = Ds[(nh0 + 8 * nt + g) * S_ + tg + 8 * ks];
            const uint32 b1 = Ds[(nh0 + 8 * nt + g) * S_ + tg + 4 + 8 * ks];
            mma8(acc3[nt], a0, a1, a2, a3, b0, b1);
        }
    }

    float* dst = out + (size_t)be * SLAB_ + hw0;
#pragma unroll
    for (int nt = 0; nt < 8; nt++) {
        const int hw = nh0 + 8 * nt + 2 * tg;
        *(float2*)(dst + (size_t)(ob + g) * HW_ + hw) =
            make_float2(acc1[nt][0] + acc3[nt][0], acc1[nt][1] + acc3[nt][1]);
        *(float2*)(dst + (size_t)(ob + g + 8) * HW_ + hw) =
            make_float2(acc1[nt][2] + acc3[nt][2], acc1[nt][3] + acc3[nt][3]);
    }
}

// ============================================================
// Launch
// ============================================================
extern "C" void kernel_launch(void* const* d_in, const int* in_sizes, int n_in,
                              void* d_out, int out_size)
{
    const float* x    = (const float*)d_in[0];
    const float* lng  = (const float*)d_in[1];
    const float* lnb  = (const float*)d_in[2];
    const float* W_v  = (const float*)d_in[3];
    const float* W_k  = (const float*)d_in[4];
    const float* W_q  = (const float*)d_in[5];
    const float* W_o  = (const float*)d_in[6];
    const float* W_m1 = (const float*)d_in[7];
    const float* b_m1 = (const float*)d_in[8];
    const float* W_m2 = (const float*)d_in[9];
    const float* b_m2 = (const float*)d_in[10];
    float* out = (float*)d_out;

    float *pv, *pk, *pq, *pt, *pw, *pp;
    cudaGetSymbolAddress((void**)&pv, g_v);
    cudaGetSymbolAddress((void**)&pk, g_k);
    cudaGetSymbolAddress((void**)&pq, g_q);
    cudaGetSymbolAddress((void**)&pt, g_t);
    cudaGetSymbolAddress((void**)&pw, g_wts);
    cudaGetSymbolAddress((void**)&pp, g_part);

    const int smem_vkq  = (3 * 64 * S_ + 64 * S_) * 4;            // 69632
    const int smem_gram = (2 * 64 * S_) * 4;                      // 34816
    const int smem_mix  = (2 * 64 * SM_ + 64 * S_) * 4;           // 48128
    const int smem_tail = (3 * 64 * S_ + 128 * S_) * 4;           // 87040
    cudaFuncSetAttribute(vkq_kernel,    cudaFuncAttributeMaxDynamicSharedMemorySize, smem_vkq);
    cudaFuncSetAttribute(gram_kernel,   cudaFuncAttributeMaxDynamicSharedMemorySize, smem_gram);
    cudaFuncSetAttribute(mixing_kernel, cudaFuncAttributeMaxDynamicSharedMemorySize, smem_mix);
    cudaFuncSetAttribute(tail_kernel,   cudaFuncAttributeMaxDynamicSharedMemorySize, smem_tail);

    ln_stats_kernel<<<BE_, 256>>>(x);

    vkq_kernel<<<dim3(HW_ / 64, BE_), 128, smem_vkq>>>(x, W_v, W_k, W_q, lng, lnb, pv, pk, pq);

    gram_kernel<<<dim3(C_, B_, 4), 128, smem_gram>>>(pk, pq, pp);
    softmax_kernel<<<B_ * C_ / 4, 256>>>(pp, pw);

    mixing_kernel<<<dim3(C_, B_, 4), 128, smem_mix>>>(pv, pw, pt);

    tail_kernel<<<dim3(HW_ / 128, BE_), 256, smem_tail>>>(pt, x, W_o, W_m1, b_m1, W_m2, b_m2, out);
}

// round 5
// speedup vs baseline: 2.4835x; 1.1186x over previous
#include <cuda_runtime.h>
#include <cuda_bf16.h>
#include <math.h>

#define B_    4
#define E_    50
#define C_    64
#define HW_   2048
#define BE_   200
#define SLAB_ 131072      // C_*HW_
#define NTOT_ 26214400    // BE_*SLAB_
#define SB_   72          // bf16 smem row stride (36 granules == 4 mod 32 -> frag loads conflict-free)

typedef unsigned int uint32;
typedef __nv_bfloat16 bf16;
typedef __nv_bfloat162 bf162;

// ---- scratch (static device globals; no allocation). Used as bf16. ----
__device__ bf16 g_v[NTOT_];   // [b][c][e][hw]
__device__ bf16 g_k[NTOT_];   // [b][c][e][hw]
__device__ bf16 g_q[NTOT_];   // [b][c][e][hw]
__device__ bf16 g_t[NTOT_];   // [b][e][c][hw]
__device__ float g_wts[B_ * C_ * E_ * E_];  // w' = softmax - 1/E
__device__ float g_mu[BE_];
__device__ float g_rs[BE_];

__device__ __forceinline__ uint32 bpack(float a, float b) {
    bf162 h = __floats2bfloat162_rn(a, b);
    return *(uint32*)&h;
}

// m16n8k16 bf16 mma, fp32 accumulate
__device__ __forceinline__ void mma16(float d[4], uint32 a0, uint32 a1, uint32 a2, uint32 a3,
                                      uint32 b0, uint32 b1) {
    asm volatile(
        "mma.sync.aligned.m16n8k16.row.col.f32.bf16.bf16.f32 "
        "{%0,%1,%2,%3}, {%4,%5,%6,%7}, {%8,%9}, {%0,%1,%2,%3};"
        : "+f"(d[0]), "+f"(d[1]), "+f"(d[2]), "+f"(d[3])
        : "r"(a0), "r"(a1), "r"(a2), "r"(a3), "r"(b0), "r"(b1));
}

// ============================================================
// Kernel 1: LayerNorm statistics per (b,e) slab
// ============================================================
__global__ void ln_stats_kernel(const float* __restrict__ x) {
    const int be = blockIdx.x;
    const float4* p = (const float4*)(x + (size_t)be * SLAB_);
    float s = 0.f, s2 = 0.f;
    for (int i = threadIdx.x; i < SLAB_ / 4; i += blockDim.x) {
        float4 v = p[i];
        s  += v.x + v.y + v.z + v.w;
        s2 += v.x * v.x + v.y * v.y + v.z * v.z + v.w * v.w;
    }
    for (int o = 16; o; o >>= 1) {
        s  += __shfl_down_sync(0xffffffffu, s,  o);
        s2 += __shfl_down_sync(0xffffffffu, s2, o);
    }
    __shared__ float shs[8], shq[8];
    const int w = threadIdx.x >> 5, l = threadIdx.x & 31;
    if (l == 0) { shs[w] = s; shq[w] = s2; }
    __syncthreads();
    if (threadIdx.x == 0) {
        float S = 0.f, Q = 0.f;
        const int nw = blockDim.x >> 5;
        for (int i = 0; i < nw; i++) { S += shs[i]; Q += shq[i]; }
        const float mu  = S * (1.f / (float)SLAB_);
        const float var = Q * (1.f / (float)SLAB_) - mu * mu;
        g_mu[be] = mu;
        g_rs[be] = rsqrtf(var + 1e-5f);
    }
}

// ============================================================
// Kernel 2: fused LN + v/k/q conv via bf16 mma.
// Block: (64-hw tile, be), 128 threads / 4 warps.
// ============================================================
__global__ void __launch_bounds__(128) vkq_kernel(
    const float* __restrict__ x,
    const float* __restrict__ Wv, const float* __restrict__ Wk, const float* __restrict__ Wq,
    const float* __restrict__ lng, const float* __restrict__ lnb,
    bf16* __restrict__ ov, bf16* __restrict__ ok, bf16* __restrict__ oq)
{
    extern __shared__ bf16 smb[];
    bf16* Ws = smb;                // [3][64 o][SB_]  cols = c
    bf16* Xs = smb + 3 * 64 * SB_; // [64 hw][SB_]    cols = c
    const int be = blockIdx.y, hw0 = blockIdx.x * 64, tid = threadIdx.x;
    const int wid = tid >> 5, lane = tid & 31;
    const int g = lane >> 2, tg = lane & 3;
    const int ob = wid * 16;

    // weights -> smem bf16
    for (int it = tid; it < 3072; it += 128) {
        const int m = it >> 10, rem = it & 1023, o = rem >> 4, c4 = (rem & 15) << 2;
        const float* Wp = (m == 0) ? Wv : ((m == 1) ? Wk : Wq);
        const float4 w = *(const float4*)(Wp + o * 64 + c4);
        bf16* dst = Ws + m * 64 * SB_ + o * SB_ + c4;
        *(bf162*)(dst)     = __floats2bfloat162_rn(w.x, w.y);
        *(bf162*)(dst + 2) = __floats2bfloat162_rn(w.z, w.w);
    }

    // x tile: LN + transpose -> Xs[hw][c]
    const float mu = g_mu[be], rs = g_rs[be];
    const float* xb = x + (size_t)be * SLAB_ + hw0;
    for (int rep = 0; rep < 16; rep++) {
        const int c = wid * 16 + rep;
        const float* xr = xb + c * HW_;
        const float* gr = lng + c * HW_ + hw0;
        const float* br = lnb + c * HW_ + hw0;
#pragma unroll
        for (int h = 0; h < 2; h++) {
            const int hw = lane + 32 * h;
            const float v = (xr[hw] - mu) * rs * gr[hw] + br[hw];
            Xs[hw * SB_ + c] = __float2bfloat16(v);
        }
    }
    __syncthreads();

    float acc[3][8][4];
#pragma unroll
    for (int m = 0; m < 3; m++)
#pragma unroll
        for (int nt = 0; nt < 8; nt++)
#pragma unroll
            for (int r = 0; r < 4; r++) acc[m][nt][r] = 0.f;

#pragma unroll
    for (int ks = 0; ks < 4; ks++) {
        const int kc = 16 * ks + 2 * tg;
        uint32 b0[8], b1[8];
#pragma unroll
        for (int nt = 0; nt < 8; nt++) {
            b0[nt] = *(const uint32*)&Xs[(8 * nt + g) * SB_ + kc];
            b1[nt] = *(const uint32*)&Xs[(8 * nt + g) * SB_ + kc + 8];
        }
#pragma unroll
        for (int m = 0; m < 3; m++) {
            const bf16* W = Ws + m * 64 * SB_;
            const uint32 a0 = *(const uint32*)&W[(ob + g) * SB_ + kc];
            const uint32 a1 = *(const uint32*)&W[(ob + g + 8) * SB_ + kc];
            const uint32 a2 = *(const uint32*)&W[(ob + g) * SB_ + kc + 8];
            const uint32 a3 = *(const uint32*)&W[(ob + g + 8) * SB_ + kc + 8];
#pragma unroll
            for (int nt = 0; nt < 8; nt++) mma16(acc[m][nt], a0, a1, a2, a3, b0[nt], b1[nt]);
        }
    }

    // epilogue: [b][c_out][e][hw] bf16
    const int bb = be / E_, ee = be % E_;
    bf16* outs[3] = {ov, ok, oq};
#pragma unroll
    for (int m = 0; m < 3; m++) {
        bf16* dst = outs[m];
#pragma unroll
        for (int nt = 0; nt < 8; nt++) {
            const int hw = hw0 + 8 * nt + 2 * tg;
            const int o0 = ob + g, o1 = ob + g + 8;
            *(bf162*)&dst[((size_t)(bb * C_ + o0) * E_ + ee) * HW_ + hw] =
                __floats2bfloat162_rn(acc[m][nt][0], acc[m][nt][1]);
            *(bf162*)&dst[((size_t)(bb * C_ + o1) * E_ + ee) * HW_ + hw] =
                __floats2bfloat162_rn(acc[m][nt][2], acc[m][nt][3]);
        }
    }
}

// ============================================================
// Kernel 3: gram via bf16 mma + in-block softmax. grid (64, 4).
// gram[i][j] = scale * sum_hw K[i,hw]*Q[j,hw]; softmax over i;
// writes w' = p - 1/E.
// ============================================================
__global__ void __launch_bounds__(128) gram_kernel(
    const bf16* __restrict__ k, const bf16* __restrict__ q,
    float* __restrict__ wts)
{
    extern __shared__ bf16 smg[];
    bf16* Ks = smg;            // [64 i][SB_] cols = hw-chunk
    bf16* Qs = smg + 64 * SB_;
    const int nh = blockIdx.x, b = blockIdx.y, tid = threadIdx.x;
    const int wid = tid >> 5, lane = tid & 31;
    const int g = lane >> 2, tg = lane & 3;
    const int ib = wid * 16;
    const bf16* kb = k + (size_t)(b * C_ + nh) * E_ * HW_;
    const bf16* qb = q + (size_t)(b * C_ + nh) * E_ * HW_;

    // zero pad rows e = 50..63 (cols 0..63)
    for (int idx = tid; idx < 14 * 64; idx += 128) {
        const int e = 50 + (idx >> 6), c = idx & 63;
        Ks[e * SB_ + c] = __float2bfloat16(0.f);
        Qs[e * SB_ + c] = __float2bfloat16(0.f);
    }

    float acc[7][4];
#pragma unroll
    for (int nt = 0; nt < 7; nt++)
#pragma unroll
        for (int r = 0; r < 4; r++) acc[nt][r] = 0.f;

    for (int ch = 0; ch < 32; ch++) {
        const int hwb = ch * 64;
        __syncthreads();
        for (int it = tid; it < 800; it += 128) {   // 2 arrays * 50 rows * 8 uint4
            const int arr = it / 400, rem = it % 400, e = rem >> 3, h8 = (rem & 7) << 3;
            const bf16* src = arr ? qb : kb;
            const uint4 v = *(const uint4*)&src[e * HW_ + hwb + h8];
            *(uint4*)&((arr ? Qs : Ks)[e * SB_ + h8]) = v;
        }
        __syncthreads();

#pragma unroll
        for (int ks = 0; ks < 4; ks++) {
            const int kc = 16 * ks + 2 * tg;
            const uint32 a0 = *(const uint32*)&Ks[(ib + g) * SB_ + kc];
            const uint32 a1 = *(const uint32*)&Ks[(ib + g + 8) * SB_ + kc];
            const uint32 a2 = *(const uint32*)&Ks[(ib + g) * SB_ + kc + 8];
            const uint32 a3 = *(const uint32*)&Ks[(ib + g + 8) * SB_ + kc + 8];
#pragma unroll
            for (int nt = 0; nt < 7; nt++) {
                const uint32 b0 = *(const uint32*)&Qs[(8 * nt + g) * SB_ + kc];
                const uint32 b1 = *(const uint32*)&Qs[(8 * nt + g) * SB_ + kc + 8];
                mma16(acc[nt], a0, a1, a2, a3, b0, b1);
            }
        }
    }

    // gram -> smem (fp32, reuse tile memory), then column softmax
    __syncthreads();
    float* gsm = (float*)smg;   // 64 x 56 floats = 14336 B (< 18432)
    const float scale = 0.02209708691207961f;   // 1/sqrt(2048)
#pragma unroll
    for (int nt = 0; nt < 7; nt++) {
        const int j = 8 * nt + 2 * tg;
        *(float2*)&gsm[(ib + g) * 56 + j]     = make_float2(acc[nt][0] * scale, acc[nt][1] * scale);
        *(float2*)&gsm[(ib + g + 8) * 56 + j] = make_float2(acc[nt][2] * scale, acc[nt][3] * scale);
    }
    __syncthreads();

    if (tid < E_) {
        const int j = tid;
        float col[E_];
        float m = -1e30f;
#pragma unroll 10
        for (int i = 0; i < E_; i++) { col[i] = gsm[i * 56 + j]; m = fmaxf(m, col[i]); }
        float s = 0.f;
#pragma unroll 10
        for (int i = 0; i < E_; i++) { col[i] = expf(col[i] - m); s += col[i]; }
        const float inv = 1.f / s;
        float* wd = wts + (size_t)(b * C_ + nh) * E_ * E_;
#pragma unroll 10
        for (int i = 0; i < E_; i++) wd[i * E_ + j] = col[i] * inv - 0.02f;
    }
}

// ============================================================
// Kernel 4: ensemble mixing via bf16 mma per (b,nh,z):
//   T[j,hw] = V[j,hw] + sum_i w'[i,j] * V[i,hw];  T: [b][e][c][hw] bf16
// ============================================================
__global__ void __launch_bounds__(128) mixing_kernel(
    const bf16* __restrict__ v, const float* __restrict__ w,
    bf16* __restrict__ tout)
{
    extern __shared__ bf16 smx[];
    bf16* As = smx;            // [64 j][SB_] cols = i
    bf16* Vs = smx + 64 * SB_; // [64 hw][SB_] cols = i
    const int nh = blockIdx.x, b = blockIdx.y, z = blockIdx.z;
    const int tid = threadIdx.x, wid = tid >> 5, lane = tid & 31;
    const int g = lane >> 2, tg = lane & 3;
    const int ob = wid * 16;
    const int bc = b * C_ + nh;

    // zero A (all 64x64 used cols) and Vs pad cols i=48..63 (real i<50 rewritten per chunk)
    for (int idx = tid; idx < 64 * 64; idx += 128)
        As[(idx >> 6) * SB_ + (idx & 63)] = __float2bfloat16(0.f);
    for (int idx = tid; idx < 64 * 16; idx += 128) {
        const int hw = idx >> 4, i = 48 + (idx & 15);
        Vs[hw * SB_ + i] = __float2bfloat16(0.f);
    }
    __syncthreads();
    // A[j][i] = w'[i][j]
    const float* wsrc = w + (size_t)bc * E_ * E_;
    for (int idx = tid; idx < E_ * E_; idx += 128) {
        const int i = idx / E_, j = idx - i * E_;
        As[j * SB_ + i] = __float2bfloat16(wsrc[idx]);
    }

    const bf16* vb = v + (size_t)bc * E_ * HW_;

    for (int t = 0; t < 8; t++) {
        const int hw0 = z * 512 + t * 64;
        __syncthreads();
        for (int p = tid; p < E_ * 64; p += 128) {
            const int i = p >> 6, hw = p & 63;
            Vs[hw * SB_ + i] = vb[i * HW_ + hw0 + hw];
        }
        __syncthreads();

        float acc[8][4];
#pragma unroll
        for (int nt = 0; nt < 8; nt++)
#pragma unroll
            for (int r = 0; r < 4; r++) acc[nt][r] = 0.f;

#pragma unroll
        for (int ks = 0; ks < 4; ks++) {
            const int kc = 16 * ks + 2 * tg;
            const uint32 a0 = *(const uint32*)&As[(ob + g) * SB_ + kc];
            const uint32 a1 = *(const uint32*)&As[(ob + g + 8) * SB_ + kc];
            const uint32 a2 = *(const uint32*)&As[(ob + g) * SB_ + kc + 8];
            const uint32 a3 = *(const uint32*)&As[(ob + g + 8) * SB_ + kc + 8];
#pragma unroll
            for (int nt = 0; nt < 8; nt++) {
                const uint32 b0 = *(const uint32*)&Vs[(8 * nt + g) * SB_ + kc];
                const uint32 b1 = *(const uint32*)&Vs[(8 * nt + g) * SB_ + kc + 8];
                mma16(acc[nt], a0, a1, a2, a3, b0, b1);
            }
        }

        const int j0 = ob + g, j1 = ob + g + 8;
#pragma unroll
        for (int nt = 0; nt < 8; nt++) {
            const int hw = 8 * nt + 2 * tg;
            if (j0 < E_) {
                const float r0 = __bfloat162float(Vs[hw * SB_ + j0]);
                const float r1 = __bfloat162float(Vs[(hw + 1) * SB_ + j0]);
                *(bf162*)&tout[((size_t)(b * E_ + j0) * C_ + nh) * HW_ + hw0 + hw] =
                    __floats2bfloat162_rn(r0 + acc[nt][0], r1 + acc[nt][1]);
            }
            if (j1 < E_) {
                const float r0 = __bfloat162float(Vs[hw * SB_ + j1]);
                const float r1 = __bfloat162float(Vs[(hw + 1) * SB_ + j1]);
                *(bf162*)&tout[((size_t)(b * E_ + j1) * C_ + nh) * HW_ + hw0 + hw] =
                    __floats2bfloat162_rn(r0 + acc[nt][2], r1 + acc[nt][3]);
            }
        }
    }
}

// ============================================================
// Kernel 5: fused tail, 256 threads, 128-hw tile, bf16 mma:
//   after = x + Wo @ T; h1 = gelu(Wm1 @ after + b1); out = after + Wm2 @ h1 + b2
// ============================================================
__global__ void __launch_bounds__(256) tail_kernel(
    const bf16* __restrict__ T, const float* __restrict__ x,
    const float* __restrict__ Wo, const float* __restrict__ Wm1,
    const float* __restrict__ bm1, const float* __restrict__ Wm2,
    const float* __restrict__ bm2, float* __restrict__ out)
{
    extern __shared__ bf16 smt[];
    bf16* Ws = smt;                // [3][64][SB_]
    bf16* Ds = smt + 3 * 64 * SB_; // [128 hw][SB_]
    const int be = blockIdx.y, hw0 = blockIdx.x * 128, tid = threadIdx.x;
    const int wid = tid >> 5, lane = tid & 31;
    const int g = lane >> 2, tg = lane & 3;
    const int ob = (wid & 3) * 16;     // out-row tile
    const int nh0 = (wid >> 2) * 64;   // hw half

    for (int it = tid; it < 3072; it += 256) {
        const int m = it >> 10, rem = it & 1023, o = rem >> 4, c4 = (rem & 15) << 2;
        const float* Wp = (m == 0) ? Wo : ((m == 1) ? Wm1 : Wm2);
        const float4 w = *(const float4*)(Wp + o * 64 + c4);
        bf16* dst = Ws + m * 64 * SB_ + o * SB_ + c4;
        *(bf162*)(dst)     = __floats2bfloat162_rn(w.x, w.y);
        *(bf162*)(dst + 2) = __floats2bfloat162_rn(w.z, w.w);
    }

    // T tile (bf16 global, hw contiguous) -> Ds[hw][c]
    const bf16* tb = T + (size_t)be * SLAB_ + hw0;
    for (int p = tid; p < 64 * 64; p += 256) {
        const int c = p >> 6, hw2 = (p & 63) << 1;
        const bf162 v2 = *(const bf162*)&tb[c * HW_ + hw2];
        Ds[hw2 * SB_ + c]       = v2.x;
        Ds[(hw2 + 1) * SB_ + c] = v2.y;
    }
    __syncthreads();

    // GEMM1: acc1 = x + Wo @ T   (acc1 stays fp32)
    float acc1[8][4];
    const float* xb = x + (size_t)be * SLAB_ + hw0;
#pragma unroll
    for (int nt = 0; nt < 8; nt++) {
        const int hw = nh0 + 8 * nt + 2 * tg;
        const float2 r0 = *(const float2*)(xb + (size_t)(ob + g) * HW_ + hw);
        const float2 r1 = *(const float2*)(xb + (size_t)(ob + g + 8) * HW_ + hw);
        acc1[nt][0] = r0.x; acc1[nt][1] = r0.y; acc1[nt][2] = r1.x; acc1[nt][3] = r1.y;
    }
#pragma unroll
    for (int ks = 0; ks < 4; ks++) {
        const int kc = 16 * ks + 2 * tg;
        const uint32 a0 = *(const uint32*)&Ws[(ob + g) * SB_ + kc];
        const uint32 a1 = *(const uint32*)&Ws[(ob + g + 8) * SB_ + kc];
        const uint32 a2 = *(const uint32*)&Ws[(ob + g) * SB_ + kc + 8];
        const uint32 a3 = *(const uint32*)&Ws[(ob + g + 8) * SB_ + kc + 8];
#pragma unroll
        for (int nt = 0; nt < 8; nt++) {
            const uint32 b0 = *(const uint32*)&Ds[(nh0 + 8 * nt + g) * SB_ + kc];
            const uint32 b1 = *(const uint32*)&Ds[(nh0 + 8 * nt + g) * SB_ + kc + 8];
            mma16(acc1[nt], a0, a1, a2, a3, b0, b1);
        }
    }
    __syncthreads();

    // after -> Ds (bf16)
#pragma unroll
    for (int nt = 0; nt < 8; nt++) {
        const int hw = nh0 + 8 * nt + 2 * tg;
        Ds[hw * SB_ + ob + g]           = __float2bfloat16(acc1[nt][0]);
        Ds[(hw + 1) * SB_ + ob + g]     = __float2bfloat16(acc1[nt][1]);
        Ds[hw * SB_ + ob + g + 8]       = __float2bfloat16(acc1[nt][2]);
        Ds[(hw + 1) * SB_ + ob + g + 8] = __float2bfloat16(acc1[nt][3]);
    }
    __syncthreads();

    // GEMM2: h1 = gelu(Wm1 @ after + b1)
    float acc2[8][4];
    {
        const float bv0 = bm1[ob + g], bv1 = bm1[ob + g + 8];
#pragma unroll
        for (int nt = 0; nt < 8; nt++) {
            acc2[nt][0] = bv0; acc2[nt][1] = bv0; acc2[nt][2] = bv1; acc2[nt][3] = bv1;
        }
    }
#pragma unroll
    for (int ks = 0; ks < 4; ks++) {
        const int kc = 16 * ks + 2 * tg;
        const bf16* W = Ws + 64 * SB_;
        const uint32 a0 = *(const uint32*)&W[(ob + g) * SB_ + kc];
        const uint32 a1 = *(const uint32*)&W[(ob + g + 8) * SB_ + kc];
        const uint32 a2 = *(const uint32*)&W[(ob + g) * SB_ + kc + 8];
        const uint32 a3 = *(const uint32*)&W[(ob + g + 8) * SB_ + kc + 8];
#pragma unroll
        for (int nt = 0; nt < 8; nt++) {
            const uint32 b0 = *(const uint32*)&Ds[(nh0 + 8 * nt + g) * SB_ + kc];
            const uint32 b1 = *(const uint32*)&Ds[(nh0 + 8 * nt + g) * SB_ + kc + 8];
            mma16(acc2[nt], a0, a1, a2, a3, b0, b1);
        }
    }
#pragma unroll
    for (int nt = 0; nt < 8; nt++)
#pragma unroll
        for (int r = 0; r < 4; r++) {
            const float v = acc2[nt][r];
            acc2[nt][r] = 0.5f * v * (1.f + erff(v * 0.7071067811865475f));
        }
    __syncthreads();

    // h1 -> Ds (bf16)
#pragma unroll
    for (int nt = 0; nt < 8; nt++) {
        const int hw = nh0 + 8 * nt + 2 * tg;
        Ds[hw * SB_ + ob + g]           = __float2bfloat16(acc2[nt][0]);
        Ds[(hw + 1) * SB_ + ob + g]     = __float2bfloat16(acc2[nt][1]);
        Ds[hw * SB_ + ob + g + 8]       = __float2bfloat16(acc2[nt][2]);
        Ds[(hw + 1) * SB_ + ob + g + 8] = __float2bfloat16(acc2[nt][3]);
    }
    __syncthreads();

    // GEMM3 (reuse acc2): mix = Wm2 @ h1 + b2; out = acc1 + mix
    {
        const float bv0 = bm2[ob + g], bv1 = bm2[ob + g + 8];
#pragma unroll
        for (int nt = 0; nt < 8; nt++) {
            acc2[nt][0] = bv0; acc2[nt][1] = bv0; acc2[nt][2] = bv1; acc2[nt][3] = bv1;
        }
    }
#pragma unroll
    for (int ks = 0; ks < 4; ks++) {
        const int kc = 16 * ks + 2 * tg;
        const bf16* W = Ws + 2 * 64 * SB_;
        const uint32 a0 = *(const uint32*)&W[(ob + g) * SB_ + kc];
        const uint32 a1 = *(const uint32*)&W[(ob + g + 8) * SB_ + kc];
        const uint32 a2 = *(const uint32*)&W[(ob + g) * SB_ + kc + 8];
        const uint32 a3 = *(const uint32*)&W[(ob + g + 8) * SB_ + kc + 8];
#pragma unroll
        for (int nt = 0; nt < 8; nt++) {
            const uint32 b0 = *(const uint32*)&Ds[(nh0 + 8 * nt + g) * SB_ + kc];
            const uint32 b1 = *(const uint32*)&Ds[(nh0 + 8 * nt + g) * SB_ + kc + 8];
            mma16(acc2[nt], a0, a1, a2, a3, b0, b1);
        }
    }

    float* dst = out + (size_t)be * SLAB_ + hw0;
#pragma unroll
    for (int nt = 0; nt < 8; nt++) {
        const int hw = nh0 + 8 * nt + 2 * tg;
        *(float2*)(dst + (size_t)(ob + g) * HW_ + hw) =
            make_float2(acc1[nt][0] + acc2[nt][0], acc1[nt][1] + acc2[nt][1]);
        *(float2*)(dst + (size_t)(ob + g + 8) * HW_ + hw) =
            make_float2(acc1[nt][2] + acc2[nt][2], acc1[nt][3] + acc2[nt][3]);
    }
}

// ============================================================
// Launch
// ============================================================
extern "C" void kernel_launch(void* const* d_in, const int* in_sizes, int n_in,
                              void* d_out, int out_size)
{
    const float* x    = (const float*)d_in[0];
    const float* lng  = (const float*)d_in[1];
    const float* lnb  = (const float*)d_in[2];
    const float* W_v  = (const float*)d_in[3];
    const float* W_k  = (const float*)d_in[4];
    const float* W_q  = (const float*)d_in[5];
    const float* W_o  = (const float*)d_in[6];
    const float* W_m1 = (const float*)d_in[7];
    const float* b_m1 = (const float*)d_in[8];
    const float* W_m2 = (const float*)d_in[9];
    const float* b_m2 = (const float*)d_in[10];
    float* out = (float*)d_out;

    bf16 *pv, *pk, *pq, *pt;
    float *pw;
    cudaGetSymbolAddress((void**)&pv, g_v);
    cudaGetSymbolAddress((void**)&pk, g_k);
    cudaGetSymbolAddress((void**)&pq, g_q);
    cudaGetSymbolAddress((void**)&pt, g_t);
    cudaGetSymbolAddress((void**)&pw, g_wts);

    const int smem_vkq  = (3 * 64 * SB_ + 64 * SB_) * 2;   // 36864
    const int smem_gram = (2 * 64 * SB_) * 2;              // 18432
    const int smem_mix  = (2 * 64 * SB_) * 2;              // 18432
    const int smem_tail = (3 * 64 * SB_ + 128 * SB_) * 2;  // 46080
    cudaFuncSetAttribute(vkq_kernel,    cudaFuncAttributeMaxDynamicSharedMemorySize, smem_vkq);
    cudaFuncSetAttribute(gram_kernel,   cudaFuncAttributeMaxDynamicSharedMemorySize, smem_gram);
    cudaFuncSetAttribute(mixing_kernel, cudaFuncAttributeMaxDynamicSharedMemorySize, smem_mix);
    cudaFuncSetAttribute(tail_kernel,   cudaFuncAttributeMaxDynamicSharedMemorySize, smem_tail);

    ln_stats_kernel<<<BE_, 256>>>(x);

    vkq_kernel<<<dim3(HW_ / 64, BE_), 128, smem_vkq>>>(x, W_v, W_k, W_q, lng, lnb, pv, pk, pq);

    gram_kernel<<<dim3(C_, B_), 128, smem_gram>>>(pk, pq, pw);

    mixing_kernel<<<dim3(C_, B_, 4), 128, smem_mix>>>(pv, pw, pt);

    tail_kernel<<<dim3(HW_ / 128, BE_), 256, smem_tail>>>(pt, x, W_o, W_m1, b_m1, W_m2, b_m2, out);
}

// round 6
// speedup vs baseline: 2.8253x; 1.1376x over previous
#include <cuda_runtime.h>
#include <cuda_bf16.h>
#include <math.h>

#define B_    4
#define E_    50
#define C_    64
#define HW_   2048
#define BE_   200
#define SLAB_ 131072      // C_*HW_
#define NTOT_ 26214400    // BE_*SLAB_
#define SB_   72          // bf16 smem row stride (9r mod 8 distinct -> LDSM conflict-free)
#define SD_   136         // tail 128-col stride (17r mod 8 distinct)

typedef unsigned int uint32;
typedef __nv_bfloat16 bf16;
typedef __nv_bfloat162 bf162;

// ---- scratch (static device globals; no allocation) ----
__device__ bf16 g_v[NTOT_];   // [b][c][e][hw]
__device__ bf16 g_k[NTOT_];   // [b][c][e][hw]
__device__ bf16 g_q[NTOT_];   // [b][c][e][hw]
__device__ bf16 g_t[NTOT_];   // [b][e][c][hw]
__device__ float g_wts[B_ * C_ * E_ * E_];  // w' = softmax - 1/E
__device__ float g_mu[BE_];
__device__ float g_rs[BE_];

// m16n8k16 bf16 mma, fp32 accumulate
__device__ __forceinline__ void mma16(float d[4], uint32 a0, uint32 a1, uint32 a2, uint32 a3,
                                      uint32 b0, uint32 b1) {
    asm volatile(
        "mma.sync.aligned.m16n8k16.row.col.f32.bf16.bf16.f32 "
        "{%0,%1,%2,%3}, {%4,%5,%6,%7}, {%8,%9}, {%0,%1,%2,%3};"
        : "+f"(d[0]), "+f"(d[1]), "+f"(d[2]), "+f"(d[3])
        : "r"(a0), "r"(a1), "r"(a2), "r"(a3), "r"(b0), "r"(b1));
}

__device__ __forceinline__ uint32 cvta_smem(const void* p) {
    return (uint32)__cvta_generic_to_shared(p);
}
__device__ __forceinline__ void ldsm4(uint32& r0, uint32& r1, uint32& r2, uint32& r3, uint32 a) {
    asm volatile("ldmatrix.sync.aligned.m8n8.x4.shared.b16 {%0,%1,%2,%3}, [%4];"
                 : "=r"(r0), "=r"(r1), "=r"(r2), "=r"(r3) : "r"(a));
}
__device__ __forceinline__ void ldsm2(uint32& r0, uint32& r1, uint32 a) {
    asm volatile("ldmatrix.sync.aligned.m8n8.x2.shared.b16 {%0,%1}, [%2];"
                 : "=r"(r0), "=r"(r1) : "r"(a));
}
__device__ __forceinline__ void ldsm2t(uint32& r0, uint32& r1, uint32 a) {
    asm volatile("ldmatrix.sync.aligned.m8n8.x2.trans.shared.b16 {%0,%1}, [%2];"
                 : "=r"(r0), "=r"(r1) : "r"(a));
}

// ============================================================
// Kernel 1: LayerNorm statistics per (b,e) slab
// ============================================================
__global__ void ln_stats_kernel(const float* __restrict__ x) {
    const int be = blockIdx.x;
    const float4* p = (const float4*)(x + (size_t)be * SLAB_);
    float s = 0.f, s2 = 0.f;
    for (int i = threadIdx.x; i < SLAB_ / 4; i += blockDim.x) {
        float4 v = p[i];
        s  += v.x + v.y + v.z + v.w;
        s2 += v.x * v.x + v.y * v.y + v.z * v.z + v.w * v.w;
    }
    for (int o = 16; o; o >>= 1) {
        s  += __shfl_down_sync(0xffffffffu, s,  o);
        s2 += __shfl_down_sync(0xffffffffu, s2, o);
    }
    __shared__ float shs[8], shq[8];
    const int w = threadIdx.x >> 5, l = threadIdx.x & 31;
    if (l == 0) { shs[w] = s; shq[w] = s2; }
    __syncthreads();
    if (threadIdx.x == 0) {
        float S = 0.f, Q = 0.f;
        const int nw = blockDim.x >> 5;
        for (int i = 0; i < nw; i++) { S += shs[i]; Q += shq[i]; }
        const float mu  = S * (1.f / (float)SLAB_);
        const float var = Q * (1.f / (float)SLAB_) - mu * mu;
        g_mu[be] = mu;
        g_rs[be] = rsqrtf(var + 1e-5f);
    }
}

// ============================================================
// Kernel 2: fused LN + v/k/q conv via bf16 mma + LDSM.
// Xs natural [c][hw]; B frags via ldmatrix.trans.
// ============================================================
__global__ void __launch_bounds__(128) vkq_kernel(
    const float* __restrict__ x,
    const float* __restrict__ Wv, const float* __restrict__ Wk, const float* __restrict__ Wq,
    const float* __restrict__ lng, const float* __restrict__ lnb,
    bf16* __restrict__ ov, bf16* __restrict__ ok, bf16* __restrict__ oq)
{
    extern __shared__ bf16 smb[];
    bf16* Ws = smb;                // [3][64 o][SB_]  (rows o, cols c)
    bf16* Xs = smb + 3 * 64 * SB_; // [64 c][SB_]     (rows c, cols hw)
    const int be = blockIdx.y, hw0 = blockIdx.x * 64, tid = threadIdx.x;
    const int wid = tid >> 5, lane = tid & 31;
    const int g = lane >> 2, tg = lane & 3;
    const int ob = wid * 16;

    for (int it = tid; it < 3072; it += 128) {
        const int m = it >> 10, rem = it & 1023, o = rem >> 4, c4 = (rem & 15) << 2;
        const float* Wp = (m == 0) ? Wv : ((m == 1) ? Wk : Wq);
        const float4 w = *(const float4*)(Wp + o * 64 + c4);
        bf16* dst = Ws + m * 64 * SB_ + o * SB_ + c4;
        *(bf162*)(dst)     = __floats2bfloat162_rn(w.x, w.y);
        *(bf162*)(dst + 2) = __floats2bfloat162_rn(w.z, w.w);
    }

    // x tile: LN -> Xs[c][hw] natural, bf162-packed stores
    const float mu = g_mu[be], rs = g_rs[be];
    const float* xb = x + (size_t)be * SLAB_ + hw0;
    for (int rep = 0; rep < 16; rep++) {
        const int c = wid * 16 + rep;
        const float2 xv = *(const float2*)(xb + c * HW_ + 2 * lane);
        const float2 gg = *(const float2*)(lng + c * HW_ + hw0 + 2 * lane);
        const float2 bb = *(const float2*)(lnb + c * HW_ + hw0 + 2 * lane);
        const float v0 = (xv.x - mu) * rs * gg.x + bb.x;
        const float v1 = (xv.y - mu) * rs * gg.y + bb.y;
        *(bf162*)&Xs[c * SB_ + 2 * lane] = __floats2bfloat162_rn(v0, v1);
    }
    __syncthreads();

    const uint32 xs0 = cvta_smem(Xs);
    const uint32 ws0 = cvta_smem(Ws);
    const int rowA = ob + (lane & 15);
    const int colA = (lane >> 4) << 3;
    const int rowB = lane & 15;

    float acc[3][8][4];
#pragma unroll
    for (int m = 0; m < 3; m++)
#pragma unroll
        for (int nt = 0; nt < 8; nt++)
#pragma unroll
            for (int r = 0; r < 4; r++) acc[m][nt][r] = 0.f;

#pragma unroll
    for (int ks = 0; ks < 4; ks++) {
        const int kc = 16 * ks;
        uint32 b0[8], b1[8];
#pragma unroll
        for (int nt = 0; nt < 8; nt++)
            ldsm2t(b0[nt], b1[nt], xs0 + (((kc + rowB) * SB_ + 8 * nt) << 1));
#pragma unroll
        for (int m = 0; m < 3; m++) {
            uint32 a0, a1, a2, a3;
            ldsm4(a0, a1, a2, a3, ws0 + ((m * 64 * SB_ + rowA * SB_ + kc + colA) << 1));
#pragma unroll
            for (int nt = 0; nt < 8; nt++) mma16(acc[m][nt], a0, a1, a2, a3, b0[nt], b1[nt]);
        }
    }

    const int bb = be / E_, ee = be % E_;
    bf16* outs[3] = {ov, ok, oq};
#pragma unroll
    for (int m = 0; m < 3; m++) {
        bf16* dst = outs[m];
#pragma unroll
        for (int nt = 0; nt < 8; nt++) {
            const int hw = hw0 + 8 * nt + 2 * tg;
            const int o0 = ob + g, o1 = ob + g + 8;
            *(bf162*)&dst[((size_t)(bb * C_ + o0) * E_ + ee) * HW_ + hw] =
                __floats2bfloat162_rn(acc[m][nt][0], acc[m][nt][1]);
            *(bf162*)&dst[((size_t)(bb * C_ + o1) * E_ + ee) * HW_ + hw] =
                __floats2bfloat162_rn(acc[m][nt][2], acc[m][nt][3]);
        }
    }
}

// ============================================================
// Kernel 3: gram via bf16 mma + LDSM + in-block softmax. grid (64, 4).
// ============================================================
__global__ void __launch_bounds__(128) gram_kernel(
    const bf16* __restrict__ k, const bf16* __restrict__ q,
    float* __restrict__ wts)
{
    extern __shared__ bf16 smg[];
    bf16* Ks = smg;            // [64 i][SB_] (rows i, cols hw-chunk)
    bf16* Qs = smg + 64 * SB_;
    const int nh = blockIdx.x, b = blockIdx.y, tid = threadIdx.x;
    const int wid = tid >> 5, lane = tid & 31;
    const int g = lane >> 2, tg = lane & 3;
    const int ib = wid * 16;
    const bf16* kb = k + (size_t)(b * C_ + nh) * E_ * HW_;
    const bf16* qb = q + (size_t)(b * C_ + nh) * E_ * HW_;

    // zero pad rows e = 50..63
    for (int idx = tid; idx < 14 * 64; idx += 128) {
        const int e = 50 + (idx >> 6), c = idx & 63;
        Ks[e * SB_ + c] = __float2bfloat16(0.f);
        Qs[e * SB_ + c] = __float2bfloat16(0.f);
    }

    const uint32 ks0 = cvta_smem(Ks);
    const uint32 qs0 = cvta_smem(Qs);
    const int rowA = ib + (lane & 15);
    const int colA = (lane >> 4) << 3;
    const int rowBb = lane & 7;
    const int colB = lane & 8;

    float acc[7][4];
#pragma unroll
    for (int nt = 0; nt < 7; nt++)
#pragma unroll
        for (int r = 0; r < 4; r++) acc[nt][r] = 0.f;

    for (int ch = 0; ch < 32; ch++) {
        const int hwb = ch * 64;
        __syncthreads();
        for (int it = tid; it < 800; it += 128) {
            const int arr = it / 400, rem = it % 400, e = rem >> 3, h8 = (rem & 7) << 3;
            const bf16* src = arr ? qb : kb;
            const uint4 v = *(const uint4*)&src[e * HW_ + hwb + h8];
            *(uint4*)&((arr ? Qs : Ks)[e * SB_ + h8]) = v;
        }
        __syncthreads();

#pragma unroll
        for (int ks = 0; ks < 4; ks++) {
            const int kc = 16 * ks;
            uint32 a0, a1, a2, a3;
            ldsm4(a0, a1, a2, a3, ks0 + ((rowA * SB_ + kc + colA) << 1));
#pragma unroll
            for (int nt = 0; nt < 7; nt++) {
                uint32 b0, b1;
                ldsm2(b0, b1, qs0 + (((8 * nt + rowBb) * SB_ + kc + colB) << 1));
                mma16(acc[nt], a0, a1, a2, a3, b0, b1);
            }
        }
    }

    __syncthreads();
    float* gsm = (float*)smg;
    const float scale = 0.02209708691207961f;   // 1/sqrt(2048)
#pragma unroll
    for (int nt = 0; nt < 7; nt++) {
        const int j = 8 * nt + 2 * tg;
        *(float2*)&gsm[(ib + g) * 56 + j]     = make_float2(acc[nt][0] * scale, acc[nt][1] * scale);
        *(float2*)&gsm[(ib + g + 8) * 56 + j] = make_float2(acc[nt][2] * scale, acc[nt][3] * scale);
    }
    __syncthreads();

    if (tid < E_) {
        const int j = tid;
        float col[E_];
        float m = -1e30f;
#pragma unroll 10
        for (int i = 0; i < E_; i++) { col[i] = gsm[i * 56 + j]; m = fmaxf(m, col[i]); }
        float s = 0.f;
#pragma unroll 10
        for (int i = 0; i < E_; i++) { col[i] = expf(col[i] - m); s += col[i]; }
        const float inv = 1.f / s;
        float* wd = wts + (size_t)(b * C_ + nh) * E_ * E_;
#pragma unroll 10
        for (int i = 0; i < E_; i++) wd[i * E_ + j] = col[i] * inv - 0.02f;
    }
}

// ============================================================
// Kernel 4: ensemble mixing, M = I + w' folded:  T = M @ V
// A = M [j][i] rows; B = V natural [i][hw] rows + ldmatrix.trans.
// ============================================================
__global__ void __launch_bounds__(128) mixing_kernel(
    const bf16* __restrict__ v, const float* __restrict__ w,
    bf16* __restrict__ tout)
{
    extern __shared__ bf16 smx[];
    bf16* Ms = smx;            // [64 j][SB_] cols i
    bf16* Vs = smx + 64 * SB_; // [64 i][SB_] cols hw
    const int nh = blockIdx.x, b = blockIdx.y, z = blockIdx.z;
    const int tid = threadIdx.x, wid = tid >> 5, lane = tid & 31;
    const int g = lane >> 2, tg = lane & 3;
    const int ob = wid * 16;
    const int bc = b * C_ + nh;

    // zero M fully; zero Vs pad rows i=50..63 once
    for (int idx = tid; idx < 64 * 8; idx += 128)
        *(uint4*)&Ms[(idx >> 3) * SB_ + ((idx & 7) << 3)] = make_uint4(0u, 0u, 0u, 0u);
    for (int idx = tid; idx < 14 * 8; idx += 128)
        *(uint4*)&Vs[(50 + (idx >> 3)) * SB_ + ((idx & 7) << 3)] = make_uint4(0u, 0u, 0u, 0u);
    __syncthreads();
    // M[j][i] = w'[i][j] + (i==j)
    const float* wsrc = w + (size_t)bc * E_ * E_;
    for (int idx = tid; idx < E_ * E_; idx += 128) {
        const int i = idx / E_, j = idx - i * E_;
        const float val = wsrc[idx] + ((i == j) ? 1.f : 0.f);
        Ms[j * SB_ + i] = __float2bfloat16(val);
    }

    const bf16* vb = v + (size_t)bc * E_ * HW_;
    const uint32 ms0 = cvta_smem(Ms);
    const uint32 vs0 = cvta_smem(Vs);
    const int rowA = ob + (lane & 15);
    const int colA = (lane >> 4) << 3;
    const int rowB = lane & 15;

    for (int t = 0; t < 8; t++) {
        const int hw0 = z * 512 + t * 64;
        __syncthreads();
        for (int p = tid; p < E_ * 8; p += 128) {
            const int i = p >> 3, h8 = (p & 7) << 3;
            *(uint4*)&Vs[i * SB_ + h8] = *(const uint4*)&vb[i * HW_ + hw0 + h8];
        }
        __syncthreads();

        float acc[8][4];
#pragma unroll
        for (int nt = 0; nt < 8; nt++)
#pragma unroll
            for (int r = 0; r < 4; r++) acc[nt][r] = 0.f;

#pragma unroll
        for (int ks = 0; ks < 4; ks++) {
            const int kc = 16 * ks;
            uint32 a0, a1, a2, a3;
            ldsm4(a0, a1, a2, a3, ms0 + ((rowA * SB_ + kc + colA) << 1));
#pragma unroll
            for (int nt = 0; nt < 8; nt++) {
                uint32 b0, b1;
                ldsm2t(b0, b1, vs0 + (((kc + rowB) * SB_ + 8 * nt) << 1));
                mma16(acc[nt], a0, a1, a2, a3, b0, b1);
            }
        }

        const int j0 = ob + g, j1 = ob + g + 8;
#pragma unroll
        for (int nt = 0; nt < 8; nt++) {
            const int hw = 8 * nt + 2 * tg;
            if (j0 < E_)
                *(bf162*)&tout[((size_t)(b * E_ + j0) * C_ + nh) * HW_ + hw0 + hw] =
                    __floats2bfloat162_rn(acc[nt][0], acc[nt][1]);
            if (j1 < E_)
                *(bf162*)&tout[((size_t)(b * E_ + j1) * C_ + nh) * HW_ + hw0 + hw] =
                    __floats2bfloat162_rn(acc[nt][2], acc[nt][3]);
        }
    }
}

// ============================================================
// Kernel 5: fused tail (256 thr, 128-hw tile), natural layouts + LDSM:
//   after = x + Wo @ T; h1 = gelu(Wm1 @ after + b1); out = after + Wm2 @ h1 + b2
// ============================================================
__global__ void __launch_bounds__(256) tail_kernel(
    const bf16* __restrict__ T, const float* __restrict__ x,
    const float* __restrict__ Wo, const float* __restrict__ Wm1,
    const float* __restrict__ bm1, const float* __restrict__ Wm2,
    const float* __restrict__ bm2, float* __restrict__ out)
{
    extern __shared__ bf16 smt[];
    bf16* Ws = smt;                // [3][64 o][SB_]
    bf16* Ds = smt + 3 * 64 * SB_; // [64 c][SD_] cols hw(128)
    const int be = blockIdx.y, hw0 = blockIdx.x * 128, tid = threadIdx.x;
    const int wid = tid >> 5, lane = tid & 31;
    const int g = lane >> 2, tg = lane & 3;
    const int ob = (wid & 3) * 16;     // out-row tile
    const int nh0 = (wid >> 2) * 64;   // hw half

    for (int it = tid; it < 3072; it += 256) {
        const int m = it >> 10, rem = it & 1023, o = rem >> 4, c4 = (rem & 15) << 2;
        const float* Wp = (m == 0) ? Wo : ((m == 1) ? Wm1 : Wm2);
        const float4 w = *(const float4*)(Wp + o * 64 + c4);
        bf16* dst = Ws + m * 64 * SB_ + o * SB_ + c4;
        *(bf162*)(dst)     = __floats2bfloat162_rn(w.x, w.y);
        *(bf162*)(dst + 2) = __floats2bfloat162_rn(w.z, w.w);
    }

    // T tile -> Ds[c][hw] natural (uint4)
    const bf16* tb = T + (size_t)be * SLAB_ + hw0;
    for (int p = tid; p < 64 * 16; p += 256) {
        const int c = p >> 4, h8 = (p & 15) << 3;
        *(uint4*)&Ds[c * SD_ + h8] = *(const uint4*)&tb[c * HW_ + h8];
    }
    __syncthreads();

    const uint32 ws0 = cvta_smem(Ws);
    const uint32 ds0 = cvta_smem(Ds);
    const int rowA = ob + (lane & 15);
    const int colA = (lane >> 4) << 3;
    const int rowB = lane & 15;

    // GEMM1: acc1 = x + Wo @ T
    float acc1[8][4];
    const float* xb = x + (size_t)be * SLAB_ + hw0;
#pragma unroll
    for (int nt = 0; nt < 8; nt++) {
        const int hw = nh0 + 8 * nt + 2 * tg;
        const float2 r0 = *(const float2*)(xb + (size_t)(ob + g) * HW_ + hw);
        const float2 r1 = *(const float2*)(xb + (size_t)(ob + g + 8) * HW_ + hw);
        acc1[nt][0] = r0.x; acc1[nt][1] = r0.y; acc1[nt][2] = r1.x; acc1[nt][3] = r1.y;
    }
#pragma unroll
    for (int ks = 0; ks < 4; ks++) {
        const int kc = 16 * ks;
        uint32 a0, a1, a2, a3;
        ldsm4(a0, a1, a2, a3, ws0 + ((rowA * SB_ + kc + colA) << 1));
#pragma unroll
        for (int nt = 0; nt < 8; nt++) {
            uint32 b0, b1;
            ldsm2t(b0, b1, ds0 + (((kc + rowB) * SD_ + nh0 + 8 * nt) << 1));
            mma16(acc1[nt], a0, a1, a2, a3, b0, b1);
        }
    }
    __syncthreads();

    // after -> Ds[o][hw] (bf162 pairs)
#pragma unroll
    for (int nt = 0; nt < 8; nt++) {
        const int hw = nh0 + 8 * nt + 2 * tg;
        *(bf162*)&Ds[(ob + g) * SD_ + hw]     = __floats2bfloat162_rn(acc1[nt][0], acc1[nt][1]);
        *(bf162*)&Ds[(ob + g + 8) * SD_ + hw] = __floats2bfloat162_rn(acc1[nt][2], acc1[nt][3]);
    }
    __syncthreads();

    // GEMM2: h1 = gelu(Wm1 @ after + b1)
    float acc2[8][4];
    {
        const float bv0 = bm1[ob + g], bv1 = bm1[ob + g + 8];
#pragma unroll
        for (int nt = 0; nt < 8; nt++) {
            acc2[nt][0] = bv0; acc2[nt][1] = bv0; acc2[nt][2] = bv1; acc2[nt][3] = bv1;
        }
    }
#pragma unroll
    for (int ks = 0; ks < 4; ks++) {
        const int kc = 16 * ks;
        uint32 a0, a1, a2, a3;
        ldsm4(a0, a1, a2, a3, ws0 + ((64 * SB_ + rowA * SB_ + kc + colA) << 1));
#pragma unroll
        for (int nt = 0; nt < 8; nt++) {
            uint32 b0, b1;
            ldsm2t(b0, b1, ds0 + (((kc + rowB) * SD_ + nh0 + 8 * nt) << 1));
            mma16(acc2[nt], a0, a1, a2, a3, b0, b1);
        }
    }
#pragma unroll
    for (int nt = 0; nt < 8; nt++)
#pragma unroll
        for (int r = 0; r < 4; r++) {
            const float v = acc2[nt][r];
            acc2[nt][r] = 0.5f * v * (1.f + erff(v * 0.7071067811865475f));
        }
    __syncthreads();

    // h1 -> Ds
#pragma unroll
    for (int nt = 0; nt < 8; nt++) {
        const int hw = nh0 + 8 * nt + 2 * tg;
        *(bf162*)&Ds[(ob + g) * SD_ + hw]     = __floats2bfloat162_rn(acc2[nt][0], acc2[nt][1]);
        *(bf162*)&Ds[(ob + g + 8) * SD_ + hw] = __floats2bfloat162_rn(acc2[nt][2], acc2[nt][3]);
    }
    __syncthreads();

    // GEMM3 (reuse acc2): out = acc1 + Wm2 @ h1 + b2
    {
        const float bv0 = bm2[ob + g], bv1 = bm2[ob + g + 8];
#pragma unroll
        for (int nt = 0; nt < 8; nt++) {
            acc2[nt][0] = bv0; acc2[nt][1] = bv0; acc2[nt][2] = bv1; acc2[nt][3] = bv1;
        }
    }
#pragma unroll
    for (int ks = 0; ks < 4; ks++) {
        const int kc = 16 * ks;
        uint32 a0, a1, a2, a3;
        ldsm4(a0, a1, a2, a3, ws0 + ((2 * 64 * SB_ + rowA * SB_ + kc + colA) << 1));
#pragma unroll
        for (int nt = 0; nt < 8; nt++) {
            uint32 b0, b1;
            ldsm2t(b0, b1, ds0 + (((kc + rowB) * SD_ + nh0 + 8 * nt) << 1));
            mma16(acc2[nt], a0, a1, a2, a3, b0, b1);
        }
    }

    float* dst = out + (size_t)be * SLAB_ + hw0;
#pragma unroll
    for (int nt = 0; nt < 8; nt++) {
        const int hw = nh0 + 8 * nt + 2 * tg;
        *(float2*)(dst + (size_t)(ob + g) * HW_ + hw) =
            make_float2(acc1[nt][0] + acc2[nt][0], acc1[nt][1] + acc2[nt][1]);
        *(float2*)(dst + (size_t)(ob + g + 8) * HW_ + hw) =
            make_float2(acc1[nt][2] + acc2[nt][2], acc1[nt][3] + acc2[nt][3]);
    }
}

// ============================================================
// Launch
// ============================================================
extern "C" void kernel_launch(void* const* d_in, const int* in_sizes, int n_in,
                              void* d_out, int out_size)
{
    const float* x    = (const float*)d_in[0];
    const float* lng  = (const float*)d_in[1];
    const float* lnb  = (const float*)d_in[2];
    const float* W_v  = (const float*)d_in[3];
    const float* W_k  = (const float*)d_in[4];
    const float* W_q  = (const float*)d_in[5];
    const float* W_o  = (const float*)d_in[6];
    const float* W_m1 = (const float*)d_in[7];
    const float* b_m1 = (const float*)d_in[8];
    const float* W_m2 = (const float*)d_in[9];
    const float* b_m2 = (const float*)d_in[10];
    float* out = (float*)d_out;

    bf16 *pv, *pk, *pq, *pt;
    float *pw;
    cudaGetSymbolAddress((void**)&pv, g_v);
    cudaGetSymbolAddress((void**)&pk, g_k);
    cudaGetSymbolAddress((void**)&pq, g_q);
    cudaGetSymbolAddress((void**)&pt, g_t);
    cudaGetSymbolAddress((void**)&pw, g_wts);

    const int smem_vkq  = (3 * 64 * SB_ + 64 * SB_) * 2;   // 36864
    const int smem_gram = (2 * 64 * SB_) * 2;              // 18432
    const int smem_mix  = (2 * 64 * SB_) * 2;              // 18432
    const int smem_tail = (3 * 64 * SB_ + 64 * SD_) * 2;   // 45056
    cudaFuncSetAttribute(vkq_kernel,    cudaFuncAttributeMaxDynamicSharedMemorySize, smem_vkq);
    cudaFuncSetAttribute(gram_kernel,   cudaFuncAttributeMaxDynamicSharedMemorySize, smem_gram);
    cudaFuncSetAttribute(mixing_kernel, cudaFuncAttributeMaxDynamicSharedMemorySize, smem_mix);
    cudaFuncSetAttribute(tail_kernel,   cudaFuncAttributeMaxDynamicSharedMemorySize, smem_tail);

    ln_stats_kernel<<<BE_, 256>>>(x);

    vkq_kernel<<<dim3(HW_ / 64, BE_), 128, smem_vkq>>>(x, W_v, W_k, W_q, lng, lnb, pv, pk, pq);

    gram_kernel<<<dim3(C_, B_), 128, smem_gram>>>(pk, pq, pw);

    mixing_kernel<<<dim3(C_, B_, 4), 128, smem_mix>>>(pv, pw, pt);

    tail_kernel<<<dim3(HW_ / 128, BE_), 256, smem_tail>>>(pt, x, W_o, W_m1, b_m1, W_m2, b_m2, out);
}

// round 7
// speedup vs baseline: 3.2408x; 1.1470x over previous
#include <cuda_runtime.h>
#include <cuda_bf16.h>
#include <math.h>

#define B_    4
#define E_    50
#define C_    64
#define HW_   2048
#define BE_   200
#define SLAB_ 131072      // C_*HW_
#define NTOT_ 26214400    // BE_*SLAB_
#define SB_   72          // bf16 smem row stride, 64 cols (9r mod 8 distinct -> LDSM conflict-free)
#define SD_   136         // bf16 smem row stride, 128 cols (17r mod 8 distinct)

typedef unsigned int uint32;
typedef __nv_bfloat16 bf16;
typedef __nv_bfloat162 bf162;

// ---- scratch (static device globals; no allocation) ----
__device__ bf16 g_v[NTOT_];   // [b][c][e][hw]
__device__ bf16 g_k[NTOT_];   // [b][c][e][hw]
__device__ bf16 g_q[NTOT_];   // [b][c][e][hw]
__device__ bf16 g_t[NTOT_];   // [b][e][c][hw]
__device__ float g_wts[B_ * C_ * E_ * E_];  // w' = softmax - 1/E
__device__ float g_mu[BE_];
__device__ float g_rs[BE_];

// m16n8k16 bf16 mma, fp32 accumulate
__device__ __forceinline__ void mma16(float d[4], uint32 a0, uint32 a1, uint32 a2, uint32 a3,
                                      uint32 b0, uint32 b1) {
    asm volatile(
        "mma.sync.aligned.m16n8k16.row.col.f32.bf16.bf16.f32 "
        "{%0,%1,%2,%3}, {%4,%5,%6,%7}, {%8,%9}, {%0,%1,%2,%3};"
        : "+f"(d[0]), "+f"(d[1]), "+f"(d[2]), "+f"(d[3])
        : "r"(a0), "r"(a1), "r"(a2), "r"(a3), "r"(b0), "r"(b1));
}

__device__ __forceinline__ uint32 cvta_smem(const void* p) {
    return (uint32)__cvta_generic_to_shared(p);
}
__device__ __forceinline__ void ldsm4(uint32& r0, uint32& r1, uint32& r2, uint32& r3, uint32 a) {
    asm volatile("ldmatrix.sync.aligned.m8n8.x4.shared.b16 {%0,%1,%2,%3}, [%4];"
                 : "=r"(r0), "=r"(r1), "=r"(r2), "=r"(r3) : "r"(a));
}
__device__ __forceinline__ void ldsm2(uint32& r0, uint32& r1, uint32 a) {
    asm volatile("ldmatrix.sync.aligned.m8n8.x2.shared.b16 {%0,%1}, [%2];"
                 : "=r"(r0), "=r"(r1) : "r"(a));
}
__device__ __forceinline__ void ldsm2t(uint32& r0, uint32& r1, uint32 a) {
    asm volatile("ldmatrix.sync.aligned.m8n8.x2.trans.shared.b16 {%0,%1}, [%2];"
                 : "=r"(r0), "=r"(r1) : "r"(a));
}
__device__ __forceinline__ void cp16(uint32 dst, const void* src) {
    asm volatile("cp.async.cg.shared.global [%0], [%1], 16;" :: "r"(dst), "l"(src));
}
__device__ __forceinline__ void cp_commit() { asm volatile("cp.async.commit_group;"); }
__device__ __forceinline__ void cp_wait1() { asm volatile("cp.async.wait_group 1;"); }
__device__ __forceinline__ void cp_wait0() { asm volatile("cp.async.wait_group 0;"); }

// ============================================================
// Kernel 1: LayerNorm statistics per (b,e) slab (512 threads)
// ============================================================
__global__ void __launch_bounds__(512) ln_stats_kernel(const float* __restrict__ x) {
    const int be = blockIdx.x;
    const float4* p = (const float4*)(x + (size_t)be * SLAB_);
    float s = 0.f, s2 = 0.f;
    for (int i = threadIdx.x; i < SLAB_ / 4; i += 512) {
        float4 v = p[i];
        s  += v.x + v.y + v.z + v.w;
        s2 += v.x * v.x + v.y * v.y + v.z * v.z + v.w * v.w;
    }
    for (int o = 16; o; o >>= 1) {
        s  += __shfl_down_sync(0xffffffffu, s,  o);
        s2 += __shfl_down_sync(0xffffffffu, s2, o);
    }
    __shared__ float shs[16], shq[16];
    const int w = threadIdx.x >> 5, l = threadIdx.x & 31;
    if (l == 0) { shs[w] = s; shq[w] = s2; }
    __syncthreads();
    if (threadIdx.x == 0) {
        float S = 0.f, Q = 0.f;
        for (int i = 0; i < 16; i++) { S += shs[i]; Q += shq[i]; }
        const float mu  = S * (1.f / (float)SLAB_);
        const float var = Q * (1.f / (float)SLAB_) - mu * mu;
        g_mu[be] = mu;
        g_rs[be] = rsqrtf(var + 1e-5f);
    }
}

// ============================================================
// Kernel 2: fused LN + v/k/q conv via bf16 mma + LDSM (proven).
// ============================================================
__global__ void __launch_bounds__(128) vkq_kernel(
    const float* __restrict__ x,
    const float* __restrict__ Wv, const float* __restrict__ Wk, const float* __restrict__ Wq,
    const float* __restrict__ lng, const float* __restrict__ lnb,
    bf16* __restrict__ ov, bf16* __restrict__ ok, bf16* __restrict__ oq)
{
    extern __shared__ bf16 smb[];
    bf16* Ws = smb;                // [3][64 o][SB_]
    bf16* Xs = smb + 3 * 64 * SB_; // [64 c][SB_]
    const int be = blockIdx.y, hw0 = blockIdx.x * 64, tid = threadIdx.x;
    const int wid = tid >> 5, lane = tid & 31;
    const int g = lane >> 2, tg = lane & 3;
    const int ob = wid * 16;

    for (int it = tid; it < 3072; it += 128) {
        const int m = it >> 10, rem = it & 1023, o = rem >> 4, c4 = (rem & 15) << 2;
        const float* Wp = (m == 0) ? Wv : ((m == 1) ? Wk : Wq);
        const float4 w = *(const float4*)(Wp + o * 64 + c4);
        bf16* dst = Ws + m * 64 * SB_ + o * SB_ + c4;
        *(bf162*)(dst)     = __floats2bfloat162_rn(w.x, w.y);
        *(bf162*)(dst + 2) = __floats2bfloat162_rn(w.z, w.w);
    }

    const float mu = g_mu[be], rs = g_rs[be];
    const float* xb = x + (size_t)be * SLAB_ + hw0;
    for (int rep = 0; rep < 16; rep++) {
        const int c = wid * 16 + rep;
        const float2 xv = *(const float2*)(xb + c * HW_ + 2 * lane);
        const float2 gg = *(const float2*)(lng + c * HW_ + hw0 + 2 * lane);
        const float2 bb = *(const float2*)(lnb + c * HW_ + hw0 + 2 * lane);
        const float v0 = (xv.x - mu) * rs * gg.x + bb.x;
        const float v1 = (xv.y - mu) * rs * gg.y + bb.y;
        *(bf162*)&Xs[c * SB_ + 2 * lane] = __floats2bfloat162_rn(v0, v1);
    }
    __syncthreads();

    const uint32 xs0 = cvta_smem(Xs);
    const uint32 ws0 = cvta_smem(Ws);
    const int rowA = ob + (lane & 15);
    const int colA = (lane >> 4) << 3;
    const int rowB = lane & 15;

    float acc[3][8][4];
#pragma unroll
    for (int m = 0; m < 3; m++)
#pragma unroll
        for (int nt = 0; nt < 8; nt++)
#pragma unroll
            for (int r = 0; r < 4; r++) acc[m][nt][r] = 0.f;

#pragma unroll
    for (int ks = 0; ks < 4; ks++) {
        const int kc = 16 * ks;
        uint32 b0[8], b1[8];
#pragma unroll
        for (int nt = 0; nt < 8; nt++)
            ldsm2t(b0[nt], b1[nt], xs0 + (((kc + rowB) * SB_ + 8 * nt) << 1));
#pragma unroll
        for (int m = 0; m < 3; m++) {
            uint32 a0, a1, a2, a3;
            ldsm4(a0, a1, a2, a3, ws0 + ((m * 64 * SB_ + rowA * SB_ + kc + colA) << 1));
#pragma unroll
            for (int nt = 0; nt < 8; nt++) mma16(acc[m][nt], a0, a1, a2, a3, b0[nt], b1[nt]);
        }
    }

    const int bb = be / E_, ee = be % E_;
    bf16* outs[3] = {ov, ok, oq};
#pragma unroll
    for (int m = 0; m < 3; m++) {
        bf16* dst = outs[m];
#pragma unroll
        for (int nt = 0; nt < 8; nt++) {
            const int hw = hw0 + 8 * nt + 2 * tg;
            const int o0 = ob + g, o1 = ob + g + 8;
            *(bf162*)&dst[((size_t)(bb * C_ + o0) * E_ + ee) * HW_ + hw] =
                __floats2bfloat162_rn(acc[m][nt][0], acc[m][nt][1]);
            *(bf162*)&dst[((size_t)(bb * C_ + o1) * E_ + ee) * HW_ + hw] =
                __floats2bfloat162_rn(acc[m][nt][2], acc[m][nt][3]);
        }
    }
}

// ============================================================
// Kernel 3: gram via bf16 mma, 256 threads, double-buffered
// cp.async 128-hw chunks, in-block softmax. grid (64, 4).
// Warps: wm = wid&3 (16 i-rows), wn = wid>>2 (j half: 32 / 24 cols).
// ============================================================
__global__ void __launch_bounds__(256) gram_kernel(
    const bf16* __restrict__ k, const bf16* __restrict__ q,
    float* __restrict__ wts)
{
    extern __shared__ bf16 smg[];
    bf16* Ks = smg;                 // [2 buf][64 i][SD_]
    bf16* Qs = smg + 2 * 64 * SD_;  // [2 buf][64 i][SD_]
    const int nh = blockIdx.x, b = blockIdx.y, tid = threadIdx.x;
    const int wid = tid >> 5, lane = tid & 31;
    const int g = lane >> 2, tg = lane & 3;
    const int wm = wid & 3, wn = wid >> 2;
    const int ib = wm * 16;
    const int ntc = wn ? 3 : 4;    // j cols: wn=0 -> 0..31, wn=1 -> 32..55
    const bf16* kb = k + (size_t)(b * C_ + nh) * E_ * HW_;
    const bf16* qb = q + (size_t)(b * C_ + nh) * E_ * HW_;

    // zero pad rows e = 50..63 in both buffers of both arrays
    for (int idx = tid; idx < 4 * 14 * 16; idx += 256) {
        const int a = idx / 224, rem = idx % 224, e = 50 + rem / 16, h8 = (rem % 16) << 3;
        bf16* base = (a & 1) ? Qs : Ks;
        *(uint4*)&base[(a >> 1) * 64 * SD_ + e * SD_ + h8] = make_uint4(0u, 0u, 0u, 0u);
    }

    const uint32 ks0 = cvta_smem(Ks);
    const uint32 qs0 = cvta_smem(Qs);

    // prefetch chunks 0 and 1
#pragma unroll
    for (int pre = 0; pre < 2; pre++) {
        for (int p = tid; p < 1600; p += 256) {
            const int arr = p / 800, rem = p % 800, e = rem >> 4, h8 = (rem & 15) << 3;
            const bf16* src = (arr ? qb : kb) + e * HW_ + pre * 128 + h8;
            const uint32 dst = (arr ? qs0 : ks0) + ((pre * 64 * SD_ + e * SD_ + h8) << 1);
            cp16(dst, src);
        }
        cp_commit();
    }

    const int rowA = ib + (lane & 15);
    const int colA = (lane >> 4) << 3;
    const int rowBb = lane & 7;
    const int colB = lane & 8;

    float acc[4][4];
#pragma unroll
    for (int nt = 0; nt < 4; nt++)
#pragma unroll
        for (int r = 0; r < 4; r++) acc[nt][r] = 0.f;

    for (int ch = 0; ch < 16; ch++) {
        const int buf = ch & 1;
        if (ch >= 15) cp_wait0(); else cp_wait1();
        __syncthreads();

        const uint32 kbase = ks0 + ((buf * 64 * SD_) << 1);
        const uint32 qbase = qs0 + ((buf * 64 * SD_) << 1);
#pragma unroll
        for (int ks = 0; ks < 8; ks++) {
            const int kc = 16 * ks;
            uint32 a0, a1, a2, a3;
            ldsm4(a0, a1, a2, a3, kbase + ((rowA * SD_ + kc + colA) << 1));
            for (int nt = 0; nt < ntc; nt++) {
                uint32 b0, b1;
                ldsm2(b0, b1, qbase + (((32 * wn + 8 * nt + rowBb) * SD_ + kc + colB) << 1));
                mma16(acc[nt], a0, a1, a2, a3, b0, b1);
            }
        }
        __syncthreads();

        if (ch + 2 < 16) {
            const int nxt = ch + 2;
            for (int p = tid; p < 1600; p += 256) {
                const int arr = p / 800, rem = p % 800, e = rem >> 4, h8 = (rem & 15) << 3;
                const bf16* src = (arr ? qb : kb) + e * HW_ + nxt * 128 + h8;
                const uint32 dst = (arr ? qs0 : ks0) + ((buf * 64 * SD_ + e * SD_ + h8) << 1);
                cp16(dst, src);
            }
            cp_commit();
        }
    }

    __syncthreads();
    float* gsm = (float*)smg;   // 64 x 56 fp32, reuses tile memory
    const float scale = 0.02209708691207961f;   // 1/sqrt(2048)
    for (int nt = 0; nt < ntc; nt++) {
        const int j = 32 * wn + 8 * nt + 2 * tg;
        *(float2*)&gsm[(ib + g) * 56 + j]     = make_float2(acc[nt][0] * scale, acc[nt][1] * scale);
        *(float2*)&gsm[(ib + g + 8) * 56 + j] = make_float2(acc[nt][2] * scale, acc[nt][3] * scale);
    }
    __syncthreads();

    if (tid < E_) {
        const int j = tid;
        float col[E_];
        float m = -1e30f;
#pragma unroll 10
        for (int i = 0; i < E_; i++) { col[i] = gsm[i * 56 + j]; m = fmaxf(m, col[i]); }
        float s = 0.f;
#pragma unroll 10
        for (int i = 0; i < E_; i++) { col[i] = expf(col[i] - m); s += col[i]; }
        const float inv = 1.f / s;
        float* wd = wts + (size_t)(b * C_ + nh) * E_ * E_;
#pragma unroll 10
        for (int i = 0; i < E_; i++) wd[i * E_ + j] = col[i] * inv - 0.02f;
    }
}

// ============================================================
// Kernel 4: ensemble mixing, M = I + w', double-buffered cp.async.
// ============================================================
__global__ void __launch_bounds__(128) mixing_kernel(
    const bf16* __restrict__ v, const float* __restrict__ w,
    bf16* __restrict__ tout)
{
    extern __shared__ bf16 smx[];
    bf16* Ms = smx;                // [64 j][SB_] cols i
    bf16* Vs = smx + 64 * SB_;     // [2 buf][64 i][SB_] cols hw
    const int nh = blockIdx.x, b = blockIdx.y, z = blockIdx.z;
    const int tid = threadIdx.x, wid = tid >> 5, lane = tid & 31;
    const int g = lane >> 2, tg = lane & 3;
    const int ob = wid * 16;
    const int bc = b * C_ + nh;

    // zero M fully; zero Vs pad rows i=50..63 in both buffers
    for (int idx = tid; idx < 64 * 8; idx += 128)
        *(uint4*)&Ms[(idx >> 3) * SB_ + ((idx & 7) << 3)] = make_uint4(0u, 0u, 0u, 0u);
    for (int idx = tid; idx < 2 * 14 * 8; idx += 128) {
        const int bfi = idx / 112, rem = idx % 112;
        *(uint4*)&Vs[bfi * 64 * SB_ + (50 + (rem >> 3)) * SB_ + ((rem & 7) << 3)] =
            make_uint4(0u, 0u, 0u, 0u);
    }
    __syncthreads();
    const float* wsrc = w + (size_t)bc * E_ * E_;
    for (int idx = tid; idx < E_ * E_; idx += 128) {
        const int i = idx / E_, j = idx - i * E_;
        const float val = wsrc[idx] + ((i == j) ? 1.f : 0.f);
        Ms[j * SB_ + i] = __float2bfloat16(val);
    }

    const bf16* vb = v + (size_t)bc * E_ * HW_;
    const uint32 ms0 = cvta_smem(Ms);
    const uint32 vs0 = cvta_smem(Vs);

    // prefetch chunks 0 and 1
#pragma unroll
    for (int pre = 0; pre < 2; pre++) {
        for (int p = tid; p < 400; p += 128) {
            const int e = p >> 3, h8 = (p & 7) << 3;
            cp16(vs0 + ((pre * 64 * SB_ + e * SB_ + h8) << 1),
                 vb + e * HW_ + z * 512 + pre * 64 + h8);
        }
        cp_commit();
    }

    const int rowA = ob + (lane & 15);
    const int colA = (lane >> 4) << 3;
    const int rowB = lane & 15;

    for (int t = 0; t < 8; t++) {
        const int buf = t & 1;
        const int hw0 = z * 512 + t * 64;
        if (t >= 7) cp_wait0(); else cp_wait1();
        __syncthreads();

        const uint32 vbase = vs0 + ((buf * 64 * SB_) << 1);
        float acc[8][4];
#pragma unroll
        for (int nt = 0; nt < 8; nt++)
#pragma unroll
            for (int r = 0; r < 4; r++) acc[nt][r] = 0.f;

#pragma unroll
        for (int ks = 0; ks < 4; ks++) {
            const int kc = 16 * ks;
            uint32 a0, a1, a2, a3;
            ldsm4(a0, a1, a2, a3, ms0 + ((rowA * SB_ + kc + colA) << 1));
#pragma unroll
            for (int nt = 0; nt < 8; nt++) {
                uint32 b0, b1;
                ldsm2t(b0, b1, vbase + (((kc + rowB) * SB_ + 8 * nt) << 1));
                mma16(acc[nt], a0, a1, a2, a3, b0, b1);
            }
        }
        __syncthreads();

        if (t + 2 < 8) {
            for (int p = tid; p < 400; p += 128) {
                const int e = p >> 3, h8 = (p & 7) << 3;
                cp16(vs0 + ((buf * 64 * SB_ + e * SB_ + h8) << 1),
                     vb + e * HW_ + z * 512 + (t + 2) * 64 + h8);
            }
            cp_commit();
        }

        const int j0 = ob + g, j1 = ob + g + 8;
#pragma unroll
        for (int nt = 0; nt < 8; nt++) {
            const int hw = 8 * nt + 2 * tg;
            if (j0 < E_)
                *(bf162*)&tout[((size_t)(b * E_ + j0) * C_ + nh) * HW_ + hw0 + hw] =
                    __floats2bfloat162_rn(acc[nt][0], acc[nt][1]);
            if (j1 < E_)
                *(bf162*)&tout[((size_t)(b * E_ + j1) * C_ + nh) * HW_ + hw0 + hw] =
                    __floats2bfloat162_rn(acc[nt][2], acc[nt][3]);
        }
    }
}

// ============================================================
// Kernel 5: fused tail (proven):
//   after = x + Wo @ T; h1 = gelu(Wm1 @ after + b1); out = after + Wm2 @ h1 + b2
// ============================================================
__global__ void __launch_bounds__(256) tail_kernel(
    const bf16* __restrict__ T, const float* __restrict__ x,
    const float* __restrict__ Wo, const float* __restrict__ Wm1,
    const float* __restrict__ bm1, const float* __restrict__ Wm2,
    const float* __restrict__ bm2, float* __restrict__ out)
{
    extern __shared__ bf16 smt[];
    bf16* Ws = smt;                // [3][64 o][SB_]
    bf16* Ds = smt + 3 * 64 * SB_; // [64 c][SD_]
    const int be = blockIdx.y, hw0 = blockIdx.x * 128, tid = threadIdx.x;
    const int wid = tid >> 5, lane = tid & 31;
    const int g = lane >> 2, tg = lane & 3;
    const int ob = (wid & 3) * 16;
    const int nh0 = (wid >> 2) * 64;

    for (int it = tid; it < 3072; it += 256) {
        const int m = it >> 10, rem = it & 1023, o = rem >> 4, c4 = (rem & 15) << 2;
        const float* Wp = (m == 0) ? Wo : ((m == 1) ? Wm1 : Wm2);
        const float4 w = *(const float4*)(Wp + o * 64 + c4);
        bf16* dst = Ws + m * 64 * SB_ + o * SB_ + c4;
        *(bf162*)(dst)     = __floats2bfloat162_rn(w.x, w.y);
        *(bf162*)(dst + 2) = __floats2bfloat162_rn(w.z, w.w);
    }

    const bf16* tb = T + (size_t)be * SLAB_ + hw0;
    for (int p = tid; p < 64 * 16; p += 256) {
        const int c = p >> 4, h8 = (p & 15) << 3;
        *(uint4*)&Ds[c * SD_ + h8] = *(const uint4*)&tb[c * HW_ + h8];
    }
    __syncthreads();

    const uint32 ws0 = cvta_smem(Ws);
    const uint32 ds0 = cvta_smem(Ds);
    const int rowA = ob + (lane & 15);
    const int colA = (lane >> 4) << 3;
    const int rowB = lane & 15;

    float acc1[8][4];
    const float* xb = x + (size_t)be * SLAB_ + hw0;
#pragma unroll
    for (int nt = 0; nt < 8; nt++) {
        const int hw = nh0 + 8 * nt + 2 * tg;
        const float2 r0 = *(const float2*)(xb + (size_t)(ob + g) * HW_ + hw);
        const float2 r1 = *(const float2*)(xb + (size_t)(ob + g + 8) * HW_ + hw);
        acc1[nt][0] = r0.x; acc1[nt][1] = r0.y; acc1[nt][2] = r1.x; acc1[nt][3] = r1.y;
    }
#pragma unroll
    for (int ks = 0; ks < 4; ks++) {
        const int kc = 16 * ks;
        uint32 a0, a1, a2, a3;
        ldsm4(a0, a1, a2, a3, ws0 + ((rowA * SB_ + kc + colA) << 1));
#pragma unroll
        for (int nt = 0; nt < 8; nt++) {
            uint32 b0, b1;
            ldsm2t(b0, b1, ds0 + (((kc + rowB) * SD_ + nh0 + 8 * nt) << 1));
            mma16(acc1[nt], a0, a1, a2, a3, b0, b1);
        }
    }
    __syncthreads();

#pragma unroll
    for (int nt = 0; nt < 8; nt++) {
        const int hw = nh0 + 8 * nt + 2 * tg;
        *(bf162*)&Ds[(ob + g) * SD_ + hw]     = __floats2bfloat162_rn(acc1[nt][0], acc1[nt][1]);
        *(bf162*)&Ds[(ob + g + 8) * SD_ + hw] = __floats2bfloat162_rn(acc1[nt][2], acc1[nt][3]);
    }
    __syncthreads();

    float acc2[8][4];
    {
        const float bv0 = bm1[ob + g], bv1 = bm1[ob + g + 8];
#pragma unroll
        for (int nt = 0; nt < 8; nt++) {
            acc2[nt][0] = bv0; acc2[nt][1] = bv0; acc2[nt][2] = bv1; acc2[nt][3] = bv1;
        }
    }
#pragma unroll
    for (int ks = 0; ks < 4; ks++) {
        const int kc = 16 * ks;
        uint32 a0, a1, a2, a3;
        ldsm4(a0, a1, a2, a3, ws0 + ((64 * SB_ + rowA * SB_ + kc + colA) << 1));
#pragma unroll
        for (int nt = 0; nt < 8; nt++) {
            uint32 b0, b1;
            ldsm2t(b0, b1, ds0 + (((kc + rowB) * SD_ + nh0 + 8 * nt) << 1));
            mma16(acc2[nt], a0, a1, a2, a3, b0, b1);
        }
    }
#pragma unroll
    for (int nt = 0; nt < 8; nt++)
#pragma unroll
        for (int r = 0; r < 4; r++) {
            const float v = acc2[nt][r];
            acc2[nt][r] = 0.5f * v * (1.f + erff(v * 0.7071067811865475f));
        }
    __syncthreads();

#pragma unroll
    for (int nt = 0; nt < 8; nt++) {
        const int hw = nh0 + 8 * nt + 2 * tg;
        *(bf162*)&Ds[(ob + g) * SD_ + hw]     = __floats2bfloat162_rn(acc2[nt][0], acc2[nt][1]);
        *(bf162*)&Ds[(ob + g + 8) * SD_ + hw] = __floats2bfloat162_rn(acc2[nt][2], acc2[nt][3]);
    }
    __syncthreads();

    {
        const float bv0 = bm2[ob + g], bv1 = bm2[ob + g + 8];
#pragma unroll
        for (int nt = 0; nt < 8; nt++) {
            acc2[nt][0] = bv0; acc2[nt][1] = bv0; acc2[nt][2] = bv1; acc2[nt][3] = bv1;
        }
    }
#pragma unroll
    for (int ks = 0; ks < 4; ks++) {
        const int kc = 16 * ks;
        uint32 a0, a1, a2, a3;
        ldsm4(a0, a1, a2, a3, ws0 + ((2 * 64 * SB_ + rowA * SB_ + kc + colA) << 1));
#pragma unroll
        for (int nt = 0; nt < 8; nt++) {
            uint32 b0, b1;
            ldsm2t(b0, b1, ds0 + (((kc + rowB) * SD_ + nh0 + 8 * nt) << 1));
            mma16(acc2[nt], a0, a1, a2, a3, b0, b1);
        }
    }

    float* dst = out + (size_t)be * SLAB_ + hw0;
#pragma unroll
    for (int nt = 0; nt < 8; nt++) {
        const int hw = nh0 + 8 * nt + 2 * tg;
        *(float2*)(dst + (size_t)(ob + g) * HW_ + hw) =
            make_float2(acc1[nt][0] + acc2[nt][0], acc1[nt][1] + acc2[nt][1]);
        *(float2*)(dst + (size_t)(ob + g + 8) * HW_ + hw) =
            make_float2(acc1[nt][2] + acc2[nt][2], acc1[nt][3] + acc2[nt][3]);
    }
}

// ============================================================
// Launch
// ============================================================
extern "C" void kernel_launch(void* const* d_in, const int* in_sizes, int n_in,
                              void* d_out, int out_size)
{
    const float* x    = (const float*)d_in[0];
    const float* lng  = (const float*)d_in[1];
    const float* lnb  = (const float*)d_in[2];
    const float* W_v  = (const float*)d_in[3];
    const float* W_k  = (const float*)d_in[4];
    const float* W_q  = (const float*)d_in[5];
    const float* W_o  = (const float*)d_in[6];
    const float* W_m1 = (const float*)d_in[7];
    const float* b_m1 = (const float*)d_in[8];
    const float* W_m2 = (const float*)d_in[9];
    const float* b_m2 = (const float*)d_in[10];
    float* out = (float*)d_out;

    bf16 *pv, *pk, *pq, *pt;
    float *pw;
    cudaGetSymbolAddress((void**)&pv, g_v);
    cudaGetSymbolAddress((void**)&pk, g_k);
    cudaGetSymbolAddress((void**)&pq, g_q);
    cudaGetSymbolAddress((void**)&pt, g_t);
    cudaGetSymbolAddress((void**)&pw, g_wts);

    const int smem_vkq  = (3 * 64 * SB_ + 64 * SB_) * 2;   // 36864
    const int smem_gram = (4 * 64 * SD_) * 2;              // 69632
    const int smem_mix  = (3 * 64 * SB_) * 2;              // 27648
    const int smem_tail = (3 * 64 * SB_ + 64 * SD_) * 2;   // 45056
    cudaFuncSetAttribute(vkq_kernel,    cudaFuncAttributeMaxDynamicSharedMemorySize, smem_vkq);
    cudaFuncSetAttribute(gram_kernel,   cudaFuncAttributeMaxDynamicSharedMemorySize, smem_gram);
    cudaFuncSetAttribute(mixing_kernel, cudaFuncAttributeMaxDynamicSharedMemorySize, smem_mix);
    cudaFuncSetAttribute(tail_kernel,   cudaFuncAttributeMaxDynamicSharedMemorySize, smem_tail);

    ln_stats_kernel<<<BE_, 512>>>(x);

    vkq_kernel<<<dim3(HW_ / 64, BE_), 128, smem_vkq>>>(x, W_v, W_k, W_q, lng, lnb, pv, pk, pq);

    gram_kernel<<<dim3(C_, B_), 256, smem_gram>>>(pk, pq, pw);

    mixing_kernel<<<dim3(C_, B_, 4), 128, smem_mix>>>(pv, pw, pt);

    tail_kernel<<<dim3(HW_ / 128, BE_), 256, smem_tail>>>(pt, x, W_o, W_m1, b_m1, W_m2, b_m2, out);
}

// round 8
// speedup vs baseline: 3.4335x; 1.0595x over previous
#include <cuda_runtime.h>
#include <cuda_bf16.h>
#include <math.h>

#define B_    4
#define E_    50
#define C_    64
#define HW_   2048
#define BE_   200
#define SLAB_ 131072      // C_*HW_
#define NTOT_ 26214400    // BE_*SLAB_
#define SB_   72          // bf16 smem row stride, 64 cols (9r mod 8 distinct -> LDSM conflict-free)
#define SD_   136         // bf16 smem row stride, 128 cols (17r mod 8 distinct)

typedef unsigned int uint32;
typedef __nv_bfloat16 bf16;
typedef __nv_bfloat162 bf162;

// ---- scratch (static device globals; no allocation) ----
__device__ bf16 g_v[NTOT_];   // [b][c][e][hw]
__device__ bf16 g_k[NTOT_];   // [b][c][e][hw]
__device__ bf16 g_q[NTOT_];   // [b][c][e][hw]
__device__ bf16 g_t[NTOT_];   // [b][e][c][hw]
__device__ float g_wts[B_ * C_ * E_ * E_];  // w' = softmax - 1/E
__device__ float g_mu[BE_];
__device__ float g_rs[BE_];
__device__ bf16 g_wb[6 * 4096];   // bf16 weights: Wv,Wk,Wq,Wo,Wm1,Wm2 [o][c]
__device__ bf16 g_lng[SLAB_];
__device__ bf16 g_lnb[SLAB_];

// m16n8k16 bf16 mma, fp32 accumulate
__device__ __forceinline__ void mma16(float d[4], uint32 a0, uint32 a1, uint32 a2, uint32 a3,
                                      uint32 b0, uint32 b1) {
    asm volatile(
        "mma.sync.aligned.m16n8k16.row.col.f32.bf16.bf16.f32 "
        "{%0,%1,%2,%3}, {%4,%5,%6,%7}, {%8,%9}, {%0,%1,%2,%3};"
        : "+f"(d[0]), "+f"(d[1]), "+f"(d[2]), "+f"(d[3])
        : "r"(a0), "r"(a1), "r"(a2), "r"(a3), "r"(b0), "r"(b1));
}

__device__ __forceinline__ uint32 cvta_smem(const void* p) {
    return (uint32)__cvta_generic_to_shared(p);
}
__device__ __forceinline__ void ldsm4(uint32& r0, uint32& r1, uint32& r2, uint32& r3, uint32 a) {
    asm volatile("ldmatrix.sync.aligned.m8n8.x4.shared.b16 {%0,%1,%2,%3}, [%4];"
                 : "=r"(r0), "=r"(r1), "=r"(r2), "=r"(r3) : "r"(a));
}
__device__ __forceinline__ void ldsm4t(uint32& r0, uint32& r1, uint32& r2, uint32& r3, uint32 a) {
    asm volatile("ldmatrix.sync.aligned.m8n8.x4.trans.shared.b16 {%0,%1,%2,%3}, [%4];"
                 : "=r"(r0), "=r"(r1), "=r"(r2), "=r"(r3) : "r"(a));
}
__device__ __forceinline__ void ldsm2(uint32& r0, uint32& r1, uint32 a) {
    asm volatile("ldmatrix.sync.aligned.m8n8.x2.shared.b16 {%0,%1}, [%2];"
                 : "=r"(r0), "=r"(r1) : "r"(a));
}
__device__ __forceinline__ void cp16(uint32 dst, const void* src) {
    asm volatile("cp.async.cg.shared.global [%0], [%1], 16;" :: "r"(dst), "l"(src));
}
__device__ __forceinline__ void cp_commit() { asm volatile("cp.async.commit_group;"); }
__device__ __forceinline__ void cp_wait1() { asm volatile("cp.async.wait_group 1;"); }
__device__ __forceinline__ void cp_wait0() { asm volatile("cp.async.wait_group 0;"); }

// ============================================================
// Kernel 0: one-time bf16 conversion of weights + ln params
// ============================================================
__global__ void setup_kernel(
    const float* __restrict__ Wv, const float* __restrict__ Wk, const float* __restrict__ Wq,
    const float* __restrict__ Wo, const float* __restrict__ Wm1, const float* __restrict__ Wm2,
    const float* __restrict__ lng, const float* __restrict__ lnb)
{
    const int idx = blockIdx.x * blockDim.x + threadIdx.x;
    const int stride = gridDim.x * blockDim.x;
    for (int i = idx; i < 6 * 4096; i += stride) {
        const int m = i >> 12, r = i & 4095;
        const float* src = (m == 0) ? Wv : (m == 1) ? Wk : (m == 2) ? Wq
                         : (m == 3) ? Wo : (m == 4) ? Wm1 : Wm2;
        g_wb[i] = __float2bfloat16(src[r]);
    }
    for (int i = idx; i < SLAB_; i += stride) {
        g_lng[i] = __float2bfloat16(lng[i]);
        g_lnb[i] = __float2bfloat16(lnb[i]);
    }
}

// ============================================================
// Kernel 1: LayerNorm statistics per (b,e) slab (512 threads)
// ============================================================
__global__ void __launch_bounds__(512) ln_stats_kernel(const float* __restrict__ x) {
    const int be = blockIdx.x;
    const float4* p = (const float4*)(x + (size_t)be * SLAB_);
    float s = 0.f, s2 = 0.f;
    for (int i = threadIdx.x; i < SLAB_ / 4; i += 512) {
        float4 v = p[i];
        s  += v.x + v.y + v.z + v.w;
        s2 += v.x * v.x + v.y * v.y + v.z * v.z + v.w * v.w;
    }
    for (int o = 16; o; o >>= 1) {
        s  += __shfl_down_sync(0xffffffffu, s,  o);
        s2 += __shfl_down_sync(0xffffffffu, s2, o);
    }
    __shared__ float shs[16], shq[16];
    const int w = threadIdx.x >> 5, l = threadIdx.x & 31;
    if (l == 0) { shs[w] = s; shq[w] = s2; }
    __syncthreads();
    if (threadIdx.x == 0) {
        float S = 0.f, Q = 0.f;
        for (int i = 0; i < 16; i++) { S += shs[i]; Q += shq[i]; }
        const float mu  = S * (1.f / (float)SLAB_);
        const float var = Q * (1.f / (float)SLAB_) - mu * mu;
        g_mu[be] = mu;
        g_rs[be] = rsqrtf(var + 1e-5f);
    }
}

// ============================================================
// Kernel 2: fused LN + v/k/q conv. bf16 weights via cp.async,
// bf16 ln params, ldsm4t B pairs shared across 3 GEMMs.
// ============================================================
__global__ void __launch_bounds__(128) vkq_kernel(
    const float* __restrict__ x,
    bf16* __restrict__ ov, bf16* __restrict__ ok, bf16* __restrict__ oq)
{
    extern __shared__ bf16 smb[];
    bf16* Ws = smb;                // [3][64 o][SB_]
    bf16* Xs = smb + 3 * 64 * SB_; // [64 c][SB_]
    const int be = blockIdx.y, hw0 = blockIdx.x * 64, tid = threadIdx.x;
    const int wid = tid >> 5, lane = tid & 31;
    const int g = lane >> 2, tg = lane & 3;
    const int ob = wid * 16;

    const uint32 ws0 = cvta_smem(Ws);
    const uint32 xs0 = cvta_smem(Xs);

    // weights via cp.async (bf16, no conversion)
    for (int it = tid; it < 1536; it += 128) {
        const int m = it >> 9, rem = it & 511, o = rem >> 3, s8 = (rem & 7) << 3;
        cp16(ws0 + ((m * 64 * SB_ + o * SB_ + s8) << 1), &g_wb[m * 4096 + o * 64 + s8]);
    }
    cp_commit();

    // x tile: LN (bf16 gamma/beta) -> Xs[c][hw]
    const float mu = g_mu[be], rs = g_rs[be];
    const float* xb = x + (size_t)be * SLAB_ + hw0;
    for (int rep = 0; rep < 16; rep++) {
        const int c = wid * 16 + rep;
        const float2 xv = *(const float2*)(xb + c * HW_ + 2 * lane);
        const bf162 gg = *(const bf162*)&g_lng[c * HW_ + hw0 + 2 * lane];
        const bf162 bb = *(const bf162*)&g_lnb[c * HW_ + hw0 + 2 * lane];
        const float2 gf = __bfloat1622float2(gg);
        const float2 bf = __bfloat1622float2(bb);
        const float v0 = (xv.x - mu) * rs * gf.x + bf.x;
        const float v1 = (xv.y - mu) * rs * gf.y + bf.y;
        *(bf162*)&Xs[c * SB_ + 2 * lane] = __floats2bfloat162_rn(v0, v1);
    }
    cp_wait0();
    __syncthreads();

    const int rowA = ob + (lane & 15);
    const int colA = (lane >> 4) << 3;
    const int krow = lane & 15;
    const int hwadd = (lane >> 4) << 3;

    float acc[3][8][4];
#pragma unroll
    for (int m = 0; m < 3; m++)
#pragma unroll
        for (int nt = 0; nt < 8; nt++)
#pragma unroll
            for (int r = 0; r < 4; r++) acc[m][nt][r] = 0.f;

#pragma unroll
    for (int ks = 0; ks < 4; ks++) {
        const int kc = 16 * ks;
        uint32 b0[8], b1[8];
#pragma unroll
        for (int p = 0; p < 4; p++)
            ldsm4t(b0[2 * p], b1[2 * p], b0[2 * p + 1], b1[2 * p + 1],
                   xs0 + (((kc + krow) * SB_ + 16 * p + hwadd) << 1));
#pragma unroll
        for (int m = 0; m < 3; m++) {
            uint32 a0, a1, a2, a3;
            ldsm4(a0, a1, a2, a3, ws0 + ((m * 64 * SB_ + rowA * SB_ + kc + colA) << 1));
#pragma unroll
            for (int nt = 0; nt < 8; nt++) mma16(acc[m][nt], a0, a1, a2, a3, b0[nt], b1[nt]);
        }
    }

    const int bb = be / E_, ee = be % E_;
    bf16* outs[3] = {ov, ok, oq};
#pragma unroll
    for (int m = 0; m < 3; m++) {
        bf16* dst = outs[m];
#pragma unroll
        for (int nt = 0; nt < 8; nt++) {
            const int hw = hw0 + 8 * nt + 2 * tg;
            const int o0 = ob + g, o1 = ob + g + 8;
            *(bf162*)&dst[((size_t)(bb * C_ + o0) * E_ + ee) * HW_ + hw] =
                __floats2bfloat162_rn(acc[m][nt][0], acc[m][nt][1]);
            *(bf162*)&dst[((size_t)(bb * C_ + o1) * E_ + ee) * HW_ + hw] =
                __floats2bfloat162_rn(acc[m][nt][2], acc[m][nt][3]);
        }
    }
}

// ============================================================
// Kernel 3: gram, 256 threads, double-buffered cp.async,
// ldsm4 B pairs, in-block softmax. grid (64, 4).
// ============================================================
__global__ void __launch_bounds__(256) gram_kernel(
    const bf16* __restrict__ k, const bf16* __restrict__ q,
    float* __restrict__ wts)
{
    extern __shared__ bf16 smg[];
    bf16* Ks = smg;                 // [2 buf][64 i][SD_]
    bf16* Qs = smg + 2 * 64 * SD_;
    const int nh = blockIdx.x, b = blockIdx.y, tid = threadIdx.x;
    const int wid = tid >> 5, lane = tid & 31;
    const int g = lane >> 2, tg = lane & 3;
    const int wm = wid & 3, wn = wid >> 2;
    const int ib = wm * 16;
    const int ntc = wn ? 3 : 4;
    const bf16* kb = k + (size_t)(b * C_ + nh) * E_ * HW_;
    const bf16* qb = q + (size_t)(b * C_ + nh) * E_ * HW_;

    for (int idx = tid; idx < 4 * 14 * 16; idx += 256) {
        const int a = idx / 224, rem = idx % 224, e = 50 + rem / 16, h8 = (rem % 16) << 3;
        bf16* base = (a & 1) ? Qs : Ks;
        *(uint4*)&base[(a >> 1) * 64 * SD_ + e * SD_ + h8] = make_uint4(0u, 0u, 0u, 0u);
    }

    const uint32 ks0 = cvta_smem(Ks);
    const uint32 qs0 = cvta_smem(Qs);

#pragma unroll
    for (int pre = 0; pre < 2; pre++) {
        for (int p = tid; p < 1600; p += 256) {
            const int arr = p / 800, rem = p % 800, e = rem >> 4, h8 = (rem & 15) << 3;
            const bf16* src = (arr ? qb : kb) + e * HW_ + pre * 128 + h8;
            const uint32 dst = (arr ? qs0 : ks0) + ((pre * 64 * SD_ + e * SD_ + h8) << 1);
            cp16(dst, src);
        }
        cp_commit();
    }

    const int rowA = ib + (lane & 15);
    const int colA = (lane >> 4) << 3;
    const int rowBb = lane & 7;
    const int colB = lane & 8;
    const int rowP = (lane >> 4) << 3;   // pair row offset (0 or 8)

    float acc[4][4];
#pragma unroll
    for (int nt = 0; nt < 4; nt++)
#pragma unroll
        for (int r = 0; r < 4; r++) acc[nt][r] = 0.f;

    for (int ch = 0; ch < 16; ch++) {
        const int buf = ch & 1;
        if (ch >= 15) cp_wait0(); else cp_wait1();
        __syncthreads();

        const uint32 kbase = ks0 + ((buf * 64 * SD_) << 1);
        const uint32 qbase = qs0 + ((buf * 64 * SD_) << 1);
#pragma unroll
        for (int ks = 0; ks < 8; ks++) {
            const int kc = 16 * ks;
            uint32 a0, a1, a2, a3;
            ldsm4(a0, a1, a2, a3, kbase + ((rowA * SD_ + kc + colA) << 1));
            uint32 bb0[4], bb1[4];
            // pair (nt0, nt1)
            ldsm4(bb0[0], bb1[0], bb0[1], bb1[1],
                  qbase + (((32 * wn + rowP + rowBb) * SD_ + kc + colB) << 1));
            if (wn == 0) {
                ldsm4(bb0[2], bb1[2], bb0[3], bb1[3],
                      qbase + (((16 + rowP + rowBb) * SD_ + kc + colB) << 1));
            } else {
                ldsm2(bb0[2], bb1[2], qbase + (((48 + rowBb) * SD_ + kc + colB) << 1));
            }
            for (int nt = 0; nt < ntc; nt++)
                mma16(acc[nt], a0, a1, a2, a3, bb0[nt], bb1[nt]);
        }
        __syncthreads();

        if (ch + 2 < 16) {
            const int nxt = ch + 2;
            for (int p = tid; p < 1600; p += 256) {
                const int arr = p / 800, rem = p % 800, e = rem >> 4, h8 = (rem & 15) << 3;
                const bf16* src = (arr ? qb : kb) + e * HW_ + nxt * 128 + h8;
                const uint32 dst = (arr ? qs0 : ks0) + ((buf * 64 * SD_ + e * SD_ + h8) << 1);
                cp16(dst, src);
            }
            cp_commit();
        }
    }

    __syncthreads();
    float* gsm = (float*)smg;
    const float scale = 0.02209708691207961f;   // 1/sqrt(2048)
    for (int nt = 0; nt < ntc; nt++) {
        const int j = 32 * wn + 8 * nt + 2 * tg;
        *(float2*)&gsm[(ib + g) * 56 + j]     = make_float2(acc[nt][0] * scale, acc[nt][1] * scale);
        *(float2*)&gsm[(ib + g + 8) * 56 + j] = make_float2(acc[nt][2] * scale, acc[nt][3] * scale);
    }
    __syncthreads();

    if (tid < E_) {
        const int j = tid;
        float col[E_];
        float m = -1e30f;
#pragma unroll 10
        for (int i = 0; i < E_; i++) { col[i] = gsm[i * 56 + j]; m = fmaxf(m, col[i]); }
        float s = 0.f;
#pragma unroll 10
        for (int i = 0; i < E_; i++) { col[i] = expf(col[i] - m); s += col[i]; }
        const float inv = 1.f / s;
        float* wd = wts + (size_t)(b * C_ + nh) * E_ * E_;
#pragma unroll 10
        for (int i = 0; i < E_; i++) wd[i * E_ + j] = col[i] * inv - 0.02f;
    }
}

// ============================================================
// Kernel 4: ensemble mixing, M = I + w', cp.async pipeline,
// ldsm4t B pairs.
// ============================================================
__global__ void __launch_bounds__(128) mixing_kernel(
    const bf16* __restrict__ v, const float* __restrict__ w,
    bf16* __restrict__ tout)
{
    extern __shared__ bf16 smx[];
    bf16* Ms = smx;                // [64 j][SB_] cols i
    bf16* Vs = smx + 64 * SB_;     // [2 buf][64 i][SB_] cols hw
    const int nh = blockIdx.x, b = blockIdx.y, z = blockIdx.z;
    const int tid = threadIdx.x, wid = tid >> 5, lane = tid & 31;
    const int g = lane >> 2, tg = lane & 3;
    const int ob = wid * 16;
    const int bc = b * C_ + nh;

    for (int idx = tid; idx < 64 * 8; idx += 128)
        *(uint4*)&Ms[(idx >> 3) * SB_ + ((idx & 7) << 3)] = make_uint4(0u, 0u, 0u, 0u);
    for (int idx = tid; idx < 2 * 14 * 8; idx += 128) {
        const int bfi = idx / 112, rem = idx % 112;
        *(uint4*)&Vs[bfi * 64 * SB_ + (50 + (rem >> 3)) * SB_ + ((rem & 7) << 3)] =
            make_uint4(0u, 0u, 0u, 0u);
    }
    __syncthreads();
    const float* wsrc = w + (size_t)bc * E_ * E_;
    for (int idx = tid; idx < E_ * E_; idx += 128) {
        const int i = idx / E_, j = idx - i * E_;
        const float val = wsrc[idx] + ((i == j) ? 1.f : 0.f);
        Ms[j * SB_ + i] = __float2bfloat16(val);
    }

    const bf16* vb = v + (size_t)bc * E_ * HW_;
    const uint32 ms0 = cvta_smem(Ms);
    const uint32 vs0 = cvta_smem(Vs);

#pragma unroll
    for (int pre = 0; pre < 2; pre++) {
        for (int p = tid; p < 400; p += 128) {
            const int e = p >> 3, h8 = (p & 7) << 3;
            cp16(vs0 + ((pre * 64 * SB_ + e * SB_ + h8) << 1),
                 vb + e * HW_ + z * 512 + pre * 64 + h8);
        }
        cp_commit();
    }

    const int rowA = ob + (lane & 15);
    const int colA = (lane >> 4) << 3;
    const int krow = lane & 15;
    const int hwadd = (lane >> 4) << 3;

    for (int t = 0; t < 8; t++) {
        const int buf = t & 1;
        const int hw0 = z * 512 + t * 64;
        if (t >= 7) cp_wait0(); else cp_wait1();
        __syncthreads();

        const uint32 vbase = vs0 + ((buf * 64 * SB_) << 1);
        float acc[8][4];
#pragma unroll
        for (int nt = 0; nt < 8; nt++)
#pragma unroll
            for (int r = 0; r < 4; r++) acc[nt][r] = 0.f;

#pragma unroll
        for (int ks = 0; ks < 4; ks++) {
            const int kc = 16 * ks;
            uint32 a0, a1, a2, a3;
            ldsm4(a0, a1, a2, a3, ms0 + ((rowA * SB_ + kc + colA) << 1));
            uint32 b0[8], b1[8];
#pragma unroll
            for (int p = 0; p < 4; p++)
                ldsm4t(b0[2 * p], b1[2 * p], b0[2 * p + 1], b1[2 * p + 1],
                       vbase + (((kc + krow) * SB_ + 16 * p + hwadd) << 1));
#pragma unroll
            for (int nt = 0; nt < 8; nt++)
                mma16(acc[nt], a0, a1, a2, a3, b0[nt], b1[nt]);
        }
        __syncthreads();

        if (t + 2 < 8) {
            for (int p = tid; p < 400; p += 128) {
                const int e = p >> 3, h8 = (p & 7) << 3;
                cp16(vs0 + ((buf * 64 * SB_ + e * SB_ + h8) << 1),
                     vb + e * HW_ + z * 512 + (t + 2) * 64 + h8);
            }
            cp_commit();
        }

        const int j0 = ob + g, j1 = ob + g + 8;
#pragma unroll
        for (int nt = 0; nt < 8; nt++) {
            const int hw = 8 * nt + 2 * tg;
            if (j0 < E_)
                *(bf162*)&tout[((size_t)(b * E_ + j0) * C_ + nh) * HW_ + hw0 + hw] =
                    __floats2bfloat162_rn(acc[nt][0], acc[nt][1]);
            if (j1 < E_)
                *(bf162*)&tout[((size_t)(b * E_ + j1) * C_ + nh) * HW_ + hw0 + hw] =
                    __floats2bfloat162_rn(acc[nt][2], acc[nt][3]);
        }
    }
}

// ============================================================
// Kernel 5: fused tail; bf16 weights + T via cp.async, ldsm4t B.
// ============================================================
__global__ void __launch_bounds__(256) tail_kernel(
    const bf16* __restrict__ T, const float* __restrict__ x,
    const float* __restrict__ bm1, const float* __restrict__ bm2,
    float* __restrict__ out)
{
    extern __shared__ bf16 smt[];
    bf16* Ws = smt;                // [3][64 o][SB_]
    bf16* Ds = smt + 3 * 64 * SB_; // [64 c][SD_]
    const int be = blockIdx.y, hw0 = blockIdx.x * 128, tid = threadIdx.x;
    const int wid = tid >> 5, lane = tid & 31;
    const int g = lane >> 2, tg = lane & 3;
    const int ob = (wid & 3) * 16;
    const int nh0 = (wid >> 2) * 64;

    const uint32 ws0 = cvta_smem(Ws);
    const uint32 ds0 = cvta_smem(Ds);

    // weights (Wo,Wm1,Wm2 = g_wb slots 3,4,5) + T tile via cp.async
    for (int it = tid; it < 1536; it += 256) {
        const int m = it >> 9, rem = it & 511, o = rem >> 3, s8 = (rem & 7) << 3;
        cp16(ws0 + ((m * 64 * SB_ + o * SB_ + s8) << 1), &g_wb[(3 + m) * 4096 + o * 64 + s8]);
    }
    const bf16* tb = T + (size_t)be * SLAB_ + hw0;
    for (int p = tid; p < 1024; p += 256) {
        const int c = p >> 4, h8 = (p & 15) << 3;
        cp16(ds0 + ((c * SD_ + h8) << 1), tb + c * HW_ + h8);
    }
    cp_commit();

    // x residual (overlaps with cp.async)
    float acc1[8][4];
    const float* xb = x + (size_t)be * SLAB_ + hw0;
#pragma unroll
    for (int nt = 0; nt < 8; nt++) {
        const int hw = nh0 + 8 * nt + 2 * tg;
        const float2 r0 = *(const float2*)(xb + (size_t)(ob + g) * HW_ + hw);
        const float2 r1 = *(const float2*)(xb + (size_t)(ob + g + 8) * HW_ + hw);
        acc1[nt][0] = r0.x; acc1[nt][1] = r0.y; acc1[nt][2] = r1.x; acc1[nt][3] = r1.y;
    }
    cp_wait0();
    __syncthreads();

    const int rowA = ob + (lane & 15);
    const int colA = (lane >> 4) << 3;
    const int krow = lane & 15;
    const int hwadd = (lane >> 4) << 3;

    // GEMM1: acc1 += Wo @ T
#pragma unroll
    for (int ks = 0; ks < 4; ks++) {
        const int kc = 16 * ks;
        uint32 a0, a1, a2, a3;
        ldsm4(a0, a1, a2, a3, ws0 + ((rowA * SB_ + kc + colA) << 1));
        uint32 b0[8], b1[8];
#pragma unroll
        for (int p = 0; p < 4; p++)
            ldsm4t(b0[2 * p], b1[2 * p], b0[2 * p + 1], b1[2 * p + 1],
                   ds0 + (((kc + krow) * SD_ + nh0 + 16 * p + hwadd) << 1));
#pragma unroll
        for (int nt = 0; nt < 8; nt++)
            mma16(acc1[nt], a0, a1, a2, a3, b0[nt], b1[nt]);
    }
    __syncthreads();

    // after -> Ds
#pragma unroll
    for (int nt = 0; nt < 8; nt++) {
        const int hw = nh0 + 8 * nt + 2 * tg;
        *(bf162*)&Ds[(ob + g) * SD_ + hw]     = __floats2bfloat162_rn(acc1[nt][0], acc1[nt][1]);
        *(bf162*)&Ds[(ob + g + 8) * SD_ + hw] = __floats2bfloat162_rn(acc1[nt][2], acc1[nt][3]);
    }
    __syncthreads();

    // GEMM2: h1 = gelu(Wm1 @ after + b1)
    float acc2[8][4];
    {
        const float bv0 = bm1[ob + g], bv1 = bm1[ob + g + 8];
#pragma unroll
        for (int nt = 0; nt < 8; nt++) {
            acc2[nt][0] = bv0; acc2[nt][1] = bv0; acc2[nt][2] = bv1; acc2[nt][3] = bv1;
        }
    }
#pragma unroll
    for (int ks = 0; ks < 4; ks++) {
        const int kc = 16 * ks;
        uint32 a0, a1, a2, a3;
        ldsm4(a0, a1, a2, a3, ws0 + ((64 * SB_ + rowA * SB_ + kc + colA) << 1));
        uint32 b0[8], b1[8];
#pragma unroll
        for (int p = 0; p < 4; p++)
            ldsm4t(b0[2 * p], b1[2 * p], b0[2 * p + 1], b1[2 * p + 1],
                   ds0 + (((kc + krow) * SD_ + nh0 + 16 * p + hwadd) << 1));
#pragma unroll
        for (int nt = 0; nt < 8; nt++)
            mma16(acc2[nt], a0, a1, a2, a3, b0[nt], b1[nt]);
    }
#pragma unroll
    for (int nt = 0; nt < 8; nt++)
#pragma unroll
        for (int r = 0; r < 4; r++) {
            const float v = acc2[nt][r];
            acc2[nt][r] = 0.5f * v * (1.f + erff(v * 0.7071067811865475f));
        }
    __syncthreads();

    // h1 -> Ds
#pragma unroll
    for (int nt = 0; nt < 8; nt++) {
        const int hw = nh0 + 8 * nt + 2 * tg;
        *(bf162*)&Ds[(ob + g) * SD_ + hw]     = __floats2bfloat162_rn(acc2[nt][0], acc2[nt][1]);
        *(bf162*)&Ds[(ob + g + 8) * SD_ + hw] = __floats2bfloat162_rn(acc2[nt][2], acc2[nt][3]);
    }
    __syncthreads();

    // GEMM3 (reuse acc2): out = acc1 + Wm2 @ h1 + b2
    {
        const float bv0 = bm2[ob + g], bv1 = bm2[ob + g + 8];
#pragma unroll
        for (int nt = 0; nt < 8; nt++) {
            acc2[nt][0] = bv0; acc2[nt][1] = bv0; acc2[nt][2] = bv1; acc2[nt][3] = bv1;
        }
    }
#pragma unroll
    for (int ks = 0; ks < 4; ks++) {
        const int kc = 16 * ks;
        uint32 a0, a1, a2, a3;
        ldsm4(a0, a1, a2, a3, ws0 + ((2 * 64 * SB_ + rowA * SB_ + kc + colA) << 1));
        uint32 b0[8], b1[8];
#pragma unroll
        for (int p = 0; p < 4; p++)
            ldsm4t(b0[2 * p], b1[2 * p], b0[2 * p + 1], b1[2 * p + 1],
                   ds0 + (((kc + krow) * SD_ + nh0 + 16 * p + hwadd) << 1));
#pragma unroll
        for (int nt = 0; nt < 8; nt++)
            mma16(acc2[nt], a0, a1, a2, a3, b0[nt], b1[nt]);
    }

    float* dst = out + (size_t)be * SLAB_ + hw0;
#pragma unroll
    for (int nt = 0; nt < 8; nt++) {
        const int hw = nh0 + 8 * nt + 2 * tg;
        *(float2*)(dst + (size_t)(ob + g) * HW_ + hw) =
            make_float2(acc1[nt][0] + acc2[nt][0], acc1[nt][1] + acc2[nt][1]);
        *(float2*)(dst + (size_t)(ob + g + 8) * HW_ + hw) =
            make_float2(acc1[nt][2] + acc2[nt][2], acc1[nt][3] + acc2[nt][3]);
    }
}

// ============================================================
// Launch
// ============================================================
extern "C" void kernel_launch(void* const* d_in, const int* in_sizes, int n_in,
                              void* d_out, int out_size)
{
    const float* x    = (const float*)d_in[0];
    const float* lng  = (const float*)d_in[1];
    const float* lnb  = (const float*)d_in[2];
    const float* W_v  = (const float*)d_in[3];
    const float* W_k  = (const float*)d_in[4];
    const float* W_q  = (const float*)d_in[5];
    const float* W_o  = (const float*)d_in[6];
    const float* W_m1 = (const float*)d_in[7];
    const float* b_m1 = (const float*)d_in[8];
    const float* W_m2 = (const float*)d_in[9];
    const float* b_m2 = (const float*)d_in[10];
    float* out = (float*)d_out;

    bf16 *pv, *pk, *pq, *pt;
    float *pw;
    cudaGetSymbolAddress((void**)&pv, g_v);
    cudaGetSymbolAddress((void**)&pk, g_k);
    cudaGetSymbolAddress((void**)&pq, g_q);
    cudaGetSymbolAddress((void**)&pt, g_t);
    cudaGetSymbolAddress((void**)&pw, g_wts);

    const int smem_vkq  = (3 * 64 * SB_ + 64 * SB_) * 2;   // 36864
    const int smem_gram = (4 * 64 * SD_) * 2;              // 69632
    const int smem_mix  = (3 * 64 * SB_) * 2;              // 27648
    const int smem_tail = (3 * 64 * SB_ + 64 * SD_) * 2;   // 45056
    cudaFuncSetAttribute(vkq_kernel,    cudaFuncAttributeMaxDynamicSharedMemorySize, smem_vkq);
    cudaFuncSetAttribute(gram_kernel,   cudaFuncAttributeMaxDynamicSharedMemorySize, smem_gram);
    cudaFuncSetAttribute(mixing_kernel, cudaFuncAttributeMaxDynamicSharedMemorySize, smem_mix);
    cudaFuncSetAttribute(tail_kernel,   cudaFuncAttributeMaxDynamicSharedMemorySize, smem_tail);

    setup_kernel<<<128, 256>>>(W_v, W_k, W_q, W_o, W_m1, W_m2, lng, lnb);

    ln_stats_kernel<<<BE_, 512>>>(x);

    vkq_kernel<<<dim3(HW_ / 64, BE_), 128, smem_vkq>>>(x, pv, pk, pq);

    gram_kernel<<<dim3(C_, B_), 256, smem_gram>>>(pk, pq, pw);

    mixing_kernel<<<dim3(C_, B_, 4), 128, smem_mix>>>(pv, pw, pt);

    tail_kernel<<<dim3(HW_ / 128, BE_), 256, smem_tail>>>(pt, x, b_m1, b_m2, out);
}